// round 2
// baseline (speedup 1.0000x reference)
#include <cuda_runtime.h>
#include <math.h>

#define B_   256
#define S_   500
#define T_   (B_*S_)        // 128000
#define DQ_  128
#define DV_  256
#define M_   50
#define F_   512
#define NEA_ 512            // concat(erase, add) output
#define KEA_ 256
#define KRO_ 384            // DV + DQ

// ---------------- scratch (device globals; no allocations) ----------------
__device__ float g_bufX [2*T_*DQ_];   // X1 rows [0,T), X2 rows [T,2T); later reused for X3 rows [0,T)
__device__ float g_bufU [2*T_*DQ_];   // tanh(lin1(.))
__device__ float g_bufTD[2*T_*DQ_];   // time_final rows [0,T), diff_final rows [T,2T)
__device__ float g_bufQP[T_*DQ_];     // q_proc
__device__ float g_bufQA[T_*DV_];     // qa embedding gather
__device__ float g_bufEA[T_*NEA_];    // e (cols 0..255), a (cols 256..511)
__device__ float g_PredIn[T_*KRO_];   // reads (0..255) | input_embed (256..383)
__device__ float g_logits[T_*M_];     // logits -> softmax weights (in place)
__device__ float g_predS[T_];
__device__ float g_accum[2];
__device__ float g_Wea[NEA_*KEA_];
__device__ float g_bea[NEA_];

// ---------------- prep: zero pred/accum, build concat EA weights ----------
__global__ void k_prep(const float* __restrict__ eW, const float* __restrict__ eb,
                       const float* __restrict__ aW, const float* __restrict__ ab)
{
    int i = blockIdx.x * blockDim.x + threadIdx.x;
    int stride = gridDim.x * blockDim.x;
    for (int j = i; j < NEA_*KEA_; j += stride) {
        int n = j / KEA_, k = j % KEA_;
        g_Wea[j] = (n < DV_) ? eW[n*KEA_ + k] : aW[(n - DV_)*KEA_ + k];
    }
    for (int j = i; j < NEA_; j += stride) g_bea[j] = (j < DV_) ? eb[j] : ab[j - DV_];
    for (int j = i; j < T_;  j += stride) g_predS[j] = 0.f;
    if (i < 2) g_accum[i] = 0.f;
}

// ---------------- gather phase 1: X1 = te+qe, X2 = he+hte+ae+qe, qa -------
__global__ void k_gather1(const int* __restrict__ q_data, const int* __restrict__ qa_data,
                          const int* __restrict__ time_data, const int* __restrict__ attempt_data,
                          const int* __restrict__ hint_data, const int* __restrict__ hintTotal_data,
                          const float* __restrict__ q_emb, const float* __restrict__ qa_emb,
                          const float* __restrict__ time_emb, const float* __restrict__ attempt_emb,
                          const float* __restrict__ ht_emb)
{
    int t = blockIdx.x, d = threadIdx.x;   // 128 threads
    int qi  = q_data[t],  ti = time_data[t], ai = attempt_data[t];
    int hi  = hint_data[t], hti = hintTotal_data[t];
    float qe  = q_emb[(size_t)qi*DQ_ + d];
    float te  = time_emb[(size_t)ti*DQ_ + d];
    float ae  = attempt_emb[(size_t)ai*DQ_ + d];
    float he  = ht_emb[(size_t)hi*DQ_ + d];
    float hte = ht_emb[(size_t)hti*DQ_ + d];
    g_bufX[(size_t)t*DQ_ + d]        = te + qe;
    g_bufX[(size_t)(T_+t)*DQ_ + d]   = he + hte + ae + qe;
    int qai = qa_data[t];
    g_bufQA[(size_t)t*DV_ + d]        = qa_emb[(size_t)qai*DV_ + d];
    g_bufQA[(size_t)t*DV_ + DQ_ + d]  = qa_emb[(size_t)qai*DV_ + DQ_ + d];
}

// ---------------- X3 = qe + diff_final * (he+hte+ae) ----------------------
__global__ void k_buildx3(const int* __restrict__ q_data, const int* __restrict__ attempt_data,
                          const int* __restrict__ hint_data, const int* __restrict__ hintTotal_data,
                          const float* __restrict__ q_emb, const float* __restrict__ attempt_emb,
                          const float* __restrict__ ht_emb)
{
    int t = blockIdx.x, d = threadIdx.x;
    float qe = q_emb[(size_t)q_data[t]*DQ_ + d];
    float g  = attempt_emb[(size_t)attempt_data[t]*DQ_ + d]
             + ht_emb[(size_t)hint_data[t]*DQ_ + d]
             + ht_emb[(size_t)hintTotal_data[t]*DQ_ + d];
    float df = g_bufTD[(size_t)(T_+t)*DQ_ + d];
    g_bufX[(size_t)t*DQ_ + d] = fmaf(df, g, qe);
}

// ---------------- input_embed = q_proc + time_final * te ------------------
__global__ void k_inputembed(const int* __restrict__ time_data, const float* __restrict__ time_emb)
{
    int t = blockIdx.x, d = threadIdx.x;
    float te = time_emb[(size_t)time_data[t]*DQ_ + d];
    float tf = g_bufTD[(size_t)t*DQ_ + d];
    g_PredIn[(size_t)t*KRO_ + DV_ + d] = fmaf(tf, te, g_bufQP[(size_t)t*DQ_ + d]);
}

// ---------------- softmax over M=50 (warp per token, in place) ------------
__global__ void k_softmax()
{
    int t = blockIdx.x * 8 + (threadIdx.x >> 5);
    int l = threadIdx.x & 31;
    if (t >= T_) return;
    float v0 = (l < M_)      ? g_logits[(size_t)t*M_ + l]      : -1e30f;
    float v1 = (l + 32 < M_) ? g_logits[(size_t)t*M_ + l + 32] : -1e30f;
    float mx = fmaxf(v0, v1);
    #pragma unroll
    for (int o = 16; o; o >>= 1) mx = fmaxf(mx, __shfl_xor_sync(0xffffffffu, mx, o));
    float e0 = (l < M_)      ? expf(v0 - mx) : 0.f;
    float e1 = (l + 32 < M_) ? expf(v1 - mx) : 0.f;
    float s = e0 + e1;
    #pragma unroll
    for (int o = 16; o; o >>= 1) s += __shfl_xor_sync(0xffffffffu, s, o);
    float inv = 1.f / s;
    if (l < M_)      g_logits[(size_t)t*M_ + l]      = e0 * inv;
    if (l + 32 < M_) g_logits[(size_t)t*M_ + l + 32] = e1 * inv;
}

// ---------------- sequential DKVMN scan: Mv in registers ------------------
__global__ void __launch_bounds__(256) k_scan(const float* __restrict__ Mv0)
{
    int b = blockIdx.x, d = threadIdx.x;   // 256 threads, one per DV column
    float mv[M_];
    #pragma unroll
    for (int m = 0; m < M_; m++) mv[m] = Mv0[m*DV_ + d];
    __shared__ float ws[M_];
    for (int s = 0; s < S_; s++) {
        size_t t = (size_t)b * S_ + s;
        if (d < M_) ws[d] = g_logits[t*M_ + d];
        __syncthreads();
        float e = g_bufEA[t*NEA_ + d];
        float a = g_bufEA[t*NEA_ + DV_ + d];
        float rd = 0.f;
        #pragma unroll
        for (int m = 0; m < M_; m++) {
            float wm = ws[m];
            rd = fmaf(wm, mv[m], rd);                       // read uses pre-update Mv
            mv[m] = fmaf(mv[m], fmaf(-wm, e, 1.f), wm * a); // Mv*(1-w*e) + w*a
        }
        g_PredIn[t*KRO_ + d] = rd;
        __syncthreads();
    }
}

// ---------------- SGEMM: C = act(A @ W^T + bias) --------------------------
// ACT: 0=none, 1=tanh, 2=sigmoid, 3=EA (sigmoid n<256, tanh else),
//      4=readout (tanh + fused dot with predW -> atomic into pred, no C store)
template<int ACT>
__global__ void __launch_bounds__(256, 2) k_sgemm(
    const float* __restrict__ A, int lda, int Trows, int K,
    const float* __restrict__ W, int N,
    const float* __restrict__ bias,
    float* __restrict__ C, int ldc,
    const float* __restrict__ predW, float* __restrict__ pred)
{
    __shared__ float As[8][128];
    __shared__ float Wsm[8][128];
    __shared__ float sred[128];

    const int tid  = threadIdx.x;
    const int m0   = blockIdx.y * 128;
    const int n0   = blockIdx.x * 128;
    const int lrow = tid >> 1;
    const int lcol = (tid & 1) * 4;
    const int tm   = tid >> 4;
    const int tn   = tid & 15;

    const bool aok = (m0 + lrow) < Trows;
    const bool wok = (n0 + lrow) < N;
    const float* Aptr = A + (size_t)(m0 + lrow) * lda + lcol;
    const float* Wptr = W + (size_t)(n0 + lrow) * K   + lcol;

    float acc[8][8];
    #pragma unroll
    for (int i = 0; i < 8; i++)
        #pragma unroll
        for (int j = 0; j < 8; j++) acc[i][j] = 0.f;

    const int ktiles = K >> 3;
    float4 a4 = aok ? *(const float4*)Aptr : make_float4(0,0,0,0);
    float4 w4 = wok ? *(const float4*)Wptr : make_float4(0,0,0,0);

    for (int kt = 0; kt < ktiles; ++kt) {
        As [lcol+0][lrow] = a4.x; As [lcol+1][lrow] = a4.y; As [lcol+2][lrow] = a4.z; As [lcol+3][lrow] = a4.w;
        Wsm[lcol+0][lrow] = w4.x; Wsm[lcol+1][lrow] = w4.y; Wsm[lcol+2][lrow] = w4.z; Wsm[lcol+3][lrow] = w4.w;
        __syncthreads();
        if (kt + 1 < ktiles) {
            a4 = aok ? *(const float4*)(Aptr + (kt+1)*8) : make_float4(0,0,0,0);
            w4 = wok ? *(const float4*)(Wptr + (kt+1)*8) : make_float4(0,0,0,0);
        }
        #pragma unroll
        for (int k = 0; k < 8; k++) {
            float af[8], wf[8];
            *(float4*)(af)   = *(const float4*)(&As [k][tm*8]);
            *(float4*)(af+4) = *(const float4*)(&As [k][tm*8+4]);
            *(float4*)(wf)   = *(const float4*)(&Wsm[k][tn*8]);
            *(float4*)(wf+4) = *(const float4*)(&Wsm[k][tn*8+4]);
            #pragma unroll
            for (int i = 0; i < 8; i++)
                #pragma unroll
                for (int j = 0; j < 8; j++)
                    acc[i][j] = fmaf(af[i], wf[j], acc[i][j]);
        }
        __syncthreads();
    }

    if (ACT == 4) {
        float pp[8];
        #pragma unroll
        for (int i = 0; i < 8; i++) pp[i] = 0.f;
        #pragma unroll
        for (int i = 0; i < 8; i++) {
            #pragma unroll
            for (int j = 0; j < 8; j++) {
                int gn = n0 + tn*8 + j;
                if (gn < N) {
                    float v = tanhf(acc[i][j] + bias[gn]);
                    pp[i] = fmaf(v, __ldg(&predW[gn]), pp[i]);
                }
            }
        }
        if (tid < 128) sred[tid] = 0.f;
        __syncthreads();
        #pragma unroll
        for (int i = 0; i < 8; i++) atomicAdd(&sred[tm*8 + i], pp[i]);
        __syncthreads();
        if (tid < 128 && (m0 + tid) < Trows) atomicAdd(&pred[m0 + tid], sred[tid]);
    } else {
        #pragma unroll
        for (int i = 0; i < 8; i++) {
            int gm = m0 + tm*8 + i;
            if (gm >= Trows) continue;
            #pragma unroll
            for (int j = 0; j < 8; j++) {
                int gn = n0 + tn*8 + j;
                if (gn >= N) continue;
                float v = acc[i][j] + (bias ? bias[gn] : 0.f);
                if (ACT == 1) v = tanhf(v);
                else if (ACT == 2) v = 1.f / (1.f + expf(-v));
                else if (ACT == 3) v = (gn < DV_) ? 1.f / (1.f + expf(-v)) : tanhf(v);
                C[(size_t)gm*ldc + gn] = v;
            }
        }
    }
}

// ---------------- loss + outputs ------------------------------------------
__global__ void k_loss(const int* __restrict__ target, const float* __restrict__ pred_b,
                       float* __restrict__ out)
{
    int i = blockIdx.x * blockDim.x + threadIdx.x;
    float le = 0.f, cnt = 0.f;
    if (i < T_) {
        float p = g_predS[i] + pred_b[0];
        int tg = target[i];
        bool mask = tg >= 1;
        float y = mask ? (float)(tg - 1) : 0.f;
        float sig = 1.f / (1.f + expf(-p));
        out[1 + i]      = mask ? sig : 0.f;
        out[1 + T_ + i] = mask ? y   : 0.f;
        if (mask) {
            le = fmaxf(p, 0.f) + log1pf(expf(-fabsf(p))) - p * y;
            cnt = 1.f;
        }
    }
    __shared__ float sle[256], scn[256];
    sle[threadIdx.x] = le; scn[threadIdx.x] = cnt;
    __syncthreads();
    for (int o = 128; o; o >>= 1) {
        if (threadIdx.x < o) { sle[threadIdx.x] += sle[threadIdx.x + o]; scn[threadIdx.x] += scn[threadIdx.x + o]; }
        __syncthreads();
    }
    if (threadIdx.x == 0) { atomicAdd(&g_accum[0], sle[0]); atomicAdd(&g_accum[1], scn[0]); }
}

__global__ void k_final(float* __restrict__ out)
{
    out[0] = g_accum[0] / fmaxf(g_accum[1], 1.f);
}

// ---------------- host launch ----------------------------------------------
extern "C" void kernel_launch(void* const* d_in, const int* in_sizes, int n_in,
                              void* d_out, int out_size)
{
    const int*   q_data      = (const int*)  d_in[0];
    const int*   qa_data     = (const int*)  d_in[1];
    const int*   target      = (const int*)  d_in[2];
    const int*   time_data   = (const int*)  d_in[3];
    const int*   attempt_data= (const int*)  d_in[4];
    const int*   hint_data   = (const int*)  d_in[5];
    const int*   hintTotal   = (const int*)  d_in[6];
    const float* q_emb       = (const float*)d_in[7];
    const float* qa_emb      = (const float*)d_in[8];
    const float* time_emb    = (const float*)d_in[9];
    const float* attempt_emb = (const float*)d_in[10];
    const float* ht_emb      = (const float*)d_in[11];
    const float* Mk          = (const float*)d_in[12];
    const float* Mv0         = (const float*)d_in[13];
    const float* diff_W      = (const float*)d_in[14];
    const float* diff_b      = (const float*)d_in[15];
    const float* diff2_W     = (const float*)d_in[16];
    const float* diff2_b     = (const float*)d_in[17];
    const float* erase_W     = (const float*)d_in[18];
    const float* erase_b     = (const float*)d_in[19];
    const float* add_W       = (const float*)d_in[20];
    const float* add_b       = (const float*)d_in[21];
    const float* read_W      = (const float*)d_in[22];
    const float* read_b      = (const float*)d_in[23];
    const float* pred_W      = (const float*)d_in[24];
    const float* pred_b      = (const float*)d_in[25];
    float* out = (float*)d_out;

    float *bufX, *bufU, *bufTD, *bufQP, *bufQA, *bufEA, *predin, *logits, *predS, *Wea, *bea;
    cudaGetSymbolAddress((void**)&bufX,   g_bufX);
    cudaGetSymbolAddress((void**)&bufU,   g_bufU);
    cudaGetSymbolAddress((void**)&bufTD,  g_bufTD);
    cudaGetSymbolAddress((void**)&bufQP,  g_bufQP);
    cudaGetSymbolAddress((void**)&bufQA,  g_bufQA);
    cudaGetSymbolAddress((void**)&bufEA,  g_bufEA);
    cudaGetSymbolAddress((void**)&predin, g_PredIn);
    cudaGetSymbolAddress((void**)&logits, g_logits);
    cudaGetSymbolAddress((void**)&predS,  g_predS);
    cudaGetSymbolAddress((void**)&Wea,    g_Wea);
    cudaGetSymbolAddress((void**)&bea,    g_bea);

    // 0) zero pred/accum, build concat EA weights
    k_prep<<<512, 256>>>(erase_W, erase_b, add_W, add_b);

    // 1) gather: X1, X2, qa_e
    k_gather1<<<T_, 128>>>(q_data, qa_data, time_data, attempt_data, hint_data, hintTotal,
                           q_emb, qa_emb, time_emb, attempt_emb, ht_emb);

    // 2) U = tanh(lin1(X)) over 2T rows
    k_sgemm<1><<<dim3(1, 2*T_/128), 256>>>(bufX, DQ_, 2*T_, DQ_, diff_W, DQ_, diff_b,
                                           bufU, DQ_, nullptr, nullptr);
    // 3) TD = sigmoid(lin2(U)) over 2T rows -> time_final, diff_final
    k_sgemm<2><<<dim3(1, 2*T_/128), 256>>>(bufU, DQ_, 2*T_, DQ_, diff2_W, DQ_, diff2_b,
                                           bufTD, DQ_, nullptr, nullptr);
    // 4) X3 = qe + diff_final * g
    k_buildx3<<<T_, 128>>>(q_data, attempt_data, hint_data, hintTotal, q_emb, attempt_emb, ht_emb);
    // 5) q_proc = lin1(X3)
    k_sgemm<0><<<dim3(1, T_/128), 256>>>(bufX, DQ_, T_, DQ_, diff_W, DQ_, diff_b,
                                         bufQP, DQ_, nullptr, nullptr);
    // 6) input_embed into PredIn cols [256,384)
    k_inputembed<<<T_, 128>>>(time_data, time_emb);
    // 7) attention logits = q_proc @ Mk^T
    k_sgemm<0><<<dim3(1, T_/128), 256>>>(bufQP, DQ_, T_, DQ_, Mk, M_, nullptr,
                                         logits, M_, nullptr, nullptr);
    // 8) softmax over M (in place)
    k_softmax<<<T_/8, 256>>>();
    // 9) E/A = [sigmoid|tanh](qa @ [erase|add]^T + b)
    k_sgemm<3><<<dim3(4, T_/128), 256>>>(bufQA, DV_, T_, KEA_, Wea, NEA_, bea,
                                         bufEA, NEA_, nullptr, nullptr);
    // 10) sequential scan -> reads into PredIn cols [0,256)
    k_scan<<<B_, 256>>>(Mv0);
    // 11) readout GEMM + fused pred reduction
    k_sgemm<4><<<dim3(4, T_/128), 256>>>(predin, KRO_, T_, KRO_, read_W, F_, read_b,
                                         nullptr, 0, pred_W, predS);
    // 12) loss elements + outputs
    k_loss<<<(T_ + 255)/256, 256>>>(target, pred_b, out);
    // 13) final loss
    k_final<<<1, 1>>>(out);
}

// round 4
// speedup vs baseline: 1.7518x; 1.7518x over previous
#include <cuda_runtime.h>
#include <math.h>
#include <stdint.h>

#define B_   256
#define S_   500
#define T_   (B_*S_)        // 128000
#define DQ_  128
#define DV_  256
#define M_   50
#define F_   512
#define NEA_ 512
#define KEA_ 256
#define KRO_ 384            // DV + DQ

// ---------------- scratch (device globals; no allocations) ----------------
__device__ float g_bufX [2*T_*DQ_];
__device__ float g_bufU [2*T_*DQ_];
__device__ float g_bufTD[2*T_*DQ_];
__device__ float g_bufQP[T_*DQ_];
__device__ float g_bufQA[T_*DV_];
__device__ float g_bufEA[T_*NEA_];
__device__ float g_PredIn[T_*KRO_];
__device__ float g_logits[T_*M_];
__device__ float g_predS[T_];
__device__ float g_accum[2];
__device__ float g_Wea[NEA_*KEA_];
__device__ float g_bea[NEA_];

// ==================== tf32 helpers (legacy mma.sync — compute_103-safe) ====
__device__ __forceinline__ uint32_t f2tf(float x) {
    uint32_t r;
    asm("cvt.rna.tf32.f32 %0, %1;" : "=r"(r) : "f"(x));
    return r;
}
__device__ __forceinline__ void mma8(float* d,
    uint32_t a0, uint32_t a1, uint32_t a2, uint32_t a3,
    uint32_t b0, uint32_t b1)
{
    asm volatile(
        "mma.sync.aligned.m16n8k8.row.col.f32.tf32.tf32.f32 "
        "{%0,%1,%2,%3},{%4,%5,%6,%7},{%8,%9},{%0,%1,%2,%3};"
        : "+f"(d[0]), "+f"(d[1]), "+f"(d[2]), "+f"(d[3])
        : "r"(a0), "r"(a1), "r"(a2), "r"(a3), "r"(b0), "r"(b1));
}

// ==================== tensor-core GEMM: C = act(A @ W^T + bias) ============
// CTA tile 128x128, 8 warps (2 m x 4 n), warp tile 64x32, K chunk 16.
// Smem k-permuted layout: k' = (k%4)*4 + k/4 -> each thread's 4 fragment
// scalars for both k-steps of a chunk form ONE contiguous uint4.
// ACT: 0=none 1=tanh 2=sigmoid 3=EA-split(sigmoid n<256 else tanh)
//      4=readout (tanh, fused dot with predW -> predS, no C store)
template<int ACT>
__global__ void __launch_bounds__(256, 2) k_mma(
    const float* __restrict__ A, int lda, int K,
    const float* __restrict__ W,
    const float* __restrict__ bias,
    float* __restrict__ C, int ldc,
    const float* __restrict__ predW, float* __restrict__ predS)
{
    __shared__ uint32_t As[128*16];
    __shared__ uint32_t Bs[128*16];
    __shared__ float sred[128];

    const int tid  = threadIdx.x;
    const int m0   = blockIdx.y * 128;
    const int n0   = blockIdx.x * 128;
    const int lane = tid & 31, w = tid >> 5;
    const int g    = lane >> 2, c = lane & 3;
    const int wm0  = (w >> 2) * 64;
    const int wn0  = (w & 3) * 32;
    const int srow = tid >> 2;
    const int sc4  = (tid & 3) * 4;

    const float* Ap = A + (size_t)(m0 + srow) * lda + sc4;
    const float* Wp = W + (size_t)(n0 + srow) * K   + sc4;
    const size_t astep = (size_t)64 * lda;
    const size_t wstep = (size_t)64 * K;

    float acc[4][4][4];
    #pragma unroll
    for (int i = 0; i < 4; i++)
        #pragma unroll
        for (int j = 0; j < 4; j++)
            #pragma unroll
            for (int r = 0; r < 4; r++) acc[i][j][r] = 0.f;

    if (ACT == 4 && tid < 128) sred[tid] = 0.f;

    const int nch = K >> 4;
    float4 pa0 = *(const float4*)Ap;
    float4 pa1 = *(const float4*)(Ap + astep);
    float4 pw0 = *(const float4*)Wp;
    float4 pw1 = *(const float4*)(Wp + wstep);

    const int sb0 = srow * 16 + (sc4 >> 2);
    const int sb1 = (srow + 64) * 16 + (sc4 >> 2);

    for (int ch = 0; ch < nch; ch++) {
        As[sb0+0]  = f2tf(pa0.x); As[sb0+4]  = f2tf(pa0.y); As[sb0+8]  = f2tf(pa0.z); As[sb0+12] = f2tf(pa0.w);
        As[sb1+0]  = f2tf(pa1.x); As[sb1+4]  = f2tf(pa1.y); As[sb1+8]  = f2tf(pa1.z); As[sb1+12] = f2tf(pa1.w);
        Bs[sb0+0]  = f2tf(pw0.x); Bs[sb0+4]  = f2tf(pw0.y); Bs[sb0+8]  = f2tf(pw0.z); Bs[sb0+12] = f2tf(pw0.w);
        Bs[sb1+0]  = f2tf(pw1.x); Bs[sb1+4]  = f2tf(pw1.y); Bs[sb1+8]  = f2tf(pw1.z); Bs[sb1+12] = f2tf(pw1.w);
        __syncthreads();
        if (ch + 1 < nch) {
            pa0 = *(const float4*)(Ap + (ch+1)*16);
            pa1 = *(const float4*)(Ap + astep + (ch+1)*16);
            pw0 = *(const float4*)(Wp + (ch+1)*16);
            pw1 = *(const float4*)(Wp + wstep + (ch+1)*16);
        }
        uint4 bq[4];
        #pragma unroll
        for (int ni = 0; ni < 4; ni++)
            bq[ni] = *(const uint4*)&Bs[(wn0 + ni*8 + g) * 16 + c*4];
        #pragma unroll
        for (int mi = 0; mi < 4; mi++) {
            uint4 alo = *(const uint4*)&As[(wm0 + mi*16 + g)     * 16 + c*4];
            uint4 ahi = *(const uint4*)&As[(wm0 + mi*16 + g + 8) * 16 + c*4];
            #pragma unroll
            for (int ni = 0; ni < 4; ni++) {
                mma8(acc[mi][ni], alo.x, ahi.x, alo.y, ahi.y, bq[ni].x, bq[ni].y);
                mma8(acc[mi][ni], alo.z, ahi.z, alo.w, ahi.w, bq[ni].z, bq[ni].w);
            }
        }
        __syncthreads();
    }

    if (ACT == 4) {
        float rsum[4][2];
        #pragma unroll
        for (int mi = 0; mi < 4; mi++) { rsum[mi][0] = 0.f; rsum[mi][1] = 0.f; }
        #pragma unroll
        for (int mi = 0; mi < 4; mi++)
            #pragma unroll
            for (int ni = 0; ni < 4; ni++) {
                int cn = n0 + wn0 + ni*8 + c*2;
                float b0 = __ldg(&bias[cn]),  b1 = __ldg(&bias[cn+1]);
                float p0 = __ldg(&predW[cn]), p1 = __ldg(&predW[cn+1]);
                rsum[mi][0] += tanhf(acc[mi][ni][0] + b0) * p0 + tanhf(acc[mi][ni][1] + b1) * p1;
                rsum[mi][1] += tanhf(acc[mi][ni][2] + b0) * p0 + tanhf(acc[mi][ni][3] + b1) * p1;
            }
        #pragma unroll
        for (int mi = 0; mi < 4; mi++)
            #pragma unroll
            for (int h = 0; h < 2; h++) {
                float v = rsum[mi][h];
                v += __shfl_xor_sync(0xffffffffu, v, 1);
                v += __shfl_xor_sync(0xffffffffu, v, 2);
                if (c == 0) atomicAdd(&sred[wm0 + mi*16 + h*8 + g], v);
            }
        __syncthreads();
        if (tid < 128) atomicAdd(&predS[m0 + tid], sred[tid]);
    } else {
        #pragma unroll
        for (int mi = 0; mi < 4; mi++) {
            int r0 = m0 + wm0 + mi*16 + g;
            #pragma unroll
            for (int ni = 0; ni < 4; ni++) {
                int cn = n0 + wn0 + ni*8 + c*2;
                float b0 = __ldg(&bias[cn]), b1 = __ldg(&bias[cn+1]);
                float v0 = acc[mi][ni][0] + b0, v1 = acc[mi][ni][1] + b1;
                float v2 = acc[mi][ni][2] + b0, v3 = acc[mi][ni][3] + b1;
                if (ACT == 1) { v0 = tanhf(v0); v1 = tanhf(v1); v2 = tanhf(v2); v3 = tanhf(v3); }
                else if (ACT == 2) {
                    v0 = 1.f/(1.f+expf(-v0)); v1 = 1.f/(1.f+expf(-v1));
                    v2 = 1.f/(1.f+expf(-v2)); v3 = 1.f/(1.f+expf(-v3));
                } else if (ACT == 3) {
                    if (cn < DV_) { v0 = 1.f/(1.f+expf(-v0)); v1 = 1.f/(1.f+expf(-v1));
                                    v2 = 1.f/(1.f+expf(-v2)); v3 = 1.f/(1.f+expf(-v3)); }
                    else          { v0 = tanhf(v0); v1 = tanhf(v1); v2 = tanhf(v2); v3 = tanhf(v3); }
                }
                *(float2*)&C[(size_t)r0    *ldc + cn] = make_float2(v0, v1);
                *(float2*)&C[(size_t)(r0+8)*ldc + cn] = make_float2(v2, v3);
            }
        }
    }
}

// ==================== FFMA SGEMM (kept for logits, N=50) ====================
template<int ACT>
__global__ void __launch_bounds__(256, 2) k_sgemm(
    const float* __restrict__ A, int lda, int Trows, int K,
    const float* __restrict__ W, int N,
    const float* __restrict__ bias,
    float* __restrict__ C, int ldc,
    const float* __restrict__ predW, float* __restrict__ pred)
{
    __shared__ float As[8][128];
    __shared__ float Wsm[8][128];

    const int tid  = threadIdx.x;
    const int m0   = blockIdx.y * 128;
    const int n0   = blockIdx.x * 128;
    const int lrow = tid >> 1;
    const int lcol = (tid & 1) * 4;
    const int tm   = tid >> 4;
    const int tn   = tid & 15;

    const bool aok = (m0 + lrow) < Trows;
    const bool wok = (n0 + lrow) < N;
    const float* Aptr = A + (size_t)(m0 + lrow) * lda + lcol;
    const float* Wptr = W + (size_t)(n0 + lrow) * K   + lcol;

    float acc[8][8];
    #pragma unroll
    for (int i = 0; i < 8; i++)
        #pragma unroll
        for (int j = 0; j < 8; j++) acc[i][j] = 0.f;

    const int ktiles = K >> 3;
    float4 a4 = aok ? *(const float4*)Aptr : make_float4(0,0,0,0);
    float4 w4 = wok ? *(const float4*)Wptr : make_float4(0,0,0,0);

    for (int kt = 0; kt < ktiles; ++kt) {
        As [lcol+0][lrow] = a4.x; As [lcol+1][lrow] = a4.y; As [lcol+2][lrow] = a4.z; As [lcol+3][lrow] = a4.w;
        Wsm[lcol+0][lrow] = w4.x; Wsm[lcol+1][lrow] = w4.y; Wsm[lcol+2][lrow] = w4.z; Wsm[lcol+3][lrow] = w4.w;
        __syncthreads();
        if (kt + 1 < ktiles) {
            a4 = aok ? *(const float4*)(Aptr + (kt+1)*8) : make_float4(0,0,0,0);
            w4 = wok ? *(const float4*)(Wptr + (kt+1)*8) : make_float4(0,0,0,0);
        }
        #pragma unroll
        for (int k = 0; k < 8; k++) {
            float af[8], wf[8];
            *(float4*)(af)   = *(const float4*)(&As [k][tm*8]);
            *(float4*)(af+4) = *(const float4*)(&As [k][tm*8+4]);
            *(float4*)(wf)   = *(const float4*)(&Wsm[k][tn*8]);
            *(float4*)(wf+4) = *(const float4*)(&Wsm[k][tn*8+4]);
            #pragma unroll
            for (int i = 0; i < 8; i++)
                #pragma unroll
                for (int j = 0; j < 8; j++)
                    acc[i][j] = fmaf(af[i], wf[j], acc[i][j]);
        }
        __syncthreads();
    }

    #pragma unroll
    for (int i = 0; i < 8; i++) {
        int gm = m0 + tm*8 + i;
        if (gm >= Trows) continue;
        #pragma unroll
        for (int j = 0; j < 8; j++) {
            int gn = n0 + tn*8 + j;
            if (gn >= N) continue;
            float v = acc[i][j] + (bias ? bias[gn] : 0.f);
            if (ACT == 1) v = tanhf(v);
            else if (ACT == 2) v = 1.f / (1.f + expf(-v));
            C[(size_t)gm*ldc + gn] = v;
        }
    }
}

// ==================== small kernels ====================
__global__ void k_prep(const float* __restrict__ eW, const float* __restrict__ eb,
                       const float* __restrict__ aW, const float* __restrict__ ab)
{
    int i = blockIdx.x * blockDim.x + threadIdx.x;
    int stride = gridDim.x * blockDim.x;
    for (int j = i; j < NEA_*KEA_; j += stride) {
        int n = j / KEA_, k = j % KEA_;
        g_Wea[j] = (n < DV_) ? eW[n*KEA_ + k] : aW[(n - DV_)*KEA_ + k];
    }
    for (int j = i; j < NEA_; j += stride) g_bea[j] = (j < DV_) ? eb[j] : ab[j - DV_];
    for (int j = i; j < T_;  j += stride) g_predS[j] = 0.f;
    if (i < 2) g_accum[i] = 0.f;
}

__global__ void k_gather1(const int* __restrict__ q_data, const int* __restrict__ qa_data,
                          const int* __restrict__ time_data, const int* __restrict__ attempt_data,
                          const int* __restrict__ hint_data, const int* __restrict__ hintTotal_data,
                          const float* __restrict__ q_emb, const float* __restrict__ qa_emb,
                          const float* __restrict__ time_emb, const float* __restrict__ attempt_emb,
                          const float* __restrict__ ht_emb)
{
    int t = blockIdx.x, d = threadIdx.x;
    int qi = q_data[t], ti = time_data[t], ai = attempt_data[t];
    int hi = hint_data[t], hti = hintTotal_data[t];
    float qe  = q_emb[(size_t)qi*DQ_ + d];
    float te  = time_emb[(size_t)ti*DQ_ + d];
    float ae  = attempt_emb[(size_t)ai*DQ_ + d];
    float he  = ht_emb[(size_t)hi*DQ_ + d];
    float hte = ht_emb[(size_t)hti*DQ_ + d];
    g_bufX[(size_t)t*DQ_ + d]      = te + qe;
    g_bufX[(size_t)(T_+t)*DQ_ + d] = he + hte + ae + qe;
    int qai = qa_data[t];
    g_bufQA[(size_t)t*DV_ + d]       = qa_emb[(size_t)qai*DV_ + d];
    g_bufQA[(size_t)t*DV_ + DQ_ + d] = qa_emb[(size_t)qai*DV_ + DQ_ + d];
}

__global__ void k_buildx3(const int* __restrict__ q_data, const int* __restrict__ attempt_data,
                          const int* __restrict__ hint_data, const int* __restrict__ hintTotal_data,
                          const float* __restrict__ q_emb, const float* __restrict__ attempt_emb,
                          const float* __restrict__ ht_emb)
{
    int t = blockIdx.x, d = threadIdx.x;
    float qe = q_emb[(size_t)q_data[t]*DQ_ + d];
    float g  = attempt_emb[(size_t)attempt_data[t]*DQ_ + d]
             + ht_emb[(size_t)hint_data[t]*DQ_ + d]
             + ht_emb[(size_t)hintTotal_data[t]*DQ_ + d];
    float df = g_bufTD[(size_t)(T_+t)*DQ_ + d];
    g_bufX[(size_t)t*DQ_ + d] = fmaf(df, g, qe);
}

__global__ void k_inputembed(const int* __restrict__ time_data, const float* __restrict__ time_emb)
{
    int t = blockIdx.x, d = threadIdx.x;
    float te = time_emb[(size_t)time_data[t]*DQ_ + d];
    float tf = g_bufTD[(size_t)t*DQ_ + d];
    g_PredIn[(size_t)t*KRO_ + DV_ + d] = fmaf(tf, te, g_bufQP[(size_t)t*DQ_ + d]);
}

__global__ void k_softmax()
{
    int t = blockIdx.x * 8 + (threadIdx.x >> 5);
    int l = threadIdx.x & 31;
    if (t >= T_) return;
    float v0 = (l < M_)      ? g_logits[(size_t)t*M_ + l]      : -1e30f;
    float v1 = (l + 32 < M_) ? g_logits[(size_t)t*M_ + l + 32] : -1e30f;
    float mx = fmaxf(v0, v1);
    #pragma unroll
    for (int o = 16; o; o >>= 1) mx = fmaxf(mx, __shfl_xor_sync(0xffffffffu, mx, o));
    float e0 = (l < M_)      ? expf(v0 - mx) : 0.f;
    float e1 = (l + 32 < M_) ? expf(v1 - mx) : 0.f;
    float s = e0 + e1;
    #pragma unroll
    for (int o = 16; o; o >>= 1) s += __shfl_xor_sync(0xffffffffu, s, o);
    float inv = 1.f / s;
    if (l < M_)      g_logits[(size_t)t*M_ + l]      = e0 * inv;
    if (l + 32 < M_) g_logits[(size_t)t*M_ + l + 32] = e1 * inv;
}

// DV split 2-way -> 512 CTAs
__global__ void __launch_bounds__(128) k_scan(const float* __restrict__ Mv0)
{
    int b = blockIdx.x;
    int d = blockIdx.y * 128 + threadIdx.x;
    float mv[M_];
    #pragma unroll
    for (int m = 0; m < M_; m++) mv[m] = Mv0[m*DV_ + d];
    __shared__ float ws[M_];
    for (int s = 0; s < S_; s++) {
        size_t t = (size_t)b * S_ + s;
        if (threadIdx.x < M_) ws[threadIdx.x] = g_logits[t*M_ + threadIdx.x];
        __syncthreads();
        float e = g_bufEA[t*NEA_ + d];
        float a = g_bufEA[t*NEA_ + DV_ + d];
        float rd = 0.f;
        #pragma unroll
        for (int m = 0; m < M_; m++) {
            float wm = ws[m];
            rd = fmaf(wm, mv[m], rd);
            mv[m] = fmaf(mv[m], fmaf(-wm, e, 1.f), wm * a);
        }
        g_PredIn[t*KRO_ + d] = rd;
        __syncthreads();
    }
}

__global__ void k_loss(const int* __restrict__ target, const float* __restrict__ pred_b,
                       float* __restrict__ out)
{
    int i = blockIdx.x * blockDim.x + threadIdx.x;
    float le = 0.f, cnt = 0.f;
    if (i < T_) {
        float p = g_predS[i] + pred_b[0];
        int tg = target[i];
        bool mask = tg >= 1;
        float y = mask ? (float)(tg - 1) : 0.f;
        float sig = 1.f / (1.f + expf(-p));
        out[1 + i]      = mask ? sig : 0.f;
        out[1 + T_ + i] = mask ? y   : 0.f;
        if (mask) {
            le = fmaxf(p, 0.f) + log1pf(expf(-fabsf(p))) - p * y;
            cnt = 1.f;
        }
    }
    __shared__ float sle[256], scn[256];
    sle[threadIdx.x] = le; scn[threadIdx.x] = cnt;
    __syncthreads();
    for (int o = 128; o; o >>= 1) {
        if (threadIdx.x < o) { sle[threadIdx.x] += sle[threadIdx.x + o]; scn[threadIdx.x] += scn[threadIdx.x + o]; }
        __syncthreads();
    }
    if (threadIdx.x == 0) { atomicAdd(&g_accum[0], sle[0]); atomicAdd(&g_accum[1], scn[0]); }
}

__global__ void k_final(float* __restrict__ out)
{
    out[0] = g_accum[0] / fmaxf(g_accum[1], 1.f);
}

// ==================== host ====================
extern "C" void kernel_launch(void* const* d_in, const int* in_sizes, int n_in,
                              void* d_out, int out_size)
{
    const int*   q_data      = (const int*)  d_in[0];
    const int*   qa_data     = (const int*)  d_in[1];
    const int*   target      = (const int*)  d_in[2];
    const int*   time_data   = (const int*)  d_in[3];
    const int*   attempt_data= (const int*)  d_in[4];
    const int*   hint_data   = (const int*)  d_in[5];
    const int*   hintTotal   = (const int*)  d_in[6];
    const float* q_emb       = (const float*)d_in[7];
    const float* qa_emb      = (const float*)d_in[8];
    const float* time_emb    = (const float*)d_in[9];
    const float* attempt_emb = (const float*)d_in[10];
    const float* ht_emb      = (const float*)d_in[11];
    const float* Mk          = (const float*)d_in[12];
    const float* Mv0         = (const float*)d_in[13];
    const float* diff_W      = (const float*)d_in[14];
    const float* diff_b      = (const float*)d_in[15];
    const float* diff2_W     = (const float*)d_in[16];
    const float* diff2_b     = (const float*)d_in[17];
    const float* erase_W     = (const float*)d_in[18];
    const float* erase_b     = (const float*)d_in[19];
    const float* add_W       = (const float*)d_in[20];
    const float* add_b       = (const float*)d_in[21];
    const float* read_W      = (const float*)d_in[22];
    const float* read_b      = (const float*)d_in[23];
    const float* pred_W      = (const float*)d_in[24];
    const float* pred_b      = (const float*)d_in[25];
    float* out = (float*)d_out;

    float *bufX, *bufU, *bufTD, *bufQP, *bufQA, *bufEA, *predin, *logits, *predS, *Wea, *bea;
    cudaGetSymbolAddress((void**)&bufX,   g_bufX);
    cudaGetSymbolAddress((void**)&bufU,   g_bufU);
    cudaGetSymbolAddress((void**)&bufTD,  g_bufTD);
    cudaGetSymbolAddress((void**)&bufQP,  g_bufQP);
    cudaGetSymbolAddress((void**)&bufQA,  g_bufQA);
    cudaGetSymbolAddress((void**)&bufEA,  g_bufEA);
    cudaGetSymbolAddress((void**)&predin, g_PredIn);
    cudaGetSymbolAddress((void**)&logits, g_logits);
    cudaGetSymbolAddress((void**)&predS,  g_predS);
    cudaGetSymbolAddress((void**)&Wea,    g_Wea);
    cudaGetSymbolAddress((void**)&bea,    g_bea);

    // 0) concat EA weights, zero predS/accum
    k_prep<<<512, 256>>>(erase_W, erase_b, add_W, add_b);
    // 1) gathers
    k_gather1<<<T_, 128>>>(q_data, qa_data, time_data, attempt_data, hint_data, hintTotal,
                           q_emb, qa_emb, time_emb, attempt_emb, ht_emb);
    // 2) U = tanh(lin1(X)) over 2T rows
    k_mma<1><<<dim3(1, 2*T_/128), 256>>>(bufX, DQ_, DQ_, diff_W, diff_b, bufU, DQ_, nullptr, nullptr);
    // 3) TD = sigmoid(lin2(U)) over 2T rows
    k_mma<2><<<dim3(1, 2*T_/128), 256>>>(bufU, DQ_, DQ_, diff2_W, diff2_b, bufTD, DQ_, nullptr, nullptr);
    // 4) X3 = qe + diff_final * g
    k_buildx3<<<T_, 128>>>(q_data, attempt_data, hint_data, hintTotal, q_emb, attempt_emb, ht_emb);
    // 5) q_proc = lin1(X3)
    k_mma<0><<<dim3(1, T_/128), 256>>>(bufX, DQ_, DQ_, diff_W, diff_b, bufQP, DQ_, nullptr, nullptr);
    // 6) input_embed into PredIn cols [256,384)
    k_inputembed<<<T_, 128>>>(time_data, time_emb);
    // 7) logits = q_proc @ Mk^T (N=50, FFMA path with guards)
    k_sgemm<0><<<dim3(1, T_/128), 256>>>(bufQP, DQ_, T_, DQ_, Mk, M_, nullptr,
                                         logits, M_, nullptr, nullptr);
    // 8) softmax
    k_softmax<<<T_/8, 256>>>();
    // 9) E/A
    k_mma<3><<<dim3(4, T_/128), 256>>>(bufQA, KEA_, KEA_, Wea, bea, bufEA, NEA_, nullptr, nullptr);
    // 10) scan -> reads
    k_scan<<<dim3(B_, 2), 128>>>(Mv0);
    // 11) readout + fused pred dot
    k_mma<4><<<dim3(4, T_/128), 256>>>(predin, KRO_, KRO_, read_W, read_b, nullptr, 0, pred_W, predS);
    // 12) loss + outputs
    k_loss<<<(T_ + 255)/256, 256>>>(target, pred_b, out);
    k_final<<<1, 1>>>(out);
}

// round 5
// speedup vs baseline: 1.9700x; 1.1246x over previous
#include <cuda_runtime.h>
#include <math.h>
#include <stdint.h>

#define B_   256
#define S_   500
#define T_   (B_*S_)        // 128000
#define DQ_  128
#define DV_  256
#define M_   50
#define F_   512
#define NEA_ 512
#define KEA_ 256
#define KRO_ 384            // DV + DQ

// ---------------- scratch (device globals; no allocations) ----------------
__device__ float g_bufX [2*T_*DQ_];
__device__ float g_bufU [2*T_*DQ_];
__device__ float g_bufTD[2*T_*DQ_];
__device__ float g_bufQP[T_*DQ_];
__device__ float g_bufQA[T_*DV_];
__device__ float g_bufEA[T_*NEA_];
__device__ float g_PredIn[T_*KRO_];
__device__ float g_logits[T_*M_];
__device__ float g_predS[T_];
__device__ float g_accum[2];
__device__ uint32_t g_Wea[NEA_*KEA_];   // pre-rounded tf32 bits
__device__ uint32_t g_Wd1[DQ_*DQ_];
__device__ uint32_t g_Wd2[DQ_*DQ_];
__device__ uint32_t g_Wro[F_*KRO_];
__device__ float g_bea[NEA_];

// ==================== tf32 helpers ====================
__device__ __forceinline__ uint32_t f2tf(float x) {
    uint32_t r;
    asm("cvt.rna.tf32.f32 %0, %1;" : "=r"(r) : "f"(x));
    return r;
}
__device__ __forceinline__ float tf32r(float x) { return __uint_as_float(f2tf(x)); }

__device__ __forceinline__ void mma8(float* d,
    uint32_t a0, uint32_t a1, uint32_t a2, uint32_t a3,
    uint32_t b0, uint32_t b1)
{
    asm volatile(
        "mma.sync.aligned.m16n8k8.row.col.f32.tf32.tf32.f32 "
        "{%0,%1,%2,%3},{%4,%5,%6,%7},{%8,%9},{%0,%1,%2,%3};"
        : "+f"(d[0]), "+f"(d[1]), "+f"(d[2]), "+f"(d[3])
        : "r"(a0), "r"(a1), "r"(a2), "r"(a3), "r"(b0), "r"(b1));
}

// ==================== tensor-core GEMM: C = act(A @ W^T + bias) ============
// CTA 128x128, 8 warps (2m x 4n), warp tile 64x32, K chunk 16, 2-stage smem.
// Operands are PRE-ROUNDED to tf32 (A by producers, W by k_prep) -> no cvt here.
// Global loads use stride-4 k so staging is 4x STS.128, conflict-free.
// ACT: 0=none 1=tanh(+tf32 round) 2=sigmoid 3=EA-split 4=readout fused pred dot
template<int ACT>
__global__ void __launch_bounds__(256, 2) k_mma(
    const float* __restrict__ A, int lda, int K,
    const uint32_t* __restrict__ W,
    const float* __restrict__ bias,
    float* __restrict__ C, int ldc,
    const float* __restrict__ predW, float* __restrict__ predS)
{
    __shared__ uint32_t As[2][128*16];
    __shared__ uint32_t Bs[2][128*16];
    __shared__ float sred[128];

    const int tid  = threadIdx.x;
    const int m0   = blockIdx.y * 128;
    const int n0   = blockIdx.x * 128;
    const int lane = tid & 31, w = tid >> 5;
    const int g    = lane >> 2, c = lane & 3;
    const int wm0  = (w >> 2) * 64;
    const int wn0  = (w & 3) * 32;
    const int srow = tid >> 2;
    const int lc   = tid & 3;

    const float*    Ap = A + (size_t)(m0 + srow) * lda + lc;
    const uint32_t* Wp = W + (size_t)(n0 + srow) * K   + lc;
    const size_t astep = (size_t)64 * lda;
    const size_t wstep = (size_t)64 * K;
    const int st0 = srow * 16 + lc * 4;          // uint4-aligned word index
    const int st1 = (srow + 64) * 16 + lc * 4;

    float acc[4][4][4];
    #pragma unroll
    for (int i = 0; i < 4; i++)
        #pragma unroll
        for (int j = 0; j < 4; j++)
            #pragma unroll
            for (int r = 0; r < 4; r++) acc[i][j][r] = 0.f;

    if (ACT == 4 && tid < 128) sred[tid] = 0.f;

    uint32_t ra0[4], ra1[4], rw0[4], rw1[4];
    const int nch = K >> 4;

    #pragma unroll
    for (int i = 0; i < 4; i++) {           // k = lc + 4i  -> contiguous in permuted layout
        ra0[i] = __float_as_uint(__ldg(Ap + 4*i));
        ra1[i] = __float_as_uint(__ldg(Ap + astep + 4*i));
        rw0[i] = __ldg(Wp + 4*i);
        rw1[i] = __ldg(Wp + wstep + 4*i);
    }
    *(uint4*)&As[0][st0] = make_uint4(ra0[0], ra0[1], ra0[2], ra0[3]);
    *(uint4*)&As[0][st1] = make_uint4(ra1[0], ra1[1], ra1[2], ra1[3]);
    *(uint4*)&Bs[0][st0] = make_uint4(rw0[0], rw0[1], rw0[2], rw0[3]);
    *(uint4*)&Bs[0][st1] = make_uint4(rw1[0], rw1[1], rw1[2], rw1[3]);

    for (int ch = 0; ch < nch; ch++) {
        __syncthreads();
        if (ch + 1 < nch) {
            const int ko = (ch + 1) * 16;
            #pragma unroll
            for (int i = 0; i < 4; i++) {
                ra0[i] = __float_as_uint(__ldg(Ap + ko + 4*i));
                ra1[i] = __float_as_uint(__ldg(Ap + astep + ko + 4*i));
                rw0[i] = __ldg(Wp + ko + 4*i);
                rw1[i] = __ldg(Wp + wstep + ko + 4*i);
            }
        }
        const uint32_t* as = As[ch & 1];
        const uint32_t* bs = Bs[ch & 1];
        uint4 bq[4];
        #pragma unroll
        for (int ni = 0; ni < 4; ni++)
            bq[ni] = *(const uint4*)&bs[(wn0 + ni*8 + g) * 16 + c*4];
        #pragma unroll
        for (int mi = 0; mi < 4; mi++) {
            uint4 alo = *(const uint4*)&as[(wm0 + mi*16 + g)     * 16 + c*4];
            uint4 ahi = *(const uint4*)&as[(wm0 + mi*16 + g + 8) * 16 + c*4];
            #pragma unroll
            for (int ni = 0; ni < 4; ni++) {
                mma8(acc[mi][ni], alo.x, ahi.x, alo.y, ahi.y, bq[ni].x, bq[ni].y);
                mma8(acc[mi][ni], alo.z, ahi.z, alo.w, ahi.w, bq[ni].z, bq[ni].w);
            }
        }
        if (ch + 1 < nch) {
            const int s = (ch + 1) & 1;
            *(uint4*)&As[s][st0] = make_uint4(ra0[0], ra0[1], ra0[2], ra0[3]);
            *(uint4*)&As[s][st1] = make_uint4(ra1[0], ra1[1], ra1[2], ra1[3]);
            *(uint4*)&Bs[s][st0] = make_uint4(rw0[0], rw0[1], rw0[2], rw0[3]);
            *(uint4*)&Bs[s][st1] = make_uint4(rw1[0], rw1[1], rw1[2], rw1[3]);
        }
    }

    if (ACT == 4) {
        float rsum[4][2];
        #pragma unroll
        for (int mi = 0; mi < 4; mi++) { rsum[mi][0] = 0.f; rsum[mi][1] = 0.f; }
        #pragma unroll
        for (int mi = 0; mi < 4; mi++)
            #pragma unroll
            for (int ni = 0; ni < 4; ni++) {
                int cn = n0 + wn0 + ni*8 + c*2;
                float b0 = __ldg(&bias[cn]),  b1 = __ldg(&bias[cn+1]);
                float p0 = __ldg(&predW[cn]), p1 = __ldg(&predW[cn+1]);
                rsum[mi][0] += tanhf(acc[mi][ni][0] + b0) * p0 + tanhf(acc[mi][ni][1] + b1) * p1;
                rsum[mi][1] += tanhf(acc[mi][ni][2] + b0) * p0 + tanhf(acc[mi][ni][3] + b1) * p1;
            }
        __syncthreads();
        #pragma unroll
        for (int mi = 0; mi < 4; mi++)
            #pragma unroll
            for (int h = 0; h < 2; h++) {
                float v = rsum[mi][h];
                v += __shfl_xor_sync(0xffffffffu, v, 1);
                v += __shfl_xor_sync(0xffffffffu, v, 2);
                if (c == 0) atomicAdd(&sred[wm0 + mi*16 + h*8 + g], v);
            }
        __syncthreads();
        if (tid < 128) atomicAdd(&predS[m0 + tid], sred[tid]);
    } else {
        #pragma unroll
        for (int mi = 0; mi < 4; mi++) {
            int r0 = m0 + wm0 + mi*16 + g;
            #pragma unroll
            for (int ni = 0; ni < 4; ni++) {
                int cn = n0 + wn0 + ni*8 + c*2;
                float b0 = __ldg(&bias[cn]), b1 = __ldg(&bias[cn+1]);
                float v0 = acc[mi][ni][0] + b0, v1 = acc[mi][ni][1] + b1;
                float v2 = acc[mi][ni][2] + b0, v3 = acc[mi][ni][3] + b1;
                if (ACT == 1) { v0 = tf32r(tanhf(v0)); v1 = tf32r(tanhf(v1));
                                v2 = tf32r(tanhf(v2)); v3 = tf32r(tanhf(v3)); }
                else if (ACT == 2) {
                    v0 = 1.f/(1.f+expf(-v0)); v1 = 1.f/(1.f+expf(-v1));
                    v2 = 1.f/(1.f+expf(-v2)); v3 = 1.f/(1.f+expf(-v3));
                } else if (ACT == 3) {
                    if (cn < DV_) { v0 = 1.f/(1.f+expf(-v0)); v1 = 1.f/(1.f+expf(-v1));
                                    v2 = 1.f/(1.f+expf(-v2)); v3 = 1.f/(1.f+expf(-v3)); }
                    else          { v0 = tanhf(v0); v1 = tanhf(v1); v2 = tanhf(v2); v3 = tanhf(v3); }
                }
                *(float2*)&C[(size_t)r0    *ldc + cn] = make_float2(v0, v1);
                *(float2*)&C[(size_t)(r0+8)*ldc + cn] = make_float2(v2, v3);
            }
        }
    }
}

// ==================== FFMA SGEMM (logits, N=50) ====================
template<int ACT>
__global__ void __launch_bounds__(256, 2) k_sgemm(
    const float* __restrict__ A, int lda, int Trows, int K,
    const float* __restrict__ W, int N,
    const float* __restrict__ bias,
    float* __restrict__ C, int ldc)
{
    __shared__ float As[8][128];
    __shared__ float Wsm[8][128];

    const int tid  = threadIdx.x;
    const int m0   = blockIdx.y * 128;
    const int n0   = blockIdx.x * 128;
    const int lrow = tid >> 1;
    const int lcol = (tid & 1) * 4;
    const int tm   = tid >> 4;
    const int tn   = tid & 15;

    const bool aok = (m0 + lrow) < Trows;
    const bool wok = (n0 + lrow) < N;
    const float* Aptr = A + (size_t)(m0 + lrow) * lda + lcol;
    const float* Wptr = W + (size_t)(n0 + lrow) * K   + lcol;

    float acc[8][8];
    #pragma unroll
    for (int i = 0; i < 8; i++)
        #pragma unroll
        for (int j = 0; j < 8; j++) acc[i][j] = 0.f;

    const int ktiles = K >> 3;
    float4 a4 = aok ? *(const float4*)Aptr : make_float4(0,0,0,0);
    float4 w4 = wok ? *(const float4*)Wptr : make_float4(0,0,0,0);

    for (int kt = 0; kt < ktiles; ++kt) {
        As [lcol+0][lrow] = a4.x; As [lcol+1][lrow] = a4.y; As [lcol+2][lrow] = a4.z; As [lcol+3][lrow] = a4.w;
        Wsm[lcol+0][lrow] = w4.x; Wsm[lcol+1][lrow] = w4.y; Wsm[lcol+2][lrow] = w4.z; Wsm[lcol+3][lrow] = w4.w;
        __syncthreads();
        if (kt + 1 < ktiles) {
            a4 = aok ? *(const float4*)(Aptr + (kt+1)*8) : make_float4(0,0,0,0);
            w4 = wok ? *(const float4*)(Wptr + (kt+1)*8) : make_float4(0,0,0,0);
        }
        #pragma unroll
        for (int k = 0; k < 8; k++) {
            float af[8], wf[8];
            *(float4*)(af)   = *(const float4*)(&As [k][tm*8]);
            *(float4*)(af+4) = *(const float4*)(&As [k][tm*8+4]);
            *(float4*)(wf)   = *(const float4*)(&Wsm[k][tn*8]);
            *(float4*)(wf+4) = *(const float4*)(&Wsm[k][tn*8+4]);
            #pragma unroll
            for (int i = 0; i < 8; i++)
                #pragma unroll
                for (int j = 0; j < 8; j++)
                    acc[i][j] = fmaf(af[i], wf[j], acc[i][j]);
        }
        __syncthreads();
    }

    #pragma unroll
    for (int i = 0; i < 8; i++) {
        int gm = m0 + tm*8 + i;
        if (gm >= Trows) continue;
        #pragma unroll
        for (int j = 0; j < 8; j++) {
            int gn = n0 + tn*8 + j;
            if (gn >= N) continue;
            C[(size_t)gm*ldc + gn] = acc[i][j] + (bias ? bias[gn] : 0.f);
        }
    }
}

// ==================== small kernels ====================
__global__ void k_prep(const float* __restrict__ eW, const float* __restrict__ eb,
                       const float* __restrict__ aW, const float* __restrict__ ab,
                       const float* __restrict__ d1W, const float* __restrict__ d2W,
                       const float* __restrict__ roW)
{
    int i = blockIdx.x * blockDim.x + threadIdx.x;
    int stride = gridDim.x * blockDim.x;
    for (int j = i; j < NEA_*KEA_; j += stride) {
        int n = j / KEA_, k = j % KEA_;
        g_Wea[j] = f2tf((n < DV_) ? eW[n*KEA_ + k] : aW[(n - DV_)*KEA_ + k]);
    }
    for (int j = i; j < DQ_*DQ_; j += stride) { g_Wd1[j] = f2tf(d1W[j]); g_Wd2[j] = f2tf(d2W[j]); }
    for (int j = i; j < F_*KRO_; j += stride) g_Wro[j] = f2tf(roW[j]);
    for (int j = i; j < NEA_; j += stride) g_bea[j] = (j < DV_) ? eb[j] : ab[j - DV_];
    for (int j = i; j < T_;  j += stride) g_predS[j] = 0.f;
    if (i < 2) g_accum[i] = 0.f;
}

__global__ void k_gather1(const int* __restrict__ q_data, const int* __restrict__ qa_data,
                          const int* __restrict__ time_data, const int* __restrict__ attempt_data,
                          const int* __restrict__ hint_data, const int* __restrict__ hintTotal_data,
                          const float* __restrict__ q_emb, const float* __restrict__ qa_emb,
                          const float* __restrict__ time_emb, const float* __restrict__ attempt_emb,
                          const float* __restrict__ ht_emb)
{
    int t = blockIdx.x, d = threadIdx.x;
    int qi = q_data[t], ti = time_data[t], ai = attempt_data[t];
    int hi = hint_data[t], hti = hintTotal_data[t];
    float qe  = q_emb[(size_t)qi*DQ_ + d];
    float te  = time_emb[(size_t)ti*DQ_ + d];
    float ae  = attempt_emb[(size_t)ai*DQ_ + d];
    float he  = ht_emb[(size_t)hi*DQ_ + d];
    float hte = ht_emb[(size_t)hti*DQ_ + d];
    g_bufX[(size_t)t*DQ_ + d]      = tf32r(te + qe);
    g_bufX[(size_t)(T_+t)*DQ_ + d] = tf32r(he + hte + ae + qe);
    int qai = qa_data[t];
    g_bufQA[(size_t)t*DV_ + d]       = tf32r(qa_emb[(size_t)qai*DV_ + d]);
    g_bufQA[(size_t)t*DV_ + DQ_ + d] = tf32r(qa_emb[(size_t)qai*DV_ + DQ_ + d]);
}

__global__ void k_buildx3(const int* __restrict__ q_data, const int* __restrict__ attempt_data,
                          const int* __restrict__ hint_data, const int* __restrict__ hintTotal_data,
                          const float* __restrict__ q_emb, const float* __restrict__ attempt_emb,
                          const float* __restrict__ ht_emb)
{
    int t = blockIdx.x, d = threadIdx.x;
    float qe = q_emb[(size_t)q_data[t]*DQ_ + d];
    float g  = attempt_emb[(size_t)attempt_data[t]*DQ_ + d]
             + ht_emb[(size_t)hint_data[t]*DQ_ + d]
             + ht_emb[(size_t)hintTotal_data[t]*DQ_ + d];
    float df = g_bufTD[(size_t)(T_+t)*DQ_ + d];
    g_bufX[(size_t)t*DQ_ + d] = tf32r(fmaf(df, g, qe));
}

__global__ void k_inputembed(const int* __restrict__ time_data, const float* __restrict__ time_emb)
{
    int t = blockIdx.x, d = threadIdx.x;
    float te = time_emb[(size_t)time_data[t]*DQ_ + d];
    float tf = g_bufTD[(size_t)t*DQ_ + d];
    g_PredIn[(size_t)t*KRO_ + DV_ + d] = tf32r(fmaf(tf, te, g_bufQP[(size_t)t*DQ_ + d]));
}

__global__ void k_softmax()
{
    int t = blockIdx.x * 8 + (threadIdx.x >> 5);
    int l = threadIdx.x & 31;
    if (t >= T_) return;
    float v0 = (l < M_)      ? g_logits[(size_t)t*M_ + l]      : -1e30f;
    float v1 = (l + 32 < M_) ? g_logits[(size_t)t*M_ + l + 32] : -1e30f;
    float mx = fmaxf(v0, v1);
    #pragma unroll
    for (int o = 16; o; o >>= 1) mx = fmaxf(mx, __shfl_xor_sync(0xffffffffu, mx, o));
    float e0 = (l < M_)      ? expf(v0 - mx) : 0.f;
    float e1 = (l + 32 < M_) ? expf(v1 - mx) : 0.f;
    float s = e0 + e1;
    #pragma unroll
    for (int o = 16; o; o >>= 1) s += __shfl_xor_sync(0xffffffffu, s, o);
    float inv = 1.f / s;
    if (l < M_)      g_logits[(size_t)t*M_ + l]      = e0 * inv;
    if (l + 32 < M_) g_logits[(size_t)t*M_ + l + 32] = e1 * inv;
}

// DV split 2-way -> 512 CTAs
__global__ void __launch_bounds__(128) k_scan(const float* __restrict__ Mv0)
{
    int b = blockIdx.x;
    int d = blockIdx.y * 128 + threadIdx.x;
    float mv[M_];
    #pragma unroll
    for (int m = 0; m < M_; m++) mv[m] = Mv0[m*DV_ + d];
    __shared__ float ws[M_];
    for (int s = 0; s < S_; s++) {
        size_t t = (size_t)b * S_ + s;
        if (threadIdx.x < M_) ws[threadIdx.x] = g_logits[t*M_ + threadIdx.x];
        __syncthreads();
        float e = g_bufEA[t*NEA_ + d];
        float a = g_bufEA[t*NEA_ + DV_ + d];
        float rd = 0.f;
        #pragma unroll
        for (int m = 0; m < M_; m++) {
            float wm = ws[m];
            rd = fmaf(wm, mv[m], rd);
            mv[m] = fmaf(mv[m], fmaf(-wm, e, 1.f), wm * a);
        }
        g_PredIn[t*KRO_ + d] = tf32r(rd);
        __syncthreads();
    }
}

__global__ void k_loss(const int* __restrict__ target, const float* __restrict__ pred_b,
                       float* __restrict__ out)
{
    int i = blockIdx.x * blockDim.x + threadIdx.x;
    float le = 0.f, cnt = 0.f;
    if (i < T_) {
        float p = g_predS[i] + pred_b[0];
        int tg = target[i];
        bool mask = tg >= 1;
        float y = mask ? (float)(tg - 1) : 0.f;
        float sig = 1.f / (1.f + expf(-p));
        out[1 + i]      = mask ? sig : 0.f;
        out[1 + T_ + i] = mask ? y   : 0.f;
        if (mask) {
            le = fmaxf(p, 0.f) + log1pf(expf(-fabsf(p))) - p * y;
            cnt = 1.f;
        }
    }
    __shared__ float sle[256], scn[256];
    sle[threadIdx.x] = le; scn[threadIdx.x] = cnt;
    __syncthreads();
    for (int o = 128; o; o >>= 1) {
        if (threadIdx.x < o) { sle[threadIdx.x] += sle[threadIdx.x + o]; scn[threadIdx.x] += scn[threadIdx.x + o]; }
        __syncthreads();
    }
    if (threadIdx.x == 0) { atomicAdd(&g_accum[0], sle[0]); atomicAdd(&g_accum[1], scn[0]); }
}

__global__ void k_final(float* __restrict__ out)
{
    out[0] = g_accum[0] / fmaxf(g_accum[1], 1.f);
}

// ==================== host ====================
extern "C" void kernel_launch(void* const* d_in, const int* in_sizes, int n_in,
                              void* d_out, int out_size)
{
    const int*   q_data      = (const int*)  d_in[0];
    const int*   qa_data     = (const int*)  d_in[1];
    const int*   target      = (const int*)  d_in[2];
    const int*   time_data   = (const int*)  d_in[3];
    const int*   attempt_data= (const int*)  d_in[4];
    const int*   hint_data   = (const int*)  d_in[5];
    const int*   hintTotal   = (const int*)  d_in[6];
    const float* q_emb       = (const float*)d_in[7];
    const float* qa_emb      = (const float*)d_in[8];
    const float* time_emb    = (const float*)d_in[9];
    const float* attempt_emb = (const float*)d_in[10];
    const float* ht_emb      = (const float*)d_in[11];
    const float* Mk          = (const float*)d_in[12];
    const float* Mv0         = (const float*)d_in[13];
    const float* diff_W      = (const float*)d_in[14];
    const float* diff_b      = (const float*)d_in[15];
    const float* diff2_W     = (const float*)d_in[16];
    const float* diff2_b     = (const float*)d_in[17];
    const float* erase_W     = (const float*)d_in[18];
    const float* erase_b     = (const float*)d_in[19];
    const float* add_W       = (const float*)d_in[20];
    const float* add_b       = (const float*)d_in[21];
    const float* read_W      = (const float*)d_in[22];
    const float* read_b      = (const float*)d_in[23];
    const float* pred_W      = (const float*)d_in[24];
    const float* pred_b      = (const float*)d_in[25];
    float* out = (float*)d_out;

    float *bufX, *bufU, *bufTD, *bufQP, *bufQA, *bufEA, *predin, *logits, *predS, *bea;
    uint32_t *Wea, *Wd1, *Wd2, *Wro;
    cudaGetSymbolAddress((void**)&bufX,   g_bufX);
    cudaGetSymbolAddress((void**)&bufU,   g_bufU);
    cudaGetSymbolAddress((void**)&bufTD,  g_bufTD);
    cudaGetSymbolAddress((void**)&bufQP,  g_bufQP);
    cudaGetSymbolAddress((void**)&bufQA,  g_bufQA);
    cudaGetSymbolAddress((void**)&bufEA,  g_bufEA);
    cudaGetSymbolAddress((void**)&predin, g_PredIn);
    cudaGetSymbolAddress((void**)&logits, g_logits);
    cudaGetSymbolAddress((void**)&predS,  g_predS);
    cudaGetSymbolAddress((void**)&Wea,    g_Wea);
    cudaGetSymbolAddress((void**)&Wd1,    g_Wd1);
    cudaGetSymbolAddress((void**)&Wd2,    g_Wd2);
    cudaGetSymbolAddress((void**)&Wro,    g_Wro);
    cudaGetSymbolAddress((void**)&bea,    g_bea);

    // 0) round weights to tf32 copies, zero predS/accum
    k_prep<<<1024, 256>>>(erase_W, erase_b, add_W, add_b, diff_W, diff2_W, read_W);
    // 1) gathers (tf32-rounded outputs)
    k_gather1<<<T_, 128>>>(q_data, qa_data, time_data, attempt_data, hint_data, hintTotal,
                           q_emb, qa_emb, time_emb, attempt_emb, ht_emb);
    // 2) U = tanh(lin1(X)) over 2T rows
    k_mma<1><<<dim3(1, 2*T_/128), 256>>>(bufX, DQ_, DQ_, Wd1, diff_b, bufU, DQ_, nullptr, nullptr);
    // 3) TD = sigmoid(lin2(U)) over 2T rows
    k_mma<2><<<dim3(1, 2*T_/128), 256>>>(bufU, DQ_, DQ_, Wd2, diff2_b, bufTD, DQ_, nullptr, nullptr);
    // 4) X3 = qe + diff_final * g
    k_buildx3<<<T_, 128>>>(q_data, attempt_data, hint_data, hintTotal, q_emb, attempt_emb, ht_emb);
    // 5) q_proc = lin1(X3)
    k_mma<0><<<dim3(1, T_/128), 256>>>(bufX, DQ_, DQ_, Wd1, diff_b, bufQP, DQ_, nullptr, nullptr);
    // 6) input_embed into PredIn cols [256,384)
    k_inputembed<<<T_, 128>>>(time_data, time_emb);
    // 7) logits = q_proc @ Mk^T (N=50, FFMA, fp32 exact)
    k_sgemm<0><<<dim3(1, T_/128), 256>>>(bufQP, DQ_, T_, DQ_, Mk, M_, nullptr, logits, M_);
    // 8) softmax
    k_softmax<<<T_/8, 256>>>();
    // 9) E/A
    k_mma<3><<<dim3(4, T_/128), 256>>>(bufQA, KEA_, KEA_, Wea, bea, bufEA, NEA_, nullptr, nullptr);
    // 10) scan -> reads (tf32-rounded)
    k_scan<<<dim3(B_, 2), 128>>>(Mv0);
    // 11) readout + fused pred dot
    k_mma<4><<<dim3(4, T_/128), 256>>>(predin, KRO_, KRO_, Wro, read_b, nullptr, 0, pred_W, predS);
    // 12) loss + outputs
    k_loss<<<(T_ + 255)/256, 256>>>(target, pred_b, out);
    k_final<<<1, 1>>>(out);
}

// round 6
// speedup vs baseline: 2.8815x; 1.4627x over previous
#include <cuda_runtime.h>
#include <cuda_fp16.h>
#include <math.h>
#include <stdint.h>

#define B_   256
#define S_   500
#define T_   (B_*S_)        // 128000
#define DQ_  128
#define DV_  256
#define M_   50
#define F_   512
#define NEA_ 512
#define KEA_ 256
#define KRO_ 384            // DV + DQ
#define LML_ 64             // padded logits row stride

// ---------------- scratch (device globals; no allocations) ----------------
__device__ __half g_bufX [2*T_*DQ_];
__device__ __half g_bufU [2*T_*DQ_];
__device__ __half g_bufTD[2*T_*DQ_];
__device__ __half g_bufQP[T_*DQ_];
__device__ __half g_bufQA[T_*DV_];
__device__ __half g_bufEA[T_*NEA_];
__device__ __half g_PredIn[T_*KRO_];
__device__ float  g_logits[T_*LML_];
__device__ float  g_predS[T_];
__device__ float  g_accum[2];
__device__ __half g_Wea[NEA_*KEA_];
__device__ __half g_Wd1[DQ_*DQ_];
__device__ __half g_Wd2[DQ_*DQ_];
__device__ __half g_Wro[F_*KRO_];
__device__ __half g_Wmk[64*DQ_];     // Mk padded to 64 rows (zeros)
__device__ float  g_bea[NEA_];

// ==================== f16 mma (legacy, compute_103-safe) ====================
__device__ __forceinline__ void mma16(float* d,
    uint32_t a0, uint32_t a1, uint32_t a2, uint32_t a3,
    uint32_t b0, uint32_t b1)
{
    asm volatile(
        "mma.sync.aligned.m16n8k16.row.col.f32.f16.f16.f32 "
        "{%0,%1,%2,%3},{%4,%5,%6,%7},{%8,%9},{%0,%1,%2,%3};"
        : "+f"(d[0]), "+f"(d[1]), "+f"(d[2]), "+f"(d[3])
        : "r"(a0), "r"(a1), "r"(a2), "r"(a3), "r"(b0), "r"(b1));
}

// ==================== f16 tensor GEMM: C = act(A @ W^T + bias) ==============
// CTA 128 x (NW*32), 8 warps (MW m x NW n), K chunk 32 halves (2 k16 steps),
// 2-stage smem. Half-pair permuted layout: pair p -> p' = (p&3)*4 + (p>>2),
// so one LDS.128 per row yields fragments for BOTH k16 steps; staging is
// 4x LDG.32 + 1x STS.128 per row. All conflict-free.
// ACT: 0=none 1=tanh 2=sigmoid 3=EA-split 4=readout+pred dot 5=logits(f32 out)
template<int ACT, int NW>
__global__ void __launch_bounds__(256, 2) k_mma(
    const __half* __restrict__ A, int lda, int K,
    const __half* __restrict__ W,
    const float* __restrict__ bias,
    void* __restrict__ Cv, int ldc,
    const float* __restrict__ predW, float* __restrict__ predS)
{
    constexpr int NCTA = NW * 32;
    constexpr int MW   = 8 / NW;
    constexpr int MT   = 128 / (MW * 16);

    __shared__ uint32_t As[2][128*16];
    __shared__ uint32_t Bs[2][NCTA*16];
    __shared__ float sred[128];

    const int tid  = threadIdx.x;
    const int m0   = blockIdx.y * 128;
    const int n0   = blockIdx.x * NCTA;
    const int lane = tid & 31, w = tid >> 5;
    const int g    = lane >> 2, c = lane & 3;
    const int wm0  = (w / NW) * (MT * 16);
    const int wn0  = (w % NW) * 32;
    const int srow = tid >> 2;
    const int lc   = tid & 3;

    // global pair (half2) pointers
    const uint32_t* Ap0 = (const uint32_t*)(A + (size_t)(m0 + srow)      * lda) + lc;
    const uint32_t* Ap1 = (const uint32_t*)(A + (size_t)(m0 + srow + 64) * lda) + lc;
    const uint32_t* Wp0 = (const uint32_t*)(W + (size_t)(n0 + srow)      * K  ) + lc;
    const uint32_t* Wp1 = (const uint32_t*)(W + (size_t)((NW==4 ? n0 + srow + 64 : 0)) * K) + lc;

    const int st0 = srow * 16 + lc * 4;
    const int st1 = (srow + 64) * 16 + lc * 4;

    float acc[MT][4][4];
    #pragma unroll
    for (int i = 0; i < MT; i++)
        #pragma unroll
        for (int j = 0; j < 4; j++)
            #pragma unroll
            for (int r = 0; r < 4; r++) acc[i][j][r] = 0.f;

    if (ACT == 4 && tid < 128) sred[tid] = 0.f;

    uint32_t ra0[4], ra1[4], rw0[4], rw1[4];
    const int nch = K >> 5;           // 32 halves (16 pairs) per chunk

    #pragma unroll
    for (int i = 0; i < 4; i++) {     // pairs lc, lc+4, lc+8, lc+12
        ra0[i] = Ap0[4*i];
        ra1[i] = Ap1[4*i];
        rw0[i] = Wp0[4*i];
        if (NW == 4) rw1[i] = Wp1[4*i];
    }
    *(uint4*)&As[0][st0] = make_uint4(ra0[0], ra0[1], ra0[2], ra0[3]);
    *(uint4*)&As[0][st1] = make_uint4(ra1[0], ra1[1], ra1[2], ra1[3]);
    *(uint4*)&Bs[0][st0] = make_uint4(rw0[0], rw0[1], rw0[2], rw0[3]);
    if (NW == 4) *(uint4*)&Bs[0][st1] = make_uint4(rw1[0], rw1[1], rw1[2], rw1[3]);

    for (int ch = 0; ch < nch; ch++) {
        __syncthreads();
        if (ch + 1 < nch) {
            const int ko = (ch + 1) * 16;
            #pragma unroll
            for (int i = 0; i < 4; i++) {
                ra0[i] = Ap0[ko + 4*i];
                ra1[i] = Ap1[ko + 4*i];
                rw0[i] = Wp0[ko + 4*i];
                if (NW == 4) rw1[i] = Wp1[ko + 4*i];
            }
        }
        const uint32_t* as = As[ch & 1];
        const uint32_t* bs = Bs[ch & 1];
        uint4 bq[4];
        #pragma unroll
        for (int ni = 0; ni < 4; ni++)
            bq[ni] = *(const uint4*)&bs[(wn0 + ni*8 + g) * 16 + c*4];
        #pragma unroll
        for (int mi = 0; mi < MT; mi++) {
            uint4 alo = *(const uint4*)&as[(wm0 + mi*16 + g)     * 16 + c*4];
            uint4 ahi = *(const uint4*)&as[(wm0 + mi*16 + g + 8) * 16 + c*4];
            #pragma unroll
            for (int ni = 0; ni < 4; ni++) {
                mma16(acc[mi][ni], alo.x, ahi.x, alo.y, ahi.y, bq[ni].x, bq[ni].y); // k 0..15
                mma16(acc[mi][ni], alo.z, ahi.z, alo.w, ahi.w, bq[ni].z, bq[ni].w); // k 16..31
            }
        }
        if (ch + 1 < nch) {
            const int s = (ch + 1) & 1;
            *(uint4*)&As[s][st0] = make_uint4(ra0[0], ra0[1], ra0[2], ra0[3]);
            *(uint4*)&As[s][st1] = make_uint4(ra1[0], ra1[1], ra1[2], ra1[3]);
            *(uint4*)&Bs[s][st0] = make_uint4(rw0[0], rw0[1], rw0[2], rw0[3]);
            if (NW == 4) *(uint4*)&Bs[s][st1] = make_uint4(rw1[0], rw1[1], rw1[2], rw1[3]);
        }
    }

    if (ACT == 4) {
        float rsum[MT][2];
        #pragma unroll
        for (int mi = 0; mi < MT; mi++) { rsum[mi][0] = 0.f; rsum[mi][1] = 0.f; }
        #pragma unroll
        for (int mi = 0; mi < MT; mi++)
            #pragma unroll
            for (int ni = 0; ni < 4; ni++) {
                int cn = n0 + wn0 + ni*8 + c*2;
                float b0 = __ldg(&bias[cn]),  b1 = __ldg(&bias[cn+1]);
                float p0 = __ldg(&predW[cn]), p1 = __ldg(&predW[cn+1]);
                rsum[mi][0] += tanhf(acc[mi][ni][0] + b0) * p0 + tanhf(acc[mi][ni][1] + b1) * p1;
                rsum[mi][1] += tanhf(acc[mi][ni][2] + b0) * p0 + tanhf(acc[mi][ni][3] + b1) * p1;
            }
        __syncthreads();
        #pragma unroll
        for (int mi = 0; mi < MT; mi++)
            #pragma unroll
            for (int h = 0; h < 2; h++) {
                float v = rsum[mi][h];
                v += __shfl_xor_sync(0xffffffffu, v, 1);
                v += __shfl_xor_sync(0xffffffffu, v, 2);
                if (c == 0) atomicAdd(&sred[wm0 + mi*16 + h*8 + g], v);
            }
        __syncthreads();
        if (tid < 128) atomicAdd(&predS[m0 + tid], sred[tid]);
    } else if (ACT == 5) {
        float* C = (float*)Cv;
        #pragma unroll
        for (int mi = 0; mi < MT; mi++) {
            int r0 = m0 + wm0 + mi*16 + g;
            #pragma unroll
            for (int ni = 0; ni < 4; ni++) {
                int cn = n0 + wn0 + ni*8 + c*2;
                *(float2*)&C[(size_t)r0    *ldc + cn] = make_float2(acc[mi][ni][0], acc[mi][ni][1]);
                *(float2*)&C[(size_t)(r0+8)*ldc + cn] = make_float2(acc[mi][ni][2], acc[mi][ni][3]);
            }
        }
    } else {
        __half* C = (__half*)Cv;
        #pragma unroll
        for (int mi = 0; mi < MT; mi++) {
            int r0 = m0 + wm0 + mi*16 + g;
            #pragma unroll
            for (int ni = 0; ni < 4; ni++) {
                int cn = n0 + wn0 + ni*8 + c*2;
                float b0 = __ldg(&bias[cn]), b1 = __ldg(&bias[cn+1]);
                float v0 = acc[mi][ni][0] + b0, v1 = acc[mi][ni][1] + b1;
                float v2 = acc[mi][ni][2] + b0, v3 = acc[mi][ni][3] + b1;
                if (ACT == 1) { v0 = tanhf(v0); v1 = tanhf(v1); v2 = tanhf(v2); v3 = tanhf(v3); }
                else if (ACT == 2) {
                    v0 = 1.f/(1.f+expf(-v0)); v1 = 1.f/(1.f+expf(-v1));
                    v2 = 1.f/(1.f+expf(-v2)); v3 = 1.f/(1.f+expf(-v3));
                } else if (ACT == 3) {
                    if (cn < DV_) { v0 = 1.f/(1.f+expf(-v0)); v1 = 1.f/(1.f+expf(-v1));
                                    v2 = 1.f/(1.f+expf(-v2)); v3 = 1.f/(1.f+expf(-v3)); }
                    else          { v0 = tanhf(v0); v1 = tanhf(v1); v2 = tanhf(v2); v3 = tanhf(v3); }
                }
                *(__half2*)&C[(size_t)r0    *ldc + cn] = __floats2half2_rn(v0, v1);
                *(__half2*)&C[(size_t)(r0+8)*ldc + cn] = __floats2half2_rn(v2, v3);
            }
        }
    }
}

// ==================== small kernels ====================
__global__ void k_prep(const float* __restrict__ eW, const float* __restrict__ eb,
                       const float* __restrict__ aW, const float* __restrict__ ab,
                       const float* __restrict__ d1W, const float* __restrict__ d2W,
                       const float* __restrict__ roW, const float* __restrict__ Mk)
{
    int i = blockIdx.x * blockDim.x + threadIdx.x;
    int stride = gridDim.x * blockDim.x;
    for (int j = i; j < NEA_*KEA_; j += stride) {
        int n = j / KEA_, k = j % KEA_;
        g_Wea[j] = __float2half((n < DV_) ? eW[n*KEA_ + k] : aW[(n - DV_)*KEA_ + k]);
    }
    for (int j = i; j < DQ_*DQ_; j += stride) {
        g_Wd1[j] = __float2half(d1W[j]);
        g_Wd2[j] = __float2half(d2W[j]);
    }
    for (int j = i; j < F_*KRO_; j += stride) g_Wro[j] = __float2half(roW[j]);
    for (int j = i; j < 64*DQ_; j += stride) {
        int n = j / DQ_, k = j % DQ_;
        g_Wmk[j] = __float2half(n < M_ ? Mk[n*DQ_ + k] : 0.f);
    }
    for (int j = i; j < NEA_; j += stride) g_bea[j] = (j < DV_) ? eb[j] : ab[j - DV_];
    for (int j = i; j < T_;  j += stride) g_predS[j] = 0.f;
    if (i < 2) g_accum[i] = 0.f;
}

__global__ void k_gather1(const int* __restrict__ q_data, const int* __restrict__ qa_data,
                          const int* __restrict__ time_data, const int* __restrict__ attempt_data,
                          const int* __restrict__ hint_data, const int* __restrict__ hintTotal_data,
                          const float* __restrict__ q_emb, const float* __restrict__ qa_emb,
                          const float* __restrict__ time_emb, const float* __restrict__ attempt_emb,
                          const float* __restrict__ ht_emb)
{
    int t = blockIdx.x, d = threadIdx.x;
    int qi = q_data[t], ti = time_data[t], ai = attempt_data[t];
    int hi = hint_data[t], hti = hintTotal_data[t];
    float qe  = q_emb[(size_t)qi*DQ_ + d];
    float te  = time_emb[(size_t)ti*DQ_ + d];
    float ae  = attempt_emb[(size_t)ai*DQ_ + d];
    float he  = ht_emb[(size_t)hi*DQ_ + d];
    float hte = ht_emb[(size_t)hti*DQ_ + d];
    g_bufX[(size_t)t*DQ_ + d]      = __float2half(te + qe);
    g_bufX[(size_t)(T_+t)*DQ_ + d] = __float2half(he + hte + ae + qe);
    int qai = qa_data[t];
    g_bufQA[(size_t)t*DV_ + d]       = __float2half(qa_emb[(size_t)qai*DV_ + d]);
    g_bufQA[(size_t)t*DV_ + DQ_ + d] = __float2half(qa_emb[(size_t)qai*DV_ + DQ_ + d]);
}

__global__ void k_buildx3(const int* __restrict__ q_data, const int* __restrict__ attempt_data,
                          const int* __restrict__ hint_data, const int* __restrict__ hintTotal_data,
                          const float* __restrict__ q_emb, const float* __restrict__ attempt_emb,
                          const float* __restrict__ ht_emb)
{
    int t = blockIdx.x, d = threadIdx.x;
    float qe = q_emb[(size_t)q_data[t]*DQ_ + d];
    float g  = attempt_emb[(size_t)attempt_data[t]*DQ_ + d]
             + ht_emb[(size_t)hint_data[t]*DQ_ + d]
             + ht_emb[(size_t)hintTotal_data[t]*DQ_ + d];
    float df = __half2float(g_bufTD[(size_t)(T_+t)*DQ_ + d]);
    g_bufX[(size_t)t*DQ_ + d] = __float2half(fmaf(df, g, qe));
}

__global__ void k_inputembed(const int* __restrict__ time_data, const float* __restrict__ time_emb)
{
    int t = blockIdx.x, d = threadIdx.x;
    float te = time_emb[(size_t)time_data[t]*DQ_ + d];
    float tf = __half2float(g_bufTD[(size_t)t*DQ_ + d]);
    float qp = __half2float(g_bufQP[(size_t)t*DQ_ + d]);
    g_PredIn[(size_t)t*KRO_ + DV_ + d] = __float2half(fmaf(tf, te, qp));
}

__global__ void k_softmax()
{
    int t = blockIdx.x * 8 + (threadIdx.x >> 5);
    int l = threadIdx.x & 31;
    if (t >= T_) return;
    float v0 = (l < M_)      ? g_logits[(size_t)t*LML_ + l]      : -1e30f;
    float v1 = (l + 32 < M_) ? g_logits[(size_t)t*LML_ + l + 32] : -1e30f;
    float mx = fmaxf(v0, v1);
    #pragma unroll
    for (int o = 16; o; o >>= 1) mx = fmaxf(mx, __shfl_xor_sync(0xffffffffu, mx, o));
    float e0 = (l < M_)      ? expf(v0 - mx) : 0.f;
    float e1 = (l + 32 < M_) ? expf(v1 - mx) : 0.f;
    float s = e0 + e1;
    #pragma unroll
    for (int o = 16; o; o >>= 1) s += __shfl_xor_sync(0xffffffffu, s, o);
    float inv = 1.f / s;
    if (l < M_)      g_logits[(size_t)t*LML_ + l]      = e0 * inv;
    if (l + 32 < M_) g_logits[(size_t)t*LML_ + l + 32] = e1 * inv;
}

// DV split 2-way -> 512 CTAs
__global__ void __launch_bounds__(128) k_scan(const float* __restrict__ Mv0)
{
    int b = blockIdx.x;
    int d = blockIdx.y * 128 + threadIdx.x;
    float mv[M_];
    #pragma unroll
    for (int m = 0; m < M_; m++) mv[m] = Mv0[m*DV_ + d];
    __shared__ float ws[M_];
    for (int s = 0; s < S_; s++) {
        size_t t = (size_t)b * S_ + s;
        if (threadIdx.x < M_) ws[threadIdx.x] = g_logits[t*LML_ + threadIdx.x];
        __syncthreads();
        float e = __half2float(g_bufEA[t*NEA_ + d]);
        float a = __half2float(g_bufEA[t*NEA_ + DV_ + d]);
        float rd = 0.f;
        #pragma unroll
        for (int m = 0; m < M_; m++) {
            float wm = ws[m];
            rd = fmaf(wm, mv[m], rd);
            mv[m] = fmaf(mv[m], fmaf(-wm, e, 1.f), wm * a);
        }
        g_PredIn[t*KRO_ + d] = __float2half(rd);
        __syncthreads();
    }
}

__global__ void k_loss(const int* __restrict__ target, const float* __restrict__ pred_b,
                       float* __restrict__ out)
{
    int i = blockIdx.x * blockDim.x + threadIdx.x;
    float le = 0.f, cnt = 0.f;
    if (i < T_) {
        float p = g_predS[i] + pred_b[0];
        int tg = target[i];
        bool mask = tg >= 1;
        float y = mask ? (float)(tg - 1) : 0.f;
        float sig = 1.f / (1.f + expf(-p));
        out[1 + i]      = mask ? sig : 0.f;
        out[1 + T_ + i] = mask ? y   : 0.f;
        if (mask) {
            le = fmaxf(p, 0.f) + log1pf(expf(-fabsf(p))) - p * y;
            cnt = 1.f;
        }
    }
    __shared__ float sle[256], scn[256];
    sle[threadIdx.x] = le; scn[threadIdx.x] = cnt;
    __syncthreads();
    for (int o = 128; o; o >>= 1) {
        if (threadIdx.x < o) { sle[threadIdx.x] += sle[threadIdx.x + o]; scn[threadIdx.x] += scn[threadIdx.x + o]; }
        __syncthreads();
    }
    if (threadIdx.x == 0) { atomicAdd(&g_accum[0], sle[0]); atomicAdd(&g_accum[1], scn[0]); }
}

__global__ void k_final(float* __restrict__ out)
{
    out[0] = g_accum[0] / fmaxf(g_accum[1], 1.f);
}

// ==================== host ====================
extern "C" void kernel_launch(void* const* d_in, const int* in_sizes, int n_in,
                              void* d_out, int out_size)
{
    const int*   q_data      = (const int*)  d_in[0];
    const int*   qa_data     = (const int*)  d_in[1];
    const int*   target      = (const int*)  d_in[2];
    const int*   time_data   = (const int*)  d_in[3];
    const int*   attempt_data= (const int*)  d_in[4];
    const int*   hint_data   = (const int*)  d_in[5];
    const int*   hintTotal   = (const int*)  d_in[6];
    const float* q_emb       = (const float*)d_in[7];
    const float* qa_emb      = (const float*)d_in[8];
    const float* time_emb    = (const float*)d_in[9];
    const float* attempt_emb = (const float*)d_in[10];
    const float* ht_emb      = (const float*)d_in[11];
    const float* Mk          = (const float*)d_in[12];
    const float* Mv0         = (const float*)d_in[13];
    const float* diff_W      = (const float*)d_in[14];
    const float* diff_b      = (const float*)d_in[15];
    const float* diff2_W     = (const float*)d_in[16];
    const float* diff2_b     = (const float*)d_in[17];
    const float* erase_W     = (const float*)d_in[18];
    const float* erase_b     = (const float*)d_in[19];
    const float* add_W       = (const float*)d_in[20];
    const float* add_b       = (const float*)d_in[21];
    const float* read_W      = (const float*)d_in[22];
    const float* read_b      = (const float*)d_in[23];
    const float* pred_W      = (const float*)d_in[24];
    const float* pred_b      = (const float*)d_in[25];
    float* out = (float*)d_out;

    __half *bufX, *bufU, *bufTD, *bufQP, *bufQA, *bufEA, *predin;
    __half *Wea, *Wd1, *Wd2, *Wro, *Wmk;
    float *logits, *predS, *bea;
    cudaGetSymbolAddress((void**)&bufX,   g_bufX);
    cudaGetSymbolAddress((void**)&bufU,   g_bufU);
    cudaGetSymbolAddress((void**)&bufTD,  g_bufTD);
    cudaGetSymbolAddress((void**)&bufQP,  g_bufQP);
    cudaGetSymbolAddress((void**)&bufQA,  g_bufQA);
    cudaGetSymbolAddress((void**)&bufEA,  g_bufEA);
    cudaGetSymbolAddress((void**)&predin, g_PredIn);
    cudaGetSymbolAddress((void**)&logits, g_logits);
    cudaGetSymbolAddress((void**)&predS,  g_predS);
    cudaGetSymbolAddress((void**)&Wea,    g_Wea);
    cudaGetSymbolAddress((void**)&Wd1,    g_Wd1);
    cudaGetSymbolAddress((void**)&Wd2,    g_Wd2);
    cudaGetSymbolAddress((void**)&Wro,    g_Wro);
    cudaGetSymbolAddress((void**)&Wmk,    g_Wmk);
    cudaGetSymbolAddress((void**)&bea,    g_bea);

    // 0) convert weights to f16, zero predS/accum
    k_prep<<<1024, 256>>>(erase_W, erase_b, add_W, add_b, diff_W, diff2_W, read_W, Mk);
    // 1) gathers (f16 outputs)
    k_gather1<<<T_, 128>>>(q_data, qa_data, time_data, attempt_data, hint_data, hintTotal,
                           q_emb, qa_emb, time_emb, attempt_emb, ht_emb);
    // 2) U = tanh(lin1(X)) over 2T rows
    k_mma<1,4><<<dim3(1, 2*T_/128), 256>>>(bufX, DQ_, DQ_, Wd1, diff_b, bufU, DQ_, nullptr, nullptr);
    // 3) TD = sigmoid(lin2(U)) over 2T rows
    k_mma<2,4><<<dim3(1, 2*T_/128), 256>>>(bufU, DQ_, DQ_, Wd2, diff2_b, bufTD, DQ_, nullptr, nullptr);
    // 4) X3 = qe + diff_final * g
    k_buildx3<<<T_, 128>>>(q_data, attempt_data, hint_data, hintTotal, q_emb, attempt_emb, ht_emb);
    // 5) q_proc = lin1(X3)
    k_mma<0,4><<<dim3(1, T_/128), 256>>>(bufX, DQ_, DQ_, Wd1, diff_b, bufQP, DQ_, nullptr, nullptr);
    // 6) input_embed into PredIn cols [256,384)
    k_inputembed<<<T_, 128>>>(time_data, time_emb);
    // 7) logits = q_proc @ Mk^T (padded N=64, f32 out)
    k_mma<5,2><<<dim3(1, T_/128), 256>>>(bufQP, DQ_, DQ_, Wmk, nullptr, logits, LML_, nullptr, nullptr);
    // 8) softmax over M
    k_softmax<<<T_/8, 256>>>();
    // 9) E/A
    k_mma<3,4><<<dim3(4, T_/128), 256>>>(bufQA, KEA_, KEA_, Wea, bea, bufEA, NEA_, nullptr, nullptr);
    // 10) scan -> reads
    k_scan<<<dim3(B_, 2), 128>>>(Mv0);
    // 11) readout + fused pred dot
    k_mma<4,4><<<dim3(4, T_/128), 256>>>(predin, KRO_, KRO_, Wro, read_b, nullptr, 0, pred_W, predS);
    // 12) loss + outputs
    k_loss<<<(T_ + 255)/256, 256>>>(target, pred_b, out);
    k_final<<<1, 1>>>(out);
}

// round 7
// speedup vs baseline: 2.8997x; 1.0063x over previous
#include <cuda_runtime.h>
#include <cuda_fp16.h>
#include <math.h>
#include <stdint.h>

#define B_   256
#define S_   500
#define T_   (B_*S_)        // 128000
#define DQ_  128
#define DV_  256
#define M_   50
#define F_   512
#define NEA_ 512
#define KEA_ 256
#define KRO_ 384            // DV + DQ
#define LML_ 64             // padded logits row stride

// ---------------- scratch (device globals; no allocations) ----------------
// All GEMM-input half buffers are stored K-PAIR-PERMUTED (see ph()).
__device__ __half g_bufX [2*T_*DQ_];
__device__ __half g_bufU [2*T_*DQ_];
__device__ __half g_bufTD[2*T_*DQ_];    // plain (elementwise-consumed only)
__device__ __half g_bufQP[T_*DQ_];
__device__ __half g_bufQA[T_*DV_];
__device__ __half g_bufEA[T_*NEA_];
__device__ __half g_PredIn[T_*KRO_];
__device__ float  g_logits[T_*LML_];
__device__ float  g_predS[T_];
__device__ float  g_accum[2];
__device__ __half g_Wea[NEA_*KEA_];     // permuted
__device__ __half g_Wd1[DQ_*DQ_];       // permuted
__device__ __half g_Wd2[DQ_*DQ_];       // permuted
__device__ __half g_Wro[F_*KRO_];       // permuted
__device__ __half g_Wmk[64*DQ_];        // permuted, Mk padded to 64 rows
__device__ float  g_bea[NEA_];

// ==================== helpers ====================
// k-pair permutation: within each 32-half chunk, pair pi -> (pi&3)*4 + (pi>>2).
__device__ __forceinline__ int ph(int d) {          // half index -> permuted half index
    int pair = d >> 1;
    int pi   = pair & 15;
    int pp   = (pair & ~15) | ((pi & 3) * 4 + (pi >> 2));
    return pp * 2 + (d & 1);
}
__device__ __forceinline__ int permc(int cn) {      // even col -> permuted even col
    int pair = cn >> 1;
    int pi   = pair & 15;
    int pp   = (pair & ~15) | ((pi & 3) * 4 + (pi >> 2));
    return pp * 2;
}
__device__ __forceinline__ float fsig(float x) { return 1.f / (1.f + __expf(-x)); }
__device__ __forceinline__ float ftanh(float x) {
    float ax = fabsf(x);
    float t  = 1.f - 2.f / (1.f + __expf(2.f * ax));
    return copysignf(t, x);
}
__device__ __forceinline__ void mma16(float* d,
    uint32_t a0, uint32_t a1, uint32_t a2, uint32_t a3,
    uint32_t b0, uint32_t b1)
{
    asm volatile(
        "mma.sync.aligned.m16n8k16.row.col.f32.f16.f16.f32 "
        "{%0,%1,%2,%3},{%4,%5,%6,%7},{%8,%9},{%0,%1,%2,%3};"
        : "+f"(d[0]), "+f"(d[1]), "+f"(d[2]), "+f"(d[3])
        : "r"(a0), "r"(a1), "r"(a2), "r"(a3), "r"(b0), "r"(b1));
}
__device__ __forceinline__ void cpa16(uint32_t dst, const void* src) {
    asm volatile("cp.async.cg.shared.global [%0], [%1], 16;" :: "r"(dst), "l"(src));
}

// ==================== f16 tensor GEMM: C = act(A @ W^T + bias) ==============
// 128 threads, 4 warps (2m x 2n), warp tile 64 x (NT*8), CTA 128 x (NT*16).
// K chunk = 32 halves, 3-stage cp.async pipeline, operands pre-permuted.
// ACT: 0=none(perm) 1=tanh(perm) 2=sigmoid(plain) 3=EA-split(perm)
//      4=readout+pred dot 5=logits(plain f32)
template<int ACT, int NT>
__global__ void __launch_bounds__(128, 2) k_mma(
    const __half* __restrict__ A, int lda, int K,
    const __half* __restrict__ W,
    const float* __restrict__ bias,
    void* __restrict__ Cv, int ldc,
    const float* __restrict__ predW, float* __restrict__ predS)
{
    constexpr int NCTA = NT * 16;
    constexpr bool PERM = (ACT == 0 || ACT == 1 || ACT == 3);

    extern __shared__ uint32_t sm[];
    uint32_t* As   = sm;                         // 3 * 2048
    uint32_t* Bs   = sm + 3 * 2048;              // 3 * NT*256
    float*    sred = (float*)(sm + 3 * 2048 + 3 * NT * 256);   // 128

    const int tid  = threadIdx.x;
    const int m0   = blockIdx.y * 128;
    const int n0   = blockIdx.x * NCTA;
    const int lane = tid & 31, w = tid >> 5;
    const int g    = lane >> 2, c = lane & 3;
    const int wm0  = (w >> 1) * 64;
    const int wn0  = (w & 1) * (NT * 8);
    const int srow = tid >> 2;
    const int grp  = tid & 3;

    const int ldpA = lda >> 1, ldpW = K >> 1;
    const uint32_t* Ag = (const uint32_t*)A + (size_t)(m0 + srow) * ldpA + grp * 4;
    const uint32_t* Wg = (const uint32_t*)W + (size_t)(n0 + srow) * ldpW + grp * 4;

    uint32_t asb, bsb;
    asb = (uint32_t)__cvta_generic_to_shared(As) + (srow * 16 + grp * 4) * 4;
    bsb = (uint32_t)__cvta_generic_to_shared(Bs) + (srow * 16 + grp * 4) * 4;

    float acc[4][NT][4];
    #pragma unroll
    for (int i = 0; i < 4; i++)
        #pragma unroll
        for (int j = 0; j < NT; j++)
            #pragma unroll
            for (int r = 0; r < 4; r++) acc[i][j][r] = 0.f;

    const int nch = K >> 5;

    auto stage = [&](int ch, int s) {
        const uint32_t* ag = Ag + ch * 16;
        uint32_t ab = asb + s * 2048 * 4;
        #pragma unroll
        for (int i = 0; i < 4; i++)
            cpa16(ab + i * (32 * 16 * 4), ag + (size_t)i * 32 * ldpA);
        const uint32_t* wg = Wg + ch * 16;
        uint32_t bb = bsb + s * (NT * 256) * 4;
        #pragma unroll
        for (int i = 0; i < NT / 2; i++)
            cpa16(bb + i * (32 * 16 * 4), wg + (size_t)i * 32 * ldpW);
        asm volatile("cp.async.commit_group;");
    };

    stage(0, 0);
    stage(1, 1);

    for (int ch = 0; ch < nch; ch++) {
        asm volatile("cp.async.wait_group 1;");
        __syncthreads();
        if (ch + 2 < nch) stage(ch + 2, (ch + 2) % 3);
        else asm volatile("cp.async.commit_group;");

        const uint32_t* as = As + (ch % 3) * 2048;
        const uint32_t* bs = Bs + (ch % 3) * (NT * 256);
        uint4 alo[4], ahi[4];
        #pragma unroll
        for (int mi = 0; mi < 4; mi++) {
            alo[mi] = *(const uint4*)&as[(wm0 + mi*16 + g)     * 16 + c*4];
            ahi[mi] = *(const uint4*)&as[(wm0 + mi*16 + g + 8) * 16 + c*4];
        }
        #pragma unroll
        for (int ni = 0; ni < NT; ni++) {
            uint4 b = *(const uint4*)&bs[(wn0 + ni*8 + g) * 16 + c*4];
            #pragma unroll
            for (int mi = 0; mi < 4; mi++) {
                mma16(acc[mi][ni], alo[mi].x, ahi[mi].x, alo[mi].y, ahi[mi].y, b.x, b.y);
                mma16(acc[mi][ni], alo[mi].z, ahi[mi].z, alo[mi].w, ahi[mi].w, b.z, b.w);
            }
        }
    }

    if (ACT == 4) {
        float rsum[4][2];
        #pragma unroll
        for (int mi = 0; mi < 4; mi++) { rsum[mi][0] = 0.f; rsum[mi][1] = 0.f; }
        #pragma unroll
        for (int ni = 0; ni < NT; ni++) {
            int cn = n0 + wn0 + ni*8 + c*2;
            float b0 = __ldg(&bias[cn]),  b1 = __ldg(&bias[cn+1]);
            float p0 = __ldg(&predW[cn]), p1 = __ldg(&predW[cn+1]);
            #pragma unroll
            for (int mi = 0; mi < 4; mi++) {
                rsum[mi][0] += ftanh(acc[mi][ni][0] + b0) * p0 + ftanh(acc[mi][ni][1] + b1) * p1;
                rsum[mi][1] += ftanh(acc[mi][ni][2] + b0) * p0 + ftanh(acc[mi][ni][3] + b1) * p1;
            }
        }
        __syncthreads();
        sred[tid] = 0.f;
        __syncthreads();
        #pragma unroll
        for (int mi = 0; mi < 4; mi++)
            #pragma unroll
            for (int h = 0; h < 2; h++) {
                float v = rsum[mi][h];
                v += __shfl_xor_sync(0xffffffffu, v, 1);
                v += __shfl_xor_sync(0xffffffffu, v, 2);
                if (c == 0) atomicAdd(&sred[wm0 + mi*16 + h*8 + g], v);
            }
        __syncthreads();
        atomicAdd(&predS[m0 + tid], sred[tid]);
    } else if (ACT == 5) {
        float* C = (float*)Cv;
        #pragma unroll
        for (int ni = 0; ni < NT; ni++) {
            int cn = n0 + wn0 + ni*8 + c*2;
            #pragma unroll
            for (int mi = 0; mi < 4; mi++) {
                int r0 = m0 + wm0 + mi*16 + g;
                *(float2*)&C[(size_t)r0    *ldc + cn] = make_float2(acc[mi][ni][0], acc[mi][ni][1]);
                *(float2*)&C[(size_t)(r0+8)*ldc + cn] = make_float2(acc[mi][ni][2], acc[mi][ni][3]);
            }
        }
    } else {
        __half* C = (__half*)Cv;
        #pragma unroll
        for (int ni = 0; ni < NT; ni++) {
            int cn  = n0 + wn0 + ni*8 + c*2;
            int cnp = PERM ? permc(cn) : cn;
            float b0 = __ldg(&bias[cn]), b1 = __ldg(&bias[cn+1]);
            #pragma unroll
            for (int mi = 0; mi < 4; mi++) {
                int r0 = m0 + wm0 + mi*16 + g;
                float v0 = acc[mi][ni][0] + b0, v1 = acc[mi][ni][1] + b1;
                float v2 = acc[mi][ni][2] + b0, v3 = acc[mi][ni][3] + b1;
                if (ACT == 1) { v0 = ftanh(v0); v1 = ftanh(v1); v2 = ftanh(v2); v3 = ftanh(v3); }
                else if (ACT == 2) { v0 = fsig(v0); v1 = fsig(v1); v2 = fsig(v2); v3 = fsig(v3); }
                else if (ACT == 3) {
                    if (cn < DV_) { v0 = fsig(v0); v1 = fsig(v1); v2 = fsig(v2); v3 = fsig(v3); }
                    else          { v0 = ftanh(v0); v1 = ftanh(v1); v2 = ftanh(v2); v3 = ftanh(v3); }
                }
                *(__half2*)&C[(size_t)r0    *ldc + cnp] = __floats2half2_rn(v0, v1);
                *(__half2*)&C[(size_t)(r0+8)*ldc + cnp] = __floats2half2_rn(v2, v3);
            }
        }
    }
}

// ==================== small kernels ====================
__global__ void k_prep(const float* __restrict__ eW, const float* __restrict__ eb,
                       const float* __restrict__ aW, const float* __restrict__ ab,
                       const float* __restrict__ d1W, const float* __restrict__ d2W,
                       const float* __restrict__ roW, const float* __restrict__ Mk)
{
    int i = blockIdx.x * blockDim.x + threadIdx.x;
    int stride = gridDim.x * blockDim.x;
    for (int j = i; j < NEA_*KEA_; j += stride) {
        int n = j / KEA_, k = j % KEA_;
        g_Wea[n*KEA_ + ph(k)] = __float2half((n < DV_) ? eW[n*KEA_ + k] : aW[(n - DV_)*KEA_ + k]);
    }
    for (int j = i; j < DQ_*DQ_; j += stride) {
        int n = j / DQ_, k = j % DQ_;
        g_Wd1[n*DQ_ + ph(k)] = __float2half(d1W[j]);
        g_Wd2[n*DQ_ + ph(k)] = __float2half(d2W[j]);
    }
    for (int j = i; j < F_*KRO_; j += stride) {
        int n = j / KRO_, k = j % KRO_;
        g_Wro[n*KRO_ + ph(k)] = __float2half(roW[j]);
    }
    for (int j = i; j < 64*DQ_; j += stride) {
        int n = j / DQ_, k = j % DQ_;
        g_Wmk[n*DQ_ + ph(k)] = __float2half(n < M_ ? Mk[n*DQ_ + k] : 0.f);
    }
    for (int j = i; j < NEA_; j += stride) g_bea[j] = (j < DV_) ? eb[j] : ab[j - DV_];
    for (int j = i; j < T_;  j += stride) g_predS[j] = 0.f;
    if (i < 2) g_accum[i] = 0.f;
}

__global__ void k_gather1(const int* __restrict__ q_data, const int* __restrict__ qa_data,
                          const int* __restrict__ time_data, const int* __restrict__ attempt_data,
                          const int* __restrict__ hint_data, const int* __restrict__ hintTotal_data,
                          const float* __restrict__ q_emb, const float* __restrict__ qa_emb,
                          const float* __restrict__ time_emb, const float* __restrict__ attempt_emb,
                          const float* __restrict__ ht_emb)
{
    int t = blockIdx.x, d = threadIdx.x;
    int pd = ph(d);
    int qi = q_data[t], ti = time_data[t], ai = attempt_data[t];
    int hi = hint_data[t], hti = hintTotal_data[t];
    float qe  = q_emb[(size_t)qi*DQ_ + d];
    float te  = time_emb[(size_t)ti*DQ_ + d];
    float ae  = attempt_emb[(size_t)ai*DQ_ + d];
    float he  = ht_emb[(size_t)hi*DQ_ + d];
    float hte = ht_emb[(size_t)hti*DQ_ + d];
    g_bufX[(size_t)t*DQ_ + pd]      = __float2half(te + qe);
    g_bufX[(size_t)(T_+t)*DQ_ + pd] = __float2half(he + hte + ae + qe);
    int qai = qa_data[t];
    g_bufQA[(size_t)t*DV_ + pd]            = __float2half(qa_emb[(size_t)qai*DV_ + d]);
    g_bufQA[(size_t)t*DV_ + ph(d + DQ_)]   = __float2half(qa_emb[(size_t)qai*DV_ + DQ_ + d]);
}

__global__ void k_buildx3(const int* __restrict__ q_data, const int* __restrict__ attempt_data,
                          const int* __restrict__ hint_data, const int* __restrict__ hintTotal_data,
                          const float* __restrict__ q_emb, const float* __restrict__ attempt_emb,
                          const float* __restrict__ ht_emb)
{
    int t = blockIdx.x, d = threadIdx.x;
    float qe = q_emb[(size_t)q_data[t]*DQ_ + d];
    float g  = attempt_emb[(size_t)attempt_data[t]*DQ_ + d]
             + ht_emb[(size_t)hint_data[t]*DQ_ + d]
             + ht_emb[(size_t)hintTotal_data[t]*DQ_ + d];
    float df = __half2float(g_bufTD[(size_t)(T_+t)*DQ_ + d]);   // plain
    g_bufX[(size_t)t*DQ_ + ph(d)] = __float2half(fmaf(df, g, qe));
}

__global__ void k_inputembed(const int* __restrict__ time_data, const float* __restrict__ time_emb)
{
    int t = blockIdx.x, d = threadIdx.x;
    int pd = ph(d);
    float te = time_emb[(size_t)time_data[t]*DQ_ + d];
    float tf = __half2float(g_bufTD[(size_t)t*DQ_ + d]);        // plain
    float qp = __half2float(g_bufQP[(size_t)t*DQ_ + pd]);       // permuted
    g_PredIn[(size_t)t*KRO_ + DV_ + pd] = __float2half(fmaf(tf, te, qp));
}

__global__ void k_softmax()
{
    int t = blockIdx.x * 8 + (threadIdx.x >> 5);
    int l = threadIdx.x & 31;
    if (t >= T_) return;
    float v0 = (l < M_)      ? g_logits[(size_t)t*LML_ + l]      : -1e30f;
    float v1 = (l + 32 < M_) ? g_logits[(size_t)t*LML_ + l + 32] : -1e30f;
    float mx = fmaxf(v0, v1);
    #pragma unroll
    for (int o = 16; o; o >>= 1) mx = fmaxf(mx, __shfl_xor_sync(0xffffffffu, mx, o));
    float e0 = (l < M_)      ? __expf(v0 - mx) : 0.f;
    float e1 = (l + 32 < M_) ? __expf(v1 - mx) : 0.f;
    float s = e0 + e1;
    #pragma unroll
    for (int o = 16; o; o >>= 1) s += __shfl_xor_sync(0xffffffffu, s, o);
    float inv = 1.f / s;
    if (l < M_)      g_logits[(size_t)t*LML_ + l]      = e0 * inv;
    if (l + 32 < M_) g_logits[(size_t)t*LML_ + l + 32] = e1 * inv;
}

// DV split 2-way -> 512 CTAs; prefetched, 1 sync/iter
__global__ void __launch_bounds__(128) k_scan(const float* __restrict__ Mv0)
{
    int b = blockIdx.x;
    int d = blockIdx.y * 128 + threadIdx.x;
    int pe = ph(d);                 // permuted col for e / predin
    int pa = ph(d + DV_) + (DV_ - DV_); // a col: logical DV_+d -> DV_ + ph within; compute directly:
    pa = ph(d + DV_);
    float mv[M_];
    #pragma unroll
    for (int m = 0; m < M_; m++) mv[m] = Mv0[m*DV_ + d];
    __shared__ float ws[2][64];
    size_t t0 = (size_t)b * S_;
    if (threadIdx.x < M_) ws[0][threadIdx.x] = g_logits[t0*LML_ + threadIdx.x];
    float e = __half2float(g_bufEA[t0*NEA_ + pe]);
    float a = __half2float(g_bufEA[t0*NEA_ + pa]);
    __syncthreads();
    for (int s = 0; s < S_; s++) {
        size_t t = t0 + s;
        float en = 0.f, an = 0.f;
        if (s + 1 < S_) {
            en = __half2float(g_bufEA[(t+1)*NEA_ + pe]);
            an = __half2float(g_bufEA[(t+1)*NEA_ + pa]);
            if (threadIdx.x < M_) ws[(s+1)&1][threadIdx.x] = g_logits[(t+1)*LML_ + threadIdx.x];
        }
        const float* wcur = ws[s&1];
        float rd = 0.f;
        #pragma unroll
        for (int m = 0; m < M_; m++) {
            float wm = wcur[m];
            rd = fmaf(wm, mv[m], rd);
            mv[m] = fmaf(mv[m], fmaf(-wm, e, 1.f), wm * a);
        }
        g_PredIn[t*KRO_ + pe] = __float2half(rd);
        __syncthreads();
        e = en; a = an;
    }
}

__global__ void k_loss(const int* __restrict__ target, const float* __restrict__ pred_b,
                       float* __restrict__ out)
{
    int i = blockIdx.x * blockDim.x + threadIdx.x;
    float le = 0.f, cnt = 0.f;
    if (i < T_) {
        float p = g_predS[i] + pred_b[0];
        int tg = target[i];
        bool mask = tg >= 1;
        float y = mask ? (float)(tg - 1) : 0.f;
        float sig = 1.f / (1.f + expf(-p));
        out[1 + i]      = mask ? sig : 0.f;
        out[1 + T_ + i] = mask ? y   : 0.f;
        if (mask) {
            le = fmaxf(p, 0.f) + log1pf(expf(-fabsf(p))) - p * y;
            cnt = 1.f;
        }
    }
    __shared__ float sle[256], scn[256];
    sle[threadIdx.x] = le; scn[threadIdx.x] = cnt;
    __syncthreads();
    for (int o = 128; o; o >>= 1) {
        if (threadIdx.x < o) { sle[threadIdx.x] += sle[threadIdx.x + o]; scn[threadIdx.x] += scn[threadIdx.x + o]; }
        __syncthreads();
    }
    if (threadIdx.x == 0) { atomicAdd(&g_accum[0], sle[0]); atomicAdd(&g_accum[1], scn[0]); }
}

__global__ void k_final(float* __restrict__ out)
{
    out[0] = g_accum[0] / fmaxf(g_accum[1], 1.f);
}

// ==================== host ====================
extern "C" void kernel_launch(void* const* d_in, const int* in_sizes, int n_in,
                              void* d_out, int out_size)
{
    const int*   q_data      = (const int*)  d_in[0];
    const int*   qa_data     = (const int*)  d_in[1];
    const int*   target      = (const int*)  d_in[2];
    const int*   time_data   = (const int*)  d_in[3];
    const int*   attempt_data= (const int*)  d_in[4];
    const int*   hint_data   = (const int*)  d_in[5];
    const int*   hintTotal   = (const int*)  d_in[6];
    const float* q_emb       = (const float*)d_in[7];
    const float* qa_emb      = (const float*)d_in[8];
    const float* time_emb    = (const float*)d_in[9];
    const float* attempt_emb = (const float*)d_in[10];
    const float* ht_emb      = (const float*)d_in[11];
    const float* Mk          = (const float*)d_in[12];
    const float* Mv0         = (const float*)d_in[13];
    const float* diff_W      = (const float*)d_in[14];
    const float* diff_b      = (const float*)d_in[15];
    const float* diff2_W     = (const float*)d_in[16];
    const float* diff2_b     = (const float*)d_in[17];
    const float* erase_W     = (const float*)d_in[18];
    const float* erase_b     = (const float*)d_in[19];
    const float* add_W       = (const float*)d_in[20];
    const float* add_b       = (const float*)d_in[21];
    const float* read_W      = (const float*)d_in[22];
    const float* read_b      = (const float*)d_in[23];
    const float* pred_W      = (const float*)d_in[24];
    const float* pred_b      = (const float*)d_in[25];
    float* out = (float*)d_out;

    __half *bufX, *bufU, *bufTD, *bufQP, *bufQA, *bufEA, *predin;
    __half *Wea, *Wd1, *Wd2, *Wro, *Wmk;
    float *logits, *predS, *bea;
    cudaGetSymbolAddress((void**)&bufX,   g_bufX);
    cudaGetSymbolAddress((void**)&bufU,   g_bufU);
    cudaGetSymbolAddress((void**)&bufTD,  g_bufTD);
    cudaGetSymbolAddress((void**)&bufQP,  g_bufQP);
    cudaGetSymbolAddress((void**)&bufQA,  g_bufQA);
    cudaGetSymbolAddress((void**)&bufEA,  g_bufEA);
    cudaGetSymbolAddress((void**)&predin, g_PredIn);
    cudaGetSymbolAddress((void**)&logits, g_logits);
    cudaGetSymbolAddress((void**)&predS,  g_predS);
    cudaGetSymbolAddress((void**)&Wea,    g_Wea);
    cudaGetSymbolAddress((void**)&Wd1,    g_Wd1);
    cudaGetSymbolAddress((void**)&Wd2,    g_Wd2);
    cudaGetSymbolAddress((void**)&Wro,    g_Wro);
    cudaGetSymbolAddress((void**)&Wmk,    g_Wmk);
    cudaGetSymbolAddress((void**)&bea,    g_bea);

    const int SM8 = (3*2048 + 3*8*256 + 128) * 4;   // 49664
    const int SM4 = (3*2048 + 3*4*256 + 128) * 4;   // 37376
    cudaFuncSetAttribute(k_mma<0,8>, cudaFuncAttributeMaxDynamicSharedMemorySize, SM8);
    cudaFuncSetAttribute(k_mma<1,8>, cudaFuncAttributeMaxDynamicSharedMemorySize, SM8);
    cudaFuncSetAttribute(k_mma<2,8>, cudaFuncAttributeMaxDynamicSharedMemorySize, SM8);
    cudaFuncSetAttribute(k_mma<3,8>, cudaFuncAttributeMaxDynamicSharedMemorySize, SM8);
    cudaFuncSetAttribute(k_mma<4,8>, cudaFuncAttributeMaxDynamicSharedMemorySize, SM8);
    cudaFuncSetAttribute(k_mma<5,4>, cudaFuncAttributeMaxDynamicSharedMemorySize, SM4);

    // 0) permuted f16 weights, zero predS/accum
    k_prep<<<1024, 256>>>(erase_W, erase_b, add_W, add_b, diff_W, diff2_W, read_W, Mk);
    // 1) gathers (permuted f16 outputs)
    k_gather1<<<T_, 128>>>(q_data, qa_data, time_data, attempt_data, hint_data, hintTotal,
                           q_emb, qa_emb, time_emb, attempt_emb, ht_emb);
    // 2) U = tanh(lin1(X)) over 2T rows
    k_mma<1,8><<<dim3(1, 2*T_/128), 128, SM8>>>(bufX, DQ_, DQ_, Wd1, diff_b, bufU, DQ_, nullptr, nullptr);
    // 3) TD = sigmoid(lin2(U)) over 2T rows (plain store)
    k_mma<2,8><<<dim3(1, 2*T_/128), 128, SM8>>>(bufU, DQ_, DQ_, Wd2, diff2_b, bufTD, DQ_, nullptr, nullptr);
    // 4) X3 = qe + diff_final * g
    k_buildx3<<<T_, 128>>>(q_data, attempt_data, hint_data, hintTotal, q_emb, attempt_emb, ht_emb);
    // 5) q_proc = lin1(X3) (permuted store)
    k_mma<0,8><<<dim3(1, T_/128), 128, SM8>>>(bufX, DQ_, DQ_, Wd1, diff_b, bufQP, DQ_, nullptr, nullptr);
    // 6) input_embed into PredIn cols [256,384)
    k_inputembed<<<T_, 128>>>(time_data, time_emb);
    // 7) logits = q_proc @ Mk^T (padded N=64, f32 plain out)
    k_mma<5,4><<<dim3(1, T_/128), 128, SM4>>>(bufQP, DQ_, DQ_, Wmk, nullptr, logits, LML_, nullptr, nullptr);
    // 8) softmax over M
    k_softmax<<<T_/8, 256>>>();
    // 9) E/A (permuted store)
    k_mma<3,8><<<dim3(4, T_/128), 128, SM8>>>(bufQA, KEA_, KEA_, Wea, bea, bufEA, NEA_, nullptr, nullptr);
    // 10) scan -> reads (permuted store)
    k_scan<<<dim3(B_, 2), 128>>>(Mv0);
    // 11) readout + fused pred dot
    k_mma<4,8><<<dim3(4, T_/128), 128, SM8>>>(predin, KRO_, KRO_, Wro, read_b, nullptr, 0, pred_W, predS);
    // 12) loss + outputs
    k_loss<<<(T_ + 255)/256, 256>>>(target, pred_b, out);
    k_final<<<1, 1>>>(out);
}

// round 8
// speedup vs baseline: 3.4801x; 1.2001x over previous
#include <cuda_runtime.h>
#include <cuda_fp16.h>
#include <math.h>
#include <stdint.h>

#define B_   256
#define S_   500
#define T_   (B_*S_)        // 128000
#define DQ_  128
#define DV_  256
#define M_   50
#define F_   512
#define NEA_ 512
#define KEA_ 256
#define KRO_ 384            // DV + DQ
#define LML_ 64             // padded logits row stride

// ---------------- scratch (device globals; no allocations) ----------------
// All GEMM-input half buffers are stored K-PAIR-PERMUTED (see ph()).
__device__ __half g_bufX [2*T_*DQ_];
__device__ __half g_bufU [2*T_*DQ_];
__device__ __half g_bufTD[2*T_*DQ_];    // plain (elementwise-consumed only)
__device__ __half g_bufQP[T_*DQ_];
__device__ __half g_bufQA[T_*DV_];
__device__ __half g_bufEA[T_*NEA_];
__device__ __half g_PredIn[T_*KRO_];
__device__ float  g_logits[T_*LML_];
__device__ float  g_predS[T_];
__device__ float  g_accum[2];
__device__ __half g_Wea[NEA_*KEA_];     // permuted
__device__ __half g_Wd1[DQ_*DQ_];       // permuted
__device__ __half g_Wd2[DQ_*DQ_];       // permuted
__device__ __half g_Wro[F_*KRO_];       // permuted
__device__ __half g_Wmk[64*DQ_];        // permuted, Mk padded to 64 rows
__device__ float  g_bea[NEA_];

// ==================== helpers ====================
__device__ __forceinline__ int ph(int d) {          // half index -> permuted half index
    int pair = d >> 1;
    int pi   = pair & 15;
    int pp   = (pair & ~15) | ((pi & 3) * 4 + (pi >> 2));
    return pp * 2 + (d & 1);
}
__device__ __forceinline__ int permc(int cn) {      // even col -> permuted even col
    int pair = cn >> 1;
    int pi   = pair & 15;
    int pp   = (pair & ~15) | ((pi & 3) * 4 + (pi >> 2));
    return pp * 2;
}
__device__ __forceinline__ float fsig(float x) { return 1.f / (1.f + __expf(-x)); }
__device__ __forceinline__ float ftanh(float x) {
    float ax = fabsf(x);
    float t  = 1.f - 2.f / (1.f + __expf(2.f * ax));
    return copysignf(t, x);
}
__device__ __forceinline__ void mma16(float* d,
    uint32_t a0, uint32_t a1, uint32_t a2, uint32_t a3,
    uint32_t b0, uint32_t b1)
{
    asm volatile(
        "mma.sync.aligned.m16n8k16.row.col.f32.f16.f16.f32 "
        "{%0,%1,%2,%3},{%4,%5,%6,%7},{%8,%9},{%0,%1,%2,%3};"
        : "+f"(d[0]), "+f"(d[1]), "+f"(d[2]), "+f"(d[3])
        : "r"(a0), "r"(a1), "r"(a2), "r"(a3), "r"(b0), "r"(b1));
}
__device__ __forceinline__ void cpa16(uint32_t dst, const void* src) {
    asm volatile("cp.async.cg.shared.global [%0], [%1], 16;" :: "r"(dst), "l"(src));
}

// ==================== f16 tensor GEMM: C = act(A @ W^T + bias) ==============
// 256 threads, 8 warps in (8/NWN) x NWN grid of 64x32 warp tiles.
// CTA tile = (8/NWN*64) x (NWN*32). K chunk 32 halves, 3-stage cp.async,
// operands pre-permuted (k-pair layout): staging is verbatim 16B copies.
// ACT: 0=none(perm) 1=tanh(perm) 2=sigmoid(plain) 3=EA-split(perm)
//      4=readout+pred dot 5=logits(plain f32)
template<int ACT, int NWN>
__global__ void __launch_bounds__(256, 2) k_mma(
    const __half* __restrict__ A, int lda, int K,
    const __half* __restrict__ W,
    const float* __restrict__ bias,
    void* __restrict__ Cv, int ldc,
    const float* __restrict__ predW, float* __restrict__ predS)
{
    constexpr int CTA_M = (8 / NWN) * 64;
    constexpr int CTA_N = NWN * 32;
    constexpr int AW = CTA_M * 16;      // uint32 words per A stage
    constexpr int BW = CTA_N * 16;
    constexpr bool PERM = (ACT == 0 || ACT == 1 || ACT == 3);

    extern __shared__ uint32_t sm[];
    uint32_t* As   = sm;                       // 3 * AW
    uint32_t* Bs   = sm + 3 * AW;              // 3 * BW
    float*    sred = (float*)(sm + 3 * AW + 3 * BW);

    const int tid  = threadIdx.x;
    const int m0   = blockIdx.y * CTA_M;
    const int n0   = blockIdx.x * CTA_N;
    const int lane = tid & 31, w = tid >> 5;
    const int g    = lane >> 2, c = lane & 3;
    const int wm0  = (w / NWN) * 64;
    const int wn0  = (w % NWN) * 32;
    const int srow = tid >> 2;                 // 0..63
    const int grp  = tid & 3;

    const int ldpA = lda >> 1, ldpW = K >> 1;
    const uint32_t* Ag = (const uint32_t*)A + (size_t)(m0 + srow) * ldpA + grp * 4;
    const uint32_t* Wg = (const uint32_t*)W + (size_t)(n0 + srow) * ldpW + grp * 4;

    const uint32_t asb = (uint32_t)__cvta_generic_to_shared(As) + (srow * 16 + grp * 4) * 4;
    const uint32_t bsb = (uint32_t)__cvta_generic_to_shared(Bs) + (srow * 16 + grp * 4) * 4;

    float acc[4][4][4];
    #pragma unroll
    for (int i = 0; i < 4; i++)
        #pragma unroll
        for (int j = 0; j < 4; j++)
            #pragma unroll
            for (int r = 0; r < 4; r++) acc[i][j][r] = 0.f;

    const int nch = K >> 5;

    auto stage = [&](int ch, int s) {
        uint32_t ab = asb + s * AW * 4;
        #pragma unroll
        for (int i = 0; i < CTA_M / 64; i++)
            cpa16(ab + i * (64 * 16 * 4), Ag + (size_t)i * 64 * ldpA + ch * 16);
        uint32_t bb = bsb + s * BW * 4;
        #pragma unroll
        for (int i = 0; i < CTA_N / 64; i++)
            cpa16(bb + i * (64 * 16 * 4), Wg + (size_t)i * 64 * ldpW + ch * 16);
        asm volatile("cp.async.commit_group;");
    };

    stage(0, 0);
    stage(1, 1);

    for (int ch = 0; ch < nch; ch++) {
        asm volatile("cp.async.wait_group 1;");
        __syncthreads();
        if (ch + 2 < nch) stage(ch + 2, (ch + 2) % 3);
        else asm volatile("cp.async.commit_group;");

        const uint32_t* as = As + (ch % 3) * AW;
        const uint32_t* bs = Bs + (ch % 3) * BW;
        uint4 alo[4], ahi[4];
        #pragma unroll
        for (int mi = 0; mi < 4; mi++) {
            alo[mi] = *(const uint4*)&as[(wm0 + mi*16 + g)     * 16 + c*4];
            ahi[mi] = *(const uint4*)&as[(wm0 + mi*16 + g + 8) * 16 + c*4];
        }
        #pragma unroll
        for (int ni = 0; ni < 4; ni++) {
            uint4 b = *(const uint4*)&bs[(wn0 + ni*8 + g) * 16 + c*4];
            #pragma unroll
            for (int mi = 0; mi < 4; mi++) {
                mma16(acc[mi][ni], alo[mi].x, ahi[mi].x, alo[mi].y, ahi[mi].y, b.x, b.y);
                mma16(acc[mi][ni], alo[mi].z, ahi[mi].z, alo[mi].w, ahi[mi].w, b.z, b.w);
            }
        }
        __syncthreads();
    }

    if (ACT == 4) {
        float rsum[4][2];
        #pragma unroll
        for (int mi = 0; mi < 4; mi++) { rsum[mi][0] = 0.f; rsum[mi][1] = 0.f; }
        #pragma unroll
        for (int ni = 0; ni < 4; ni++) {
            int cn = n0 + wn0 + ni*8 + c*2;
            float b0 = __ldg(&bias[cn]),  b1 = __ldg(&bias[cn+1]);
            float p0 = __ldg(&predW[cn]), p1 = __ldg(&predW[cn+1]);
            #pragma unroll
            for (int mi = 0; mi < 4; mi++) {
                rsum[mi][0] += ftanh(acc[mi][ni][0] + b0) * p0 + ftanh(acc[mi][ni][1] + b1) * p1;
                rsum[mi][1] += ftanh(acc[mi][ni][2] + b0) * p0 + ftanh(acc[mi][ni][3] + b1) * p1;
            }
        }
        if (tid < CTA_M) sred[tid] = 0.f;
        __syncthreads();
        #pragma unroll
        for (int mi = 0; mi < 4; mi++)
            #pragma unroll
            for (int h = 0; h < 2; h++) {
                float v = rsum[mi][h];
                v += __shfl_xor_sync(0xffffffffu, v, 1);
                v += __shfl_xor_sync(0xffffffffu, v, 2);
                if (c == 0) atomicAdd(&sred[wm0 + mi*16 + h*8 + g], v);
            }
        __syncthreads();
        if (tid < CTA_M) atomicAdd(&predS[m0 + tid], sred[tid]);
    } else if (ACT == 5) {
        float* C = (float*)Cv;
        #pragma unroll
        for (int ni = 0; ni < 4; ni++) {
            int cn = n0 + wn0 + ni*8 + c*2;
            #pragma unroll
            for (int mi = 0; mi < 4; mi++) {
                int r0 = m0 + wm0 + mi*16 + g;
                *(float2*)&C[(size_t)r0    *ldc + cn] = make_float2(acc[mi][ni][0], acc[mi][ni][1]);
                *(float2*)&C[(size_t)(r0+8)*ldc + cn] = make_float2(acc[mi][ni][2], acc[mi][ni][3]);
            }
        }
    } else {
        __half* C = (__half*)Cv;
        #pragma unroll
        for (int ni = 0; ni < 4; ni++) {
            int cn  = n0 + wn0 + ni*8 + c*2;
            int cnp = PERM ? permc(cn) : cn;
            float b0 = __ldg(&bias[cn]), b1 = __ldg(&bias[cn+1]);
            #pragma unroll
            for (int mi = 0; mi < 4; mi++) {
                int r0 = m0 + wm0 + mi*16 + g;
                float v0 = acc[mi][ni][0] + b0, v1 = acc[mi][ni][1] + b1;
                float v2 = acc[mi][ni][2] + b0, v3 = acc[mi][ni][3] + b1;
                if (ACT == 1) { v0 = ftanh(v0); v1 = ftanh(v1); v2 = ftanh(v2); v3 = ftanh(v3); }
                else if (ACT == 2) { v0 = fsig(v0); v1 = fsig(v1); v2 = fsig(v2); v3 = fsig(v3); }
                else if (ACT == 3) {
                    if (cn < DV_) { v0 = fsig(v0); v1 = fsig(v1); v2 = fsig(v2); v3 = fsig(v3); }
                    else          { v0 = ftanh(v0); v1 = ftanh(v1); v2 = ftanh(v2); v3 = ftanh(v3); }
                }
                *(__half2*)&C[(size_t)r0    *ldc + cnp] = __floats2half2_rn(v0, v1);
                *(__half2*)&C[(size_t)(r0+8)*ldc + cnp] = __floats2half2_rn(v2, v3);
            }
        }
    }
}

// ==================== small kernels ====================
__global__ void k_prep(const float* __restrict__ eW, const float* __restrict__ eb,
                       const float* __restrict__ aW, const float* __restrict__ ab,
                       const float* __restrict__ d1W, const float* __restrict__ d2W,
                       const float* __restrict__ roW, const float* __restrict__ Mk)
{
    int i = blockIdx.x * blockDim.x + threadIdx.x;
    int stride = gridDim.x * blockDim.x;
    for (int j = i; j < NEA_*KEA_; j += stride) {
        int n = j / KEA_, k = j % KEA_;
        g_Wea[n*KEA_ + ph(k)] = __float2half((n < DV_) ? eW[n*KEA_ + k] : aW[(n - DV_)*KEA_ + k]);
    }
    for (int j = i; j < DQ_*DQ_; j += stride) {
        int n = j / DQ_, k = j % DQ_;
        g_Wd1[n*DQ_ + ph(k)] = __float2half(d1W[j]);
        g_Wd2[n*DQ_ + ph(k)] = __float2half(d2W[j]);
    }
    for (int j = i; j < F_*KRO_; j += stride) {
        int n = j / KRO_, k = j % KRO_;
        g_Wro[n*KRO_ + ph(k)] = __float2half(roW[j]);
    }
    for (int j = i; j < 64*DQ_; j += stride) {
        int n = j / DQ_, k = j % DQ_;
        g_Wmk[n*DQ_ + ph(k)] = __float2half(n < M_ ? Mk[n*DQ_ + k] : 0.f);
    }
    for (int j = i; j < NEA_; j += stride) g_bea[j] = (j < DV_) ? eb[j] : ab[j - DV_];
    for (int j = i; j < T_;  j += stride) g_predS[j] = 0.f;
    if (i < 2) g_accum[i] = 0.f;
}

__global__ void k_gather1(const int* __restrict__ q_data, const int* __restrict__ qa_data,
                          const int* __restrict__ time_data, const int* __restrict__ attempt_data,
                          const int* __restrict__ hint_data, const int* __restrict__ hintTotal_data,
                          const float* __restrict__ q_emb, const float* __restrict__ qa_emb,
                          const float* __restrict__ time_emb, const float* __restrict__ attempt_emb,
                          const float* __restrict__ ht_emb)
{
    int t = blockIdx.x, d = threadIdx.x;
    int pd = ph(d);
    int qi = q_data[t], ti = time_data[t], ai = attempt_data[t];
    int hi = hint_data[t], hti = hintTotal_data[t];
    float qe  = q_emb[(size_t)qi*DQ_ + d];
    float te  = time_emb[(size_t)ti*DQ_ + d];
    float ae  = attempt_emb[(size_t)ai*DQ_ + d];
    float he  = ht_emb[(size_t)hi*DQ_ + d];
    float hte = ht_emb[(size_t)hti*DQ_ + d];
    g_bufX[(size_t)t*DQ_ + pd]      = __float2half(te + qe);
    g_bufX[(size_t)(T_+t)*DQ_ + pd] = __float2half(he + hte + ae + qe);
    int qai = qa_data[t];
    g_bufQA[(size_t)t*DV_ + pd]          = __float2half(qa_emb[(size_t)qai*DV_ + d]);
    g_bufQA[(size_t)t*DV_ + ph(d + DQ_)] = __float2half(qa_emb[(size_t)qai*DV_ + DQ_ + d]);
}

__global__ void k_buildx3(const int* __restrict__ q_data, const int* __restrict__ attempt_data,
                          const int* __restrict__ hint_data, const int* __restrict__ hintTotal_data,
                          const float* __restrict__ q_emb, const float* __restrict__ attempt_emb,
                          const float* __restrict__ ht_emb)
{
    int t = blockIdx.x, d = threadIdx.x;
    float qe = q_emb[(size_t)q_data[t]*DQ_ + d];
    float g  = attempt_emb[(size_t)attempt_data[t]*DQ_ + d]
             + ht_emb[(size_t)hint_data[t]*DQ_ + d]
             + ht_emb[(size_t)hintTotal_data[t]*DQ_ + d];
    float df = __half2float(g_bufTD[(size_t)(T_+t)*DQ_ + d]);   // plain
    g_bufX[(size_t)t*DQ_ + ph(d)] = __float2half(fmaf(df, g, qe));
}

__global__ void k_inputembed(const int* __restrict__ time_data, const float* __restrict__ time_emb)
{
    int t = blockIdx.x, d = threadIdx.x;
    int pd = ph(d);
    float te = time_emb[(size_t)time_data[t]*DQ_ + d];
    float tf = __half2float(g_bufTD[(size_t)t*DQ_ + d]);        // plain
    float qp = __half2float(g_bufQP[(size_t)t*DQ_ + pd]);       // permuted
    g_PredIn[(size_t)t*KRO_ + DV_ + pd] = __float2half(fmaf(tf, te, qp));
}

__global__ void k_softmax()
{
    int t = blockIdx.x * 8 + (threadIdx.x >> 5);
    int l = threadIdx.x & 31;
    if (t >= T_) return;
    float v0 = (l < M_)      ? g_logits[(size_t)t*LML_ + l]      : -1e30f;
    float v1 = (l + 32 < M_) ? g_logits[(size_t)t*LML_ + l + 32] : -1e30f;
    float mx = fmaxf(v0, v1);
    #pragma unroll
    for (int o = 16; o; o >>= 1) mx = fmaxf(mx, __shfl_xor_sync(0xffffffffu, mx, o));
    float e0 = (l < M_)      ? __expf(v0 - mx) : 0.f;
    float e1 = (l + 32 < M_) ? __expf(v1 - mx) : 0.f;
    float s = e0 + e1;
    #pragma unroll
    for (int o = 16; o; o >>= 1) s += __shfl_xor_sync(0xffffffffu, s, o);
    float inv = 1.f / s;
    if (l < M_)      g_logits[(size_t)t*LML_ + l]      = e0 * inv;
    if (l + 32 < M_) g_logits[(size_t)t*LML_ + l + 32] = e1 * inv;
}

// DV split 2-way -> 512 CTAs; prefetched, 1 sync/iter
__global__ void __launch_bounds__(128) k_scan(const float* __restrict__ Mv0)
{
    int b = blockIdx.x;
    int d = blockIdx.y * 128 + threadIdx.x;
    int pe = ph(d);
    int pa = ph(d + DV_);
    float mv[M_];
    #pragma unroll
    for (int m = 0; m < M_; m++) mv[m] = Mv0[m*DV_ + d];
    __shared__ float ws[2][64];
    size_t t0 = (size_t)b * S_;
    if (threadIdx.x < M_) ws[0][threadIdx.x] = g_logits[t0*LML_ + threadIdx.x];
    float e = __half2float(g_bufEA[t0*NEA_ + pe]);
    float a = __half2float(g_bufEA[t0*NEA_ + pa]);
    __syncthreads();
    for (int s = 0; s < S_; s++) {
        size_t t = t0 + s;
        float en = 0.f, an = 0.f;
        if (s + 1 < S_) {
            en = __half2float(g_bufEA[(t+1)*NEA_ + pe]);
            an = __half2float(g_bufEA[(t+1)*NEA_ + pa]);
            if (threadIdx.x < M_) ws[(s+1)&1][threadIdx.x] = g_logits[(t+1)*LML_ + threadIdx.x];
        }
        const float* wcur = ws[s&1];
        float rd = 0.f;
        #pragma unroll
        for (int m = 0; m < M_; m++) {
            float wm = wcur[m];
            rd = fmaf(wm, mv[m], rd);
            mv[m] = fmaf(mv[m], fmaf(-wm, e, 1.f), wm * a);
        }
        g_PredIn[t*KRO_ + pe] = __float2half(rd);
        __syncthreads();
        e = en; a = an;
    }
}

__global__ void k_loss(const int* __restrict__ target, const float* __restrict__ pred_b,
                       float* __restrict__ out)
{
    int i = blockIdx.x * blockDim.x + threadIdx.x;
    float le = 0.f, cnt = 0.f;
    if (i < T_) {
        float p = g_predS[i] + pred_b[0];
        int tg = target[i];
        bool mask = tg >= 1;
        float y = mask ? (float)(tg - 1) : 0.f;
        float sig = 1.f / (1.f + expf(-p));
        out[1 + i]      = mask ? sig : 0.f;
        out[1 + T_ + i] = mask ? y   : 0.f;
        if (mask) {
            le = fmaxf(p, 0.f) + log1pf(expf(-fabsf(p))) - p * y;
            cnt = 1.f;
        }
    }
    __shared__ float sle[256], scn[256];
    sle[threadIdx.x] = le; scn[threadIdx.x] = cnt;
    __syncthreads();
    for (int o = 128; o; o >>= 1) {
        if (threadIdx.x < o) { sle[threadIdx.x] += sle[threadIdx.x + o]; scn[threadIdx.x] += scn[threadIdx.x + o]; }
        __syncthreads();
    }
    if (threadIdx.x == 0) { atomicAdd(&g_accum[0], sle[0]); atomicAdd(&g_accum[1], scn[0]); }
}

__global__ void k_final(float* __restrict__ out)
{
    out[0] = g_accum[0] / fmaxf(g_accum[1], 1.f);
}

// ==================== host ====================
extern "C" void kernel_launch(void* const* d_in, const int* in_sizes, int n_in,
                              void* d_out, int out_size)
{
    const int*   q_data      = (const int*)  d_in[0];
    const int*   qa_data     = (const int*)  d_in[1];
    const int*   target      = (const int*)  d_in[2];
    const int*   time_data   = (const int*)  d_in[3];
    const int*   attempt_data= (const int*)  d_in[4];
    const int*   hint_data   = (const int*)  d_in[5];
    const int*   hintTotal   = (const int*)  d_in[6];
    const float* q_emb       = (const float*)d_in[7];
    const float* qa_emb      = (const float*)d_in[8];
    const float* time_emb    = (const float*)d_in[9];
    const float* attempt_emb = (const float*)d_in[10];
    const float* ht_emb      = (const float*)d_in[11];
    const float* Mk          = (const float*)d_in[12];
    const float* Mv0         = (const float*)d_in[13];
    const float* diff_W      = (const float*)d_in[14];
    const float* diff_b      = (const float*)d_in[15];
    const float* diff2_W     = (const float*)d_in[16];
    const float* diff2_b     = (const float*)d_in[17];
    const float* erase_W     = (const float*)d_in[18];
    const float* erase_b     = (const float*)d_in[19];
    const float* add_W       = (const float*)d_in[20];
    const float* add_b       = (const float*)d_in[21];
    const float* read_W      = (const float*)d_in[22];
    const float* read_b      = (const float*)d_in[23];
    const float* pred_W      = (const float*)d_in[24];
    const float* pred_b      = (const float*)d_in[25];
    float* out = (float*)d_out;

    __half *bufX, *bufU, *bufTD, *bufQP, *bufQA, *bufEA, *predin;
    __half *Wea, *Wd1, *Wd2, *Wro, *Wmk;
    float *logits, *predS, *bea;
    cudaGetSymbolAddress((void**)&bufX,   g_bufX);
    cudaGetSymbolAddress((void**)&bufU,   g_bufU);
    cudaGetSymbolAddress((void**)&bufTD,  g_bufTD);
    cudaGetSymbolAddress((void**)&bufQP,  g_bufQP);
    cudaGetSymbolAddress((void**)&bufQA,  g_bufQA);
    cudaGetSymbolAddress((void**)&bufEA,  g_bufEA);
    cudaGetSymbolAddress((void**)&predin, g_PredIn);
    cudaGetSymbolAddress((void**)&logits, g_logits);
    cudaGetSymbolAddress((void**)&predS,  g_predS);
    cudaGetSymbolAddress((void**)&Wea,    g_Wea);
    cudaGetSymbolAddress((void**)&Wd1,    g_Wd1);
    cudaGetSymbolAddress((void**)&Wd2,    g_Wd2);
    cudaGetSymbolAddress((void**)&Wro,    g_Wro);
    cudaGetSymbolAddress((void**)&Wmk,    g_Wmk);
    cudaGetSymbolAddress((void**)&bea,    g_bea);

    // smem: 3 stages * (CTA_M*16 + CTA_N*16) words + 128 floats
    const int SM44 = (3*(128*16) + 3*(128*16) + 128) * 4;   // NWN=4: 49664
    const int SM52 = (3*(256*16) + 3*(64*16)  + 128) * 4;   // NWN=2: 61952
    cudaFuncSetAttribute(k_mma<0,4>, cudaFuncAttributeMaxDynamicSharedMemorySize, SM44);
    cudaFuncSetAttribute(k_mma<1,4>, cudaFuncAttributeMaxDynamicSharedMemorySize, SM44);
    cudaFuncSetAttribute(k_mma<2,4>, cudaFuncAttributeMaxDynamicSharedMemorySize, SM44);
    cudaFuncSetAttribute(k_mma<3,4>, cudaFuncAttributeMaxDynamicSharedMemorySize, SM44);
    cudaFuncSetAttribute(k_mma<4,4>, cudaFuncAttributeMaxDynamicSharedMemorySize, SM44);
    cudaFuncSetAttribute(k_mma<5,2>, cudaFuncAttributeMaxDynamicSharedMemorySize, SM52);

    // 0) permuted f16 weights, zero predS/accum
    k_prep<<<1024, 256>>>(erase_W, erase_b, add_W, add_b, diff_W, diff2_W, read_W, Mk);
    // 1) gathers (permuted f16 outputs)
    k_gather1<<<T_, 128>>>(q_data, qa_data, time_data, attempt_data, hint_data, hintTotal,
                           q_emb, qa_emb, time_emb, attempt_emb, ht_emb);
    // 2) U = tanh(lin1(X)) over 2T rows
    k_mma<1,4><<<dim3(1, 2*T_/128), 256, SM44>>>(bufX, DQ_, DQ_, Wd1, diff_b, bufU, DQ_, nullptr, nullptr);
    // 3) TD = sigmoid(lin2(U)) over 2T rows (plain store)
    k_mma<2,4><<<dim3(1, 2*T_/128), 256, SM44>>>(bufU, DQ_, DQ_, Wd2, diff2_b, bufTD, DQ_, nullptr, nullptr);
    // 4) X3 = qe + diff_final * g
    k_buildx3<<<T_, 128>>>(q_data, attempt_data, hint_data, hintTotal, q_emb, attempt_emb, ht_emb);
    // 5) q_proc = lin1(X3) (permuted store)
    k_mma<0,4><<<dim3(1, T_/128), 256, SM44>>>(bufX, DQ_, DQ_, Wd1, diff_b, bufQP, DQ_, nullptr, nullptr);
    // 6) input_embed into PredIn cols [256,384)
    k_inputembed<<<T_, 128>>>(time_data, time_emb);
    // 7) logits = q_proc @ Mk^T (CTA 256x64, padded N=64, f32 plain out)
    k_mma<5,2><<<dim3(1, T_/256), 256, SM52>>>(bufQP, DQ_, DQ_, Wmk, nullptr, logits, LML_, nullptr, nullptr);
    // 8) softmax over M
    k_softmax<<<T_/8, 256>>>();
    // 9) E/A (permuted store)
    k_mma<3,4><<<dim3(4, T_/128), 256, SM44>>>(bufQA, KEA_, KEA_, Wea, bea, bufEA, NEA_, nullptr, nullptr);
    // 10) scan -> reads (permuted store)
    k_scan<<<dim3(B_, 2), 128>>>(Mv0);
    // 11) readout + fused pred dot
    k_mma<4,4><<<dim3(4, T_/128), 256, SM44>>>(predin, KRO_, KRO_, Wro, read_b, nullptr, 0, pred_W, predS);
    // 12) loss + outputs
    k_loss<<<(T_ + 255)/256, 256>>>(target, pred_b, out);
    k_final<<<1, 1>>>(out);
}

// round 9
// speedup vs baseline: 3.7037x; 1.0642x over previous
#include <cuda_runtime.h>
#include <cuda_fp16.h>
#include <math.h>
#include <stdint.h>

#define B_   256
#define S_   500
#define T_   (B_*S_)        // 128000
#define DQ_  128
#define DV_  256
#define M_   50
#define F_   512
#define NEA_ 512
#define KEA_ 256
#define KRO_ 384            // DV + DQ
#define LML_ 64             // padded logits row stride

// ---------------- scratch (device globals; no allocations) ----------------
// GEMM-input half buffers stored K-PAIR-PERMUTED (see ph()).
__device__ __half g_bufX [2*T_*DQ_];    // X1 rows [0,T), X2 rows [T,2T)
__device__ __half g_bufX3[T_*DQ_];      // X3 (permuted)
__device__ __half g_bufTD[T_*DQ_];      // time_final rows, plain
__device__ __half g_bufQA[T_*DV_];
__device__ __half g_bufEA[T_*NEA_];
__device__ __half g_PredIn[T_*KRO_];
__device__ float  g_logits[T_*LML_];
__device__ float  g_predS[T_];
__device__ float  g_accum[2];
__device__ __half g_Wea[NEA_*KEA_];     // permuted
__device__ __half g_Wd1[DQ_*DQ_];       // permuted
__device__ __half g_Wd2[DQ_*DQ_];       // permuted
__device__ __half g_Wro[F_*KRO_];       // permuted
__device__ __half g_Wmk[128*DQ_];       // permuted, Mk padded to 128 rows
__device__ float  g_bea[NEA_];

// ==================== helpers ====================
__device__ __forceinline__ int ph(int d) {
    int pair = d >> 1;
    int pi   = pair & 15;
    int pp   = (pair & ~15) | ((pi & 3) * 4 + (pi >> 2));
    return pp * 2 + (d & 1);
}
__device__ __forceinline__ int permc(int cn) {      // even col -> permuted even col
    int pair = cn >> 1;
    int pi   = pair & 15;
    int pp   = (pair & ~15) | ((pi & 3) * 4 + (pi >> 2));
    return pp * 2;
}
__device__ __forceinline__ float fsig(float x) { return 1.f / (1.f + __expf(-x)); }
__device__ __forceinline__ float ftanh(float x) {
    float ax = fabsf(x);
    float t  = 1.f - 2.f / (1.f + __expf(2.f * ax));
    return copysignf(t, x);
}
__device__ __forceinline__ void mma16(float* d,
    uint32_t a0, uint32_t a1, uint32_t a2, uint32_t a3,
    uint32_t b0, uint32_t b1)
{
    asm volatile(
        "mma.sync.aligned.m16n8k16.row.col.f32.f16.f16.f32 "
        "{%0,%1,%2,%3},{%4,%5,%6,%7},{%8,%9},{%0,%1,%2,%3};"
        : "+f"(d[0]), "+f"(d[1]), "+f"(d[2]), "+f"(d[3])
        : "r"(a0), "r"(a1), "r"(a2), "r"(a3), "r"(b0), "r"(b1));
}
__device__ __forceinline__ void cpa16(uint32_t dst, const void* src) {
    asm volatile("cp.async.cg.shared.global [%0], [%1], 16;" :: "r"(dst), "l"(src));
}

// ==================== generic f16 tensor GEMM (EA / readout) ================
// 256 threads, 8 warps 2m x 4n, warp tile 64x32, CTA 128x128.
// ACT: 3=EA-split(perm store)  4=readout + fused pred dot
template<int ACT>
__global__ void __launch_bounds__(256, 2) k_mma(
    const __half* __restrict__ A, int lda, int K,
    const __half* __restrict__ W,
    const float* __restrict__ bias,
    void* __restrict__ Cv, int ldc,
    const float* __restrict__ predW, float* __restrict__ predS)
{
    extern __shared__ uint32_t sm[];
    uint32_t* As   = sm;                       // 3 * 2048
    uint32_t* Bs   = sm + 3 * 2048;            // 3 * 2048
    float*    sred = (float*)(sm + 6 * 2048);

    const int tid  = threadIdx.x;
    const int m0   = blockIdx.y * 128;
    const int n0   = blockIdx.x * 128;
    const int lane = tid & 31, w = tid >> 5;
    const int g    = lane >> 2, c = lane & 3;
    const int wm0  = (w >> 2) * 64;
    const int wn0  = (w & 3) * 32;
    const int srow = tid >> 2;
    const int grp  = tid & 3;

    const int ldpA = lda >> 1, ldpW = K >> 1;
    const uint32_t* Ag = (const uint32_t*)A + (size_t)(m0 + srow) * ldpA + grp * 4;
    const uint32_t* Wg = (const uint32_t*)W + (size_t)(n0 + srow) * ldpW + grp * 4;

    const uint32_t asb = (uint32_t)__cvta_generic_to_shared(As) + (srow * 16 + grp * 4) * 4;
    const uint32_t bsb = (uint32_t)__cvta_generic_to_shared(Bs) + (srow * 16 + grp * 4) * 4;

    float acc[4][4][4];
    #pragma unroll
    for (int i = 0; i < 4; i++)
        #pragma unroll
        for (int j = 0; j < 4; j++)
            #pragma unroll
            for (int r = 0; r < 4; r++) acc[i][j][r] = 0.f;

    const int nch = K >> 5;

    auto stage = [&](int ch, int s) {
        uint32_t ab = asb + s * 2048 * 4;
        cpa16(ab,                Ag + ch * 16);
        cpa16(ab + 64 * 16 * 4,  Ag + (size_t)64 * ldpA + ch * 16);
        uint32_t bb = bsb + s * 2048 * 4;
        cpa16(bb,                Wg + ch * 16);
        cpa16(bb + 64 * 16 * 4,  Wg + (size_t)64 * ldpW + ch * 16);
        asm volatile("cp.async.commit_group;");
    };

    stage(0, 0);
    stage(1, 1);

    for (int ch = 0; ch < nch; ch++) {
        asm volatile("cp.async.wait_group 1;");
        __syncthreads();
        if (ch + 2 < nch) stage(ch + 2, (ch + 2) % 3);
        else asm volatile("cp.async.commit_group;");

        const uint32_t* as = As + (ch % 3) * 2048;
        const uint32_t* bs = Bs + (ch % 3) * 2048;
        uint4 alo[4], ahi[4];
        #pragma unroll
        for (int mi = 0; mi < 4; mi++) {
            alo[mi] = *(const uint4*)&as[(wm0 + mi*16 + g)     * 16 + c*4];
            ahi[mi] = *(const uint4*)&as[(wm0 + mi*16 + g + 8) * 16 + c*4];
        }
        #pragma unroll
        for (int ni = 0; ni < 4; ni++) {
            uint4 b = *(const uint4*)&bs[(wn0 + ni*8 + g) * 16 + c*4];
            #pragma unroll
            for (int mi = 0; mi < 4; mi++) {
                mma16(acc[mi][ni], alo[mi].x, ahi[mi].x, alo[mi].y, ahi[mi].y, b.x, b.y);
                mma16(acc[mi][ni], alo[mi].z, ahi[mi].z, alo[mi].w, ahi[mi].w, b.z, b.w);
            }
        }
    }

    if (ACT == 4) {
        float rsum[4][2];
        #pragma unroll
        for (int mi = 0; mi < 4; mi++) { rsum[mi][0] = 0.f; rsum[mi][1] = 0.f; }
        #pragma unroll
        for (int ni = 0; ni < 4; ni++) {
            int cn = n0 + wn0 + ni*8 + c*2;
            float b0 = __ldg(&bias[cn]),  b1 = __ldg(&bias[cn+1]);
            float p0 = __ldg(&predW[cn]), p1 = __ldg(&predW[cn+1]);
            #pragma unroll
            for (int mi = 0; mi < 4; mi++) {
                rsum[mi][0] += ftanh(acc[mi][ni][0] + b0) * p0 + ftanh(acc[mi][ni][1] + b1) * p1;
                rsum[mi][1] += ftanh(acc[mi][ni][2] + b0) * p0 + ftanh(acc[mi][ni][3] + b1) * p1;
            }
        }
        __syncthreads();
        if (tid < 128) sred[tid] = 0.f;
        __syncthreads();
        #pragma unroll
        for (int mi = 0; mi < 4; mi++)
            #pragma unroll
            for (int h = 0; h < 2; h++) {
                float v = rsum[mi][h];
                v += __shfl_xor_sync(0xffffffffu, v, 1);
                v += __shfl_xor_sync(0xffffffffu, v, 2);
                if (c == 0) atomicAdd(&sred[wm0 + mi*16 + h*8 + g], v);
            }
        __syncthreads();
        if (tid < 128) atomicAdd(&predS[m0 + tid], sred[tid]);
    } else {
        __half* C = (__half*)Cv;
        #pragma unroll
        for (int ni = 0; ni < 4; ni++) {
            int cn  = n0 + wn0 + ni*8 + c*2;
            int cnp = permc(cn);
            float b0 = __ldg(&bias[cn]), b1 = __ldg(&bias[cn+1]);
            #pragma unroll
            for (int mi = 0; mi < 4; mi++) {
                int r0 = m0 + wm0 + mi*16 + g;
                float v0 = acc[mi][ni][0] + b0, v1 = acc[mi][ni][1] + b1;
                float v2 = acc[mi][ni][2] + b0, v3 = acc[mi][ni][3] + b1;
                if (cn < DV_) { v0 = fsig(v0); v1 = fsig(v1); v2 = fsig(v2); v3 = fsig(v3); }
                else          { v0 = ftanh(v0); v1 = ftanh(v1); v2 = ftanh(v2); v3 = ftanh(v3); }
                *(__half2*)&C[(size_t)r0    *ldc + cnp] = __floats2half2_rn(v0, v1);
                *(__half2*)&C[(size_t)(r0+8)*ldc + cnp] = __floats2half2_rn(v2, v3);
            }
        }
    }
}

// ==================== fused lin1 -> tanh -> lin2 (+ X3 build) ===============
// Grid 2T/128 CTAs of 256 threads. U stays in smem between the two GEMMs.
__global__ void __launch_bounds__(256, 2) k_lin12(
    const __half* __restrict__ A,    // bufX permuted, 2T x 128
    const __half* __restrict__ W1, const __half* __restrict__ W2,
    const float* __restrict__ b1, const float* __restrict__ b2,
    __half* __restrict__ TD, __half* __restrict__ X3,
    const int* __restrict__ q_data, const int* __restrict__ attempt_data,
    const int* __restrict__ hint_data, const int* __restrict__ hintTotal_data,
    const float* __restrict__ q_emb, const float* __restrict__ attempt_emb,
    const float* __restrict__ ht_emb)
{
    extern __shared__ uint32_t sm[];
    uint32_t* Xs = sm;             // 3*2048
    uint32_t* Bs = sm + 3*2048;    // 3*2048
    uint32_t* Us = sm + 6*2048;    // 8192 (128 rows x 64 words, permuted)

    const int tid  = threadIdx.x;
    const int m0   = blockIdx.x * 128;
    const int lane = tid & 31, w = tid >> 5;
    const int g    = lane >> 2, c = lane & 3;
    const int wm0  = (w >> 2) * 64;
    const int wn0  = (w & 3) * 32;
    const int srow = tid >> 2;
    const int grp  = tid & 3;

    const uint32_t* Ag  = (const uint32_t*)A  + (size_t)(m0 + srow) * 64 + grp * 4;
    const uint32_t* W1g = (const uint32_t*)W1 + (size_t)srow * 64 + grp * 4;
    const uint32_t* W2g = (const uint32_t*)W2 + (size_t)srow * 64 + grp * 4;

    const uint32_t xsb = (uint32_t)__cvta_generic_to_shared(Xs) + (srow*16 + grp*4) * 4;
    const uint32_t bsb = (uint32_t)__cvta_generic_to_shared(Bs) + (srow*16 + grp*4) * 4;

    float acc[4][4][4];
    #pragma unroll
    for (int i = 0; i < 4; i++)
        #pragma unroll
        for (int j = 0; j < 4; j++)
            #pragma unroll
            for (int r = 0; r < 4; r++) acc[i][j][r] = 0.f;

    auto stage1 = [&](int ch, int s) {
        uint32_t xb = xsb + s * 2048 * 4;
        cpa16(xb,               Ag + ch * 16);
        cpa16(xb + 64*16*4,     Ag + (size_t)64*64 + ch * 16);
        uint32_t bb = bsb + s * 2048 * 4;
        cpa16(bb,               W1g + ch * 16);
        cpa16(bb + 64*16*4,     W1g + (size_t)64*64 + ch * 16);
        asm volatile("cp.async.commit_group;");
    };

    stage1(0, 0); stage1(1, 1);
    for (int ch = 0; ch < 4; ch++) {
        asm volatile("cp.async.wait_group 1;");
        __syncthreads();
        if (ch + 2 < 4) stage1(ch + 2, (ch + 2) % 3);
        else asm volatile("cp.async.commit_group;");
        const uint32_t* xs = Xs + (ch % 3) * 2048;
        const uint32_t* bs = Bs + (ch % 3) * 2048;
        uint4 alo[4], ahi[4];
        #pragma unroll
        for (int mi = 0; mi < 4; mi++) {
            alo[mi] = *(const uint4*)&xs[(wm0 + mi*16 + g)     * 16 + c*4];
            ahi[mi] = *(const uint4*)&xs[(wm0 + mi*16 + g + 8) * 16 + c*4];
        }
        #pragma unroll
        for (int ni = 0; ni < 4; ni++) {
            uint4 b = *(const uint4*)&bs[(wn0 + ni*8 + g) * 16 + c*4];
            #pragma unroll
            for (int mi = 0; mi < 4; mi++) {
                mma16(acc[mi][ni], alo[mi].x, ahi[mi].x, alo[mi].y, ahi[mi].y, b.x, b.y);
                mma16(acc[mi][ni], alo[mi].z, ahi[mi].z, alo[mi].w, ahi[mi].w, b.z, b.w);
            }
        }
    }
    asm volatile("cp.async.wait_group 0;");

    // U = tanh(acc + b1) -> smem (permuted f16), reset acc
    #pragma unroll
    for (int ni = 0; ni < 4; ni++) {
        int cn = wn0 + ni*8 + c*2;
        float bb0 = __ldg(&b1[cn]), bb1 = __ldg(&b1[cn+1]);
        int pw = permc(cn) >> 1;
        #pragma unroll
        for (int mi = 0; mi < 4; mi++) {
            int r0 = wm0 + mi*16 + g;
            __half2 h0 = __floats2half2_rn(ftanh(acc[mi][ni][0] + bb0), ftanh(acc[mi][ni][1] + bb1));
            __half2 h1 = __floats2half2_rn(ftanh(acc[mi][ni][2] + bb0), ftanh(acc[mi][ni][3] + bb1));
            Us[r0*64 + pw]     = *(uint32_t*)&h0;
            Us[(r0+8)*64 + pw] = *(uint32_t*)&h1;
            acc[mi][ni][0] = acc[mi][ni][1] = acc[mi][ni][2] = acc[mi][ni][3] = 0.f;
        }
    }
    __syncthreads();

    // GEMM2: A = Us (smem), B = W2 staged
    auto stage2 = [&](int ch, int s) {
        uint32_t bb = bsb + s * 2048 * 4;
        cpa16(bb,           W2g + ch * 16);
        cpa16(bb + 64*16*4, W2g + (size_t)64*64 + ch * 16);
        asm volatile("cp.async.commit_group;");
    };
    stage2(0, 0); stage2(1, 1);
    for (int ch = 0; ch < 4; ch++) {
        asm volatile("cp.async.wait_group 1;");
        __syncthreads();
        if (ch + 2 < 4) stage2(ch + 2, (ch + 2) % 3);
        else asm volatile("cp.async.commit_group;");
        const uint32_t* bs = Bs + (ch % 3) * 2048;
        uint4 alo[4], ahi[4];
        #pragma unroll
        for (int mi = 0; mi < 4; mi++) {
            alo[mi] = *(const uint4*)&Us[(wm0 + mi*16 + g)     * 64 + ch*16 + c*4];
            ahi[mi] = *(const uint4*)&Us[(wm0 + mi*16 + g + 8) * 64 + ch*16 + c*4];
        }
        #pragma unroll
        for (int ni = 0; ni < 4; ni++) {
            uint4 b = *(const uint4*)&bs[(wn0 + ni*8 + g) * 16 + c*4];
            #pragma unroll
            for (int mi = 0; mi < 4; mi++) {
                mma16(acc[mi][ni], alo[mi].x, ahi[mi].x, alo[mi].y, ahi[mi].y, b.x, b.y);
                mma16(acc[mi][ni], alo[mi].z, ahi[mi].z, alo[mi].w, ahi[mi].w, b.z, b.w);
            }
        }
    }

    // epilogue: sigmoid; time rows -> TD plain; diff rows -> X3 permuted
    const bool isdiff = (m0 >= T_);
    #pragma unroll
    for (int mi = 0; mi < 4; mi++) {
        #pragma unroll
        for (int h = 0; h < 2; h++) {
            int r = wm0 + mi*16 + g + h*8;
            int t = m0 + r;
            if (!isdiff) {
                #pragma unroll
                for (int ni = 0; ni < 4; ni++) {
                    int cn = wn0 + ni*8 + c*2;
                    float v0 = fsig(acc[mi][ni][2*h]   + __ldg(&b2[cn]));
                    float v1 = fsig(acc[mi][ni][2*h+1] + __ldg(&b2[cn+1]));
                    *(__half2*)&TD[(size_t)t*DQ_ + cn] = __floats2half2_rn(v0, v1);
                }
            } else {
                int tt = t - T_;
                int qi = q_data[tt], ai = attempt_data[tt];
                int hi = hint_data[tt], hti = hintTotal_data[tt];
                #pragma unroll
                for (int ni = 0; ni < 4; ni++) {
                    int cn = wn0 + ni*8 + c*2;
                    float v0 = fsig(acc[mi][ni][2*h]   + __ldg(&b2[cn]));
                    float v1 = fsig(acc[mi][ni][2*h+1] + __ldg(&b2[cn+1]));
                    float qe0 = q_emb[(size_t)qi*DQ_ + cn],   qe1 = q_emb[(size_t)qi*DQ_ + cn+1];
                    float g0  = attempt_emb[(size_t)ai*DQ_ + cn]
                              + ht_emb[(size_t)hi*DQ_ + cn] + ht_emb[(size_t)hti*DQ_ + cn];
                    float g1  = attempt_emb[(size_t)ai*DQ_ + cn+1]
                              + ht_emb[(size_t)hi*DQ_ + cn+1] + ht_emb[(size_t)hti*DQ_ + cn+1];
                    *(__half2*)&X3[(size_t)tt*DQ_ + permc(cn)] =
                        __floats2half2_rn(fmaf(v0, g0, qe0), fmaf(v1, g1, qe1));
                }
            }
        }
    }
}

// ==================== fused q_proc -> input_embed + logits -> softmax =======
__global__ void __launch_bounds__(256, 2) k_qplog(
    const __half* __restrict__ A,    // X3 permuted, T x 128
    const __half* __restrict__ W1,   // Wd1
    const __half* __restrict__ WM,   // Wmk padded 128x128
    const float* __restrict__ b1,
    const __half* __restrict__ TD,
    const int* __restrict__ time_data, const float* __restrict__ time_emb,
    __half* __restrict__ PredIn, float* __restrict__ logits)
{
    extern __shared__ uint32_t sm[];
    uint32_t* Xs  = sm;
    uint32_t* Bs  = sm + 3*2048;
    uint32_t* Us  = sm + 6*2048;
    float*    red = (float*)(sm + 6*2048 + 8192);   // 4*128 floats

    const int tid  = threadIdx.x;
    const int m0   = blockIdx.x * 128;
    const int lane = tid & 31, w = tid >> 5;
    const int g    = lane >> 2, c = lane & 3;
    const int wm0  = (w >> 2) * 64;
    const int wn0  = (w & 3) * 32;
    const int srow = tid >> 2;
    const int grp  = tid & 3;

    const uint32_t* Ag  = (const uint32_t*)A  + (size_t)(m0 + srow) * 64 + grp * 4;
    const uint32_t* W1g = (const uint32_t*)W1 + (size_t)srow * 64 + grp * 4;
    const uint32_t* WMg = (const uint32_t*)WM + (size_t)srow * 64 + grp * 4;

    const uint32_t xsb = (uint32_t)__cvta_generic_to_shared(Xs) + (srow*16 + grp*4) * 4;
    const uint32_t bsb = (uint32_t)__cvta_generic_to_shared(Bs) + (srow*16 + grp*4) * 4;

    float acc[4][4][4];
    #pragma unroll
    for (int i = 0; i < 4; i++)
        #pragma unroll
        for (int j = 0; j < 4; j++)
            #pragma unroll
            for (int r = 0; r < 4; r++) acc[i][j][r] = 0.f;

    auto stage1 = [&](int ch, int s) {
        uint32_t xb = xsb + s * 2048 * 4;
        cpa16(xb,           Ag + ch * 16);
        cpa16(xb + 64*16*4, Ag + (size_t)64*64 + ch * 16);
        uint32_t bb = bsb + s * 2048 * 4;
        cpa16(bb,           W1g + ch * 16);
        cpa16(bb + 64*16*4, W1g + (size_t)64*64 + ch * 16);
        asm volatile("cp.async.commit_group;");
    };
    stage1(0, 0); stage1(1, 1);
    for (int ch = 0; ch < 4; ch++) {
        asm volatile("cp.async.wait_group 1;");
        __syncthreads();
        if (ch + 2 < 4) stage1(ch + 2, (ch + 2) % 3);
        else asm volatile("cp.async.commit_group;");
        const uint32_t* xs = Xs + (ch % 3) * 2048;
        const uint32_t* bs = Bs + (ch % 3) * 2048;
        uint4 alo[4], ahi[4];
        #pragma unroll
        for (int mi = 0; mi < 4; mi++) {
            alo[mi] = *(const uint4*)&xs[(wm0 + mi*16 + g)     * 16 + c*4];
            ahi[mi] = *(const uint4*)&xs[(wm0 + mi*16 + g + 8) * 16 + c*4];
        }
        #pragma unroll
        for (int ni = 0; ni < 4; ni++) {
            uint4 b = *(const uint4*)&bs[(wn0 + ni*8 + g) * 16 + c*4];
            #pragma unroll
            for (int mi = 0; mi < 4; mi++) {
                mma16(acc[mi][ni], alo[mi].x, ahi[mi].x, alo[mi].y, ahi[mi].y, b.x, b.y);
                mma16(acc[mi][ni], alo[mi].z, ahi[mi].z, alo[mi].w, ahi[mi].w, b.z, b.w);
            }
        }
    }
    asm volatile("cp.async.wait_group 0;");

    // epilogue1: qp = acc + b1 -> f16 -> Us; input_embed -> PredIn
    #pragma unroll
    for (int mi = 0; mi < 4; mi++) {
        #pragma unroll
        for (int h = 0; h < 2; h++) {
            int r = wm0 + mi*16 + g + h*8;
            int t = m0 + r;
            int ti = time_data[t];
            #pragma unroll
            for (int ni = 0; ni < 4; ni++) {
                int cn = wn0 + ni*8 + c*2;
                float q0 = acc[mi][ni][2*h]   + __ldg(&b1[cn]);
                float q1 = acc[mi][ni][2*h+1] + __ldg(&b1[cn+1]);
                __half2 hq = __floats2half2_rn(q0, q1);
                Us[r*64 + (permc(cn) >> 1)] = *(uint32_t*)&hq;
                float2 qp2 = __half22float2(hq);
                __half2 tfh = *(const __half2*)&TD[(size_t)t*DQ_ + cn];
                float2 tf2 = __half22float2(tfh);
                float te0 = time_emb[(size_t)ti*DQ_ + cn], te1 = time_emb[(size_t)ti*DQ_ + cn+1];
                *(__half2*)&PredIn[(size_t)t*KRO_ + DV_ + permc(cn)] =
                    __floats2half2_rn(fmaf(tf2.x, te0, qp2.x), fmaf(tf2.y, te1, qp2.y));
                acc[mi][ni][2*h] = 0.f; acc[mi][ni][2*h+1] = 0.f;
            }
        }
    }
    __syncthreads();

    // GEMM2: logits = QP(Us) @ Mk128^T
    auto stage2 = [&](int ch, int s) {
        uint32_t bb = bsb + s * 2048 * 4;
        cpa16(bb,           WMg + ch * 16);
        cpa16(bb + 64*16*4, WMg + (size_t)64*64 + ch * 16);
        asm volatile("cp.async.commit_group;");
    };
    stage2(0, 0); stage2(1, 1);
    for (int ch = 0; ch < 4; ch++) {
        asm volatile("cp.async.wait_group 1;");
        __syncthreads();
        if (ch + 2 < 4) stage2(ch + 2, (ch + 2) % 3);
        else asm volatile("cp.async.commit_group;");
        const uint32_t* bs = Bs + (ch % 3) * 2048;
        uint4 alo[4], ahi[4];
        #pragma unroll
        for (int mi = 0; mi < 4; mi++) {
            alo[mi] = *(const uint4*)&Us[(wm0 + mi*16 + g)     * 64 + ch*16 + c*4];
            ahi[mi] = *(const uint4*)&Us[(wm0 + mi*16 + g + 8) * 64 + ch*16 + c*4];
        }
        #pragma unroll
        for (int ni = 0; ni < 4; ni++) {
            uint4 b = *(const uint4*)&bs[(wn0 + ni*8 + g) * 16 + c*4];
            #pragma unroll
            for (int mi = 0; mi < 4; mi++) {
                mma16(acc[mi][ni], alo[mi].x, ahi[mi].x, alo[mi].y, ahi[mi].y, b.x, b.y);
                mma16(acc[mi][ni], alo[mi].z, ahi[mi].z, alo[mi].w, ahi[mi].w, b.z, b.w);
            }
        }
    }

    // fused masked softmax over cols < M_ (50)
    float mx[4][2];
    #pragma unroll
    for (int mi = 0; mi < 4; mi++) { mx[mi][0] = -1e30f; mx[mi][1] = -1e30f; }
    #pragma unroll
    for (int ni = 0; ni < 4; ni++) {
        int cn = wn0 + ni*8 + c*2;
        bool ok0 = cn < M_, ok1 = (cn+1) < M_;
        #pragma unroll
        for (int mi = 0; mi < 4; mi++)
            #pragma unroll
            for (int h = 0; h < 2; h++) {
                if (ok0) mx[mi][h] = fmaxf(mx[mi][h], acc[mi][ni][2*h]);
                if (ok1) mx[mi][h] = fmaxf(mx[mi][h], acc[mi][ni][2*h+1]);
            }
    }
    #pragma unroll
    for (int mi = 0; mi < 4; mi++)
        #pragma unroll
        for (int h = 0; h < 2; h++) {
            mx[mi][h] = fmaxf(mx[mi][h], __shfl_xor_sync(0xffffffffu, mx[mi][h], 1));
            mx[mi][h] = fmaxf(mx[mi][h], __shfl_xor_sync(0xffffffffu, mx[mi][h], 2));
        }
    __syncthreads();
    if (c == 0) {
        #pragma unroll
        for (int mi = 0; mi < 4; mi++)
            #pragma unroll
            for (int h = 0; h < 2; h++)
                red[(w & 3) * 128 + wm0 + mi*16 + g + h*8] = mx[mi][h];
    }
    __syncthreads();
    float mxr[4][2];
    #pragma unroll
    for (int mi = 0; mi < 4; mi++)
        #pragma unroll
        for (int h = 0; h < 2; h++) {
            int r = wm0 + mi*16 + g + h*8;
            mxr[mi][h] = fmaxf(fmaxf(red[r], red[128 + r]), fmaxf(red[256 + r], red[384 + r]));
        }
    __syncthreads();
    float sum_[4][2];
    #pragma unroll
    for (int mi = 0; mi < 4; mi++) { sum_[mi][0] = 0.f; sum_[mi][1] = 0.f; }
    #pragma unroll
    for (int ni = 0; ni < 4; ni++) {
        int cn = wn0 + ni*8 + c*2;
        bool ok0 = cn < M_, ok1 = (cn+1) < M_;
        #pragma unroll
        for (int mi = 0; mi < 4; mi++)
            #pragma unroll
            for (int h = 0; h < 2; h++) {
                float e0 = ok0 ? __expf(acc[mi][ni][2*h]   - mxr[mi][h]) : 0.f;
                float e1 = ok1 ? __expf(acc[mi][ni][2*h+1] - mxr[mi][h]) : 0.f;
                acc[mi][ni][2*h] = e0; acc[mi][ni][2*h+1] = e1;
                sum_[mi][h] += e0 + e1;
            }
    }
    #pragma unroll
    for (int mi = 0; mi < 4; mi++)
        #pragma unroll
        for (int h = 0; h < 2; h++) {
            sum_[mi][h] += __shfl_xor_sync(0xffffffffu, sum_[mi][h], 1);
            sum_[mi][h] += __shfl_xor_sync(0xffffffffu, sum_[mi][h], 2);
        }
    if (c == 0) {
        #pragma unroll
        for (int mi = 0; mi < 4; mi++)
            #pragma unroll
            for (int h = 0; h < 2; h++)
                red[(w & 3) * 128 + wm0 + mi*16 + g + h*8] = sum_[mi][h];
    }
    __syncthreads();
    #pragma unroll
    for (int mi = 0; mi < 4; mi++) {
        #pragma unroll
        for (int h = 0; h < 2; h++) {
            int r = wm0 + mi*16 + g + h*8;
            float inv = 1.f / (red[r] + red[128 + r] + red[256 + r] + red[384 + r]);
            size_t t = m0 + r;
            #pragma unroll
            for (int ni = 0; ni < 4; ni++) {
                int cn = wn0 + ni*8 + c*2;
                if (cn < M_)   logits[t*LML_ + cn]   = acc[mi][ni][2*h]   * inv;
                if (cn+1 < M_) logits[t*LML_ + cn+1] = acc[mi][ni][2*h+1] * inv;
            }
        }
    }
}

// ==================== small kernels ====================
__global__ void k_prep(const float* __restrict__ eW, const float* __restrict__ eb,
                       const float* __restrict__ aW, const float* __restrict__ ab,
                       const float* __restrict__ d1W, const float* __restrict__ d2W,
                       const float* __restrict__ roW, const float* __restrict__ Mk)
{
    int i = blockIdx.x * blockDim.x + threadIdx.x;
    int stride = gridDim.x * blockDim.x;
    for (int j = i; j < NEA_*KEA_; j += stride) {
        int n = j / KEA_, k = j % KEA_;
        g_Wea[n*KEA_ + ph(k)] = __float2half((n < DV_) ? eW[n*KEA_ + k] : aW[(n - DV_)*KEA_ + k]);
    }
    for (int j = i; j < DQ_*DQ_; j += stride) {
        int n = j / DQ_, k = j % DQ_;
        g_Wd1[n*DQ_ + ph(k)] = __float2half(d1W[j]);
        g_Wd2[n*DQ_ + ph(k)] = __float2half(d2W[j]);
    }
    for (int j = i; j < F_*KRO_; j += stride) {
        int n = j / KRO_, k = j % KRO_;
        g_Wro[n*KRO_ + ph(k)] = __float2half(roW[j]);
    }
    for (int j = i; j < 128*DQ_; j += stride) {
        int n = j / DQ_, k = j % DQ_;
        g_Wmk[n*DQ_ + ph(k)] = __float2half(n < M_ ? Mk[n*DQ_ + k] : 0.f);
    }
    for (int j = i; j < NEA_; j += stride) g_bea[j] = (j < DV_) ? eb[j] : ab[j - DV_];
    for (int j = i; j < T_;  j += stride) g_predS[j] = 0.f;
    if (i < 2) g_accum[i] = 0.f;
}

__global__ void k_gather1(const int* __restrict__ q_data, const int* __restrict__ qa_data,
                          const int* __restrict__ time_data, const int* __restrict__ attempt_data,
                          const int* __restrict__ hint_data, const int* __restrict__ hintTotal_data,
                          const float* __restrict__ q_emb, const float* __restrict__ qa_emb,
                          const float* __restrict__ time_emb, const float* __restrict__ attempt_emb,
                          const float* __restrict__ ht_emb)
{
    int t = blockIdx.x, d = threadIdx.x;
    int pd = ph(d);
    int qi = q_data[t], ti = time_data[t], ai = attempt_data[t];
    int hi = hint_data[t], hti = hintTotal_data[t];
    float qe  = q_emb[(size_t)qi*DQ_ + d];
    float te  = time_emb[(size_t)ti*DQ_ + d];
    float ae  = attempt_emb[(size_t)ai*DQ_ + d];
    float he  = ht_emb[(size_t)hi*DQ_ + d];
    float hte = ht_emb[(size_t)hti*DQ_ + d];
    g_bufX[(size_t)t*DQ_ + pd]      = __float2half(te + qe);
    g_bufX[(size_t)(T_+t)*DQ_ + pd] = __float2half(he + hte + ae + qe);
    int qai = qa_data[t];
    g_bufQA[(size_t)t*DV_ + pd]          = __float2half(qa_emb[(size_t)qai*DV_ + d]);
    g_bufQA[(size_t)t*DV_ + ph(d + DQ_)] = __float2half(qa_emb[(size_t)qai*DV_ + DQ_ + d]);
}

// DV split 2-way -> 512 CTAs; prefetched, 1 sync/iter, 2-chain rd
__global__ void __launch_bounds__(128) k_scan(const float* __restrict__ Mv0)
{
    int b = blockIdx.x;
    int d = blockIdx.y * 128 + threadIdx.x;
    int pe = ph(d);
    int pa = ph(d + DV_);
    float mv[M_];
    #pragma unroll
    for (int m = 0; m < M_; m++) mv[m] = Mv0[m*DV_ + d];
    __shared__ float ws[2][64];
    size_t t0 = (size_t)b * S_;
    if (threadIdx.x < M_) ws[0][threadIdx.x] = g_logits[t0*LML_ + threadIdx.x];
    float e = __half2float(g_bufEA[t0*NEA_ + pe]);
    float a = __half2float(g_bufEA[t0*NEA_ + pa]);
    __syncthreads();
    for (int s = 0; s < S_; s++) {
        size_t t = t0 + s;
        float en = 0.f, an = 0.f;
        if (s + 1 < S_) {
            en = __half2float(g_bufEA[(t+1)*NEA_ + pe]);
            an = __half2float(g_bufEA[(t+1)*NEA_ + pa]);
            if (threadIdx.x < M_) ws[(s+1)&1][threadIdx.x] = g_logits[(t+1)*LML_ + threadIdx.x];
        }
        const float* wcur = ws[s&1];
        float rd0 = 0.f, rd1 = 0.f;
        #pragma unroll
        for (int m = 0; m < M_; m += 2) {
            float w0 = wcur[m], w1 = wcur[m+1];
            rd0 = fmaf(w0, mv[m],   rd0);
            rd1 = fmaf(w1, mv[m+1], rd1);
            mv[m]   = fmaf(mv[m],   fmaf(-w0, e, 1.f), w0 * a);
            mv[m+1] = fmaf(mv[m+1], fmaf(-w1, e, 1.f), w1 * a);
        }
        g_PredIn[t*KRO_ + pe] = __float2half(rd0 + rd1);
        __syncthreads();
        e = en; a = an;
    }
}

__global__ void k_loss(const int* __restrict__ target, const float* __restrict__ pred_b,
                       float* __restrict__ out)
{
    int i = blockIdx.x * blockDim.x + threadIdx.x;
    float le = 0.f, cnt = 0.f;
    if (i < T_) {
        float p = g_predS[i] + pred_b[0];
        int tg = target[i];
        bool mask = tg >= 1;
        float y = mask ? (float)(tg - 1) : 0.f;
        float sig = 1.f / (1.f + expf(-p));
        out[1 + i]      = mask ? sig : 0.f;
        out[1 + T_ + i] = mask ? y   : 0.f;
        if (mask) {
            le = fmaxf(p, 0.f) + log1pf(expf(-fabsf(p))) - p * y;
            cnt = 1.f;
        }
    }
    __shared__ float sle[256], scn[256];
    sle[threadIdx.x] = le; scn[threadIdx.x] = cnt;
    __syncthreads();
    for (int o = 128; o; o >>= 1) {
        if (threadIdx.x < o) { sle[threadIdx.x] += sle[threadIdx.x + o]; scn[threadIdx.x] += scn[threadIdx.x + o]; }
        __syncthreads();
    }
    if (threadIdx.x == 0) { atomicAdd(&g_accum[0], sle[0]); atomicAdd(&g_accum[1], scn[0]); }
}

__global__ void k_final(float* __restrict__ out)
{
    out[0] = g_accum[0] / fmaxf(g_accum[1], 1.f);
}

// ==================== host ====================
extern "C" void kernel_launch(void* const* d_in, const int* in_sizes, int n_in,
                              void* d_out, int out_size)
{
    const int*   q_data      = (const int*)  d_in[0];
    const int*   qa_data     = (const int*)  d_in[1];
    const int*   target      = (const int*)  d_in[2];
    const int*   time_data   = (const int*)  d_in[3];
    const int*   attempt_data= (const int*)  d_in[4];
    const int*   hint_data   = (const int*)  d_in[5];
    const int*   hintTotal   = (const int*)  d_in[6];
    const float* q_emb       = (const float*)d_in[7];
    const float* qa_emb      = (const float*)d_in[8];
    const float* time_emb    = (const float*)d_in[9];
    const float* attempt_emb = (const float*)d_in[10];
    const float* ht_emb      = (const float*)d_in[11];
    const float* Mk          = (const float*)d_in[12];
    const float* Mv0         = (const float*)d_in[13];
    const float* diff_W      = (const float*)d_in[14];
    const float* diff_b      = (const float*)d_in[15];
    const float* diff2_W     = (const float*)d_in[16];
    const float* diff2_b     = (const float*)d_in[17];
    const float* erase_W     = (const float*)d_in[18];
    const float* erase_b     = (const float*)d_in[19];
    const float* add_W       = (const float*)d_in[20];
    const float* add_b       = (const float*)d_in[21];
    const float* read_W      = (const float*)d_in[22];
    const float* read_b      = (const float*)d_in[23];
    const float* pred_W      = (const float*)d_in[24];
    const float* pred_b      = (const float*)d_in[25];
    float* out = (float*)d_out;

    __half *bufX, *bufX3, *bufTD, *bufQA, *bufEA, *predin;
    __half *Wea, *Wd1, *Wd2, *Wro, *Wmk;
    float *logits, *predS, *bea;
    cudaGetSymbolAddress((void**)&bufX,   g_bufX);
    cudaGetSymbolAddress((void**)&bufX3,  g_bufX3);
    cudaGetSymbolAddress((void**)&bufTD,  g_bufTD);
    cudaGetSymbolAddress((void**)&bufQA,  g_bufQA);
    cudaGetSymbolAddress((void**)&bufEA,  g_bufEA);
    cudaGetSymbolAddress((void**)&predin, g_PredIn);
    cudaGetSymbolAddress((void**)&logits, g_logits);
    cudaGetSymbolAddress((void**)&predS,  g_predS);
    cudaGetSymbolAddress((void**)&Wea,    g_Wea);
    cudaGetSymbolAddress((void**)&Wd1,    g_Wd1);
    cudaGetSymbolAddress((void**)&Wd2,    g_Wd2);
    cudaGetSymbolAddress((void**)&Wro,    g_Wro);
    cudaGetSymbolAddress((void**)&Wmk,    g_Wmk);
    cudaGetSymbolAddress((void**)&bea,    g_bea);

    const int SMG   = (6*2048 + 128) * 4;            // k_mma: 49664
    const int SML   = (6*2048 + 8192) * 4;           // k_lin12: 81920
    const int SMQ   = (6*2048 + 8192 + 512) * 4;     // k_qplog: 83968
    cudaFuncSetAttribute(k_mma<3>, cudaFuncAttributeMaxDynamicSharedMemorySize, SMG);
    cudaFuncSetAttribute(k_mma<4>, cudaFuncAttributeMaxDynamicSharedMemorySize, SMG);
    cudaFuncSetAttribute(k_lin12,  cudaFuncAttributeMaxDynamicSharedMemorySize, SML);
    cudaFuncSetAttribute(k_qplog,  cudaFuncAttributeMaxDynamicSharedMemorySize, SMQ);

    // 0) permuted f16 weights, zero predS/accum
    k_prep<<<1024, 256>>>(erase_W, erase_b, add_W, add_b, diff_W, diff2_W, read_W, Mk);
    // 1) gathers (permuted f16)
    k_gather1<<<T_, 128>>>(q_data, qa_data, time_data, attempt_data, hint_data, hintTotal,
                           q_emb, qa_emb, time_emb, attempt_emb, ht_emb);
    // 2) fused lin1->tanh->lin2 (+X3)
    k_lin12<<<2*T_/128, 256, SML>>>(bufX, Wd1, Wd2, diff_b, diff2_b, bufTD, bufX3,
                                    q_data, attempt_data, hint_data, hintTotal,
                                    q_emb, attempt_emb, ht_emb);
    // 3) fused q_proc -> input_embed + logits -> softmax
    k_qplog<<<T_/128, 256, SMQ>>>(bufX3, Wd1, Wmk, diff_b, bufTD,
                                  time_data, time_emb, predin, logits);
    // 4) E/A (permuted store)
    k_mma<3><<<dim3(4, T_/128), 256, SMG>>>(bufQA, KEA_, KEA_, Wea, bea, bufEA, NEA_, nullptr, nullptr);
    // 5) scan -> reads
    k_scan<<<dim3(B_, 2), 128>>>(Mv0);
    // 6) readout + fused pred dot
    k_mma<4><<<dim3(4, T_/128), 256, SMG>>>(predin, KRO_, KRO_, Wro, read_b, nullptr, 0, pred_W, predS);
    // 7) loss + outputs
    k_loss<<<(T_ + 255)/256, 256>>>(target, pred_b, out);
    k_final<<<1, 1>>>(out);
}

// round 10
// speedup vs baseline: 3.8556x; 1.0410x over previous
#include <cuda_runtime.h>
#include <cuda_fp16.h>
#include <math.h>
#include <stdint.h>

#define B_   256
#define S_   500
#define T_   (B_*S_)        // 128000
#define DQ_  128
#define DV_  256
#define M_   50
#define F_   512
#define NEA_ 512
#define KEA_ 256
#define KRO_ 384            // DV + DQ
#define LML_ 64             // padded logits row stride
#define USTR 80             // padded Us row stride (words) -> conflict-free

// ---------------- scratch (device globals; no allocations) ----------------
__device__ __half g_bufX [2*T_*DQ_];    // permuted
__device__ __half g_bufX3[T_*DQ_];      // permuted
__device__ __half g_bufTD[T_*DQ_];      // plain
__device__ __half g_bufQA[T_*DV_];      // permuted
__device__ __half g_bufEA[T_*NEA_];     // permuted
__device__ __half g_PredIn[T_*KRO_];    // permuted
__device__ float  g_logits[T_*LML_];
__device__ float  g_predS[T_];
__device__ float  g_accum[2];
__device__ __half g_Wea[NEA_*KEA_];
__device__ __half g_Wd1[DQ_*DQ_];
__device__ __half g_Wd2[DQ_*DQ_];
__device__ __half g_Wro[F_*KRO_];
__device__ __half g_Wmk[128*DQ_];
__device__ float  g_bea[NEA_];

// ==================== helpers ====================
__device__ __forceinline__ int ph(int d) {
    int pair = d >> 1;
    int pi   = pair & 15;
    int pp   = (pair & ~15) | ((pi & 3) * 4 + (pi >> 2));
    return pp * 2 + (d & 1);
}
__device__ __forceinline__ int permc(int cn) {
    int pair = cn >> 1;
    int pi   = pair & 15;
    int pp   = (pair & ~15) | ((pi & 3) * 4 + (pi >> 2));
    return pp * 2;
}
__device__ __forceinline__ float fsig(float x) { return 1.f / (1.f + __expf(-x)); }
__device__ __forceinline__ float ftanh(float x) {
    float ax = fabsf(x);
    float t  = 1.f - 2.f / (1.f + __expf(2.f * ax));
    return copysignf(t, x);
}
__device__ __forceinline__ void mma16(float* d,
    uint32_t a0, uint32_t a1, uint32_t a2, uint32_t a3,
    uint32_t b0, uint32_t b1)
{
    asm volatile(
        "mma.sync.aligned.m16n8k16.row.col.f32.f16.f16.f32 "
        "{%0,%1,%2,%3},{%4,%5,%6,%7},{%8,%9},{%0,%1,%2,%3};"
        : "+f"(d[0]), "+f"(d[1]), "+f"(d[2]), "+f"(d[3])
        : "r"(a0), "r"(a1), "r"(a2), "r"(a3), "r"(b0), "r"(b1));
}
__device__ __forceinline__ void cpa16(uint32_t dst, const void* src) {
    asm volatile("cp.async.cg.shared.global [%0], [%1], 16;" :: "r"(dst), "l"(src));
}

// ==================== generic f16 tensor GEMM (EA / readout) ================
template<int ACT>
__global__ void __launch_bounds__(256, 2) k_mma(
    const __half* __restrict__ A, int lda, int K,
    const __half* __restrict__ W,
    const float* __restrict__ bias,
    void* __restrict__ Cv, int ldc,
    const float* __restrict__ predW, float* __restrict__ predS)
{
    extern __shared__ uint32_t sm[];
    uint32_t* As   = sm;
    uint32_t* Bs   = sm + 3 * 2048;
    float*    sred = (float*)(sm + 6 * 2048);

    const int tid  = threadIdx.x;
    const int m0   = blockIdx.y * 128;
    const int n0   = blockIdx.x * 128;
    const int lane = tid & 31, w = tid >> 5;
    const int g    = lane >> 2, c = lane & 3;
    const int wm0  = (w >> 2) * 64;
    const int wn0  = (w & 3) * 32;
    const int srow = tid >> 2;
    const int grp  = tid & 3;

    const int ldpA = lda >> 1, ldpW = K >> 1;
    const uint32_t* Ag = (const uint32_t*)A + (size_t)(m0 + srow) * ldpA + grp * 4;
    const uint32_t* Wg = (const uint32_t*)W + (size_t)(n0 + srow) * ldpW + grp * 4;

    const uint32_t asb = (uint32_t)__cvta_generic_to_shared(As) + (srow * 16 + grp * 4) * 4;
    const uint32_t bsb = (uint32_t)__cvta_generic_to_shared(Bs) + (srow * 16 + grp * 4) * 4;

    float acc[4][4][4];
    #pragma unroll
    for (int i = 0; i < 4; i++)
        #pragma unroll
        for (int j = 0; j < 4; j++)
            #pragma unroll
            for (int r = 0; r < 4; r++) acc[i][j][r] = 0.f;

    const int nch = K >> 5;

    auto stage = [&](int ch, int s) {
        uint32_t ab = asb + s * 2048 * 4;
        cpa16(ab,                Ag + ch * 16);
        cpa16(ab + 64 * 16 * 4,  Ag + (size_t)64 * ldpA + ch * 16);
        uint32_t bb = bsb + s * 2048 * 4;
        cpa16(bb,                Wg + ch * 16);
        cpa16(bb + 64 * 16 * 4,  Wg + (size_t)64 * ldpW + ch * 16);
        asm volatile("cp.async.commit_group;");
    };

    stage(0, 0);
    stage(1, 1);

    for (int ch = 0; ch < nch; ch++) {
        asm volatile("cp.async.wait_group 1;");
        __syncthreads();
        if (ch + 2 < nch) stage(ch + 2, (ch + 2) % 3);
        else asm volatile("cp.async.commit_group;");

        const uint32_t* as = As + (ch % 3) * 2048;
        const uint32_t* bs = Bs + (ch % 3) * 2048;
        uint4 alo[4], ahi[4];
        #pragma unroll
        for (int mi = 0; mi < 4; mi++) {
            alo[mi] = *(const uint4*)&as[(wm0 + mi*16 + g)     * 16 + c*4];
            ahi[mi] = *(const uint4*)&as[(wm0 + mi*16 + g + 8) * 16 + c*4];
        }
        #pragma unroll
        for (int ni = 0; ni < 4; ni++) {
            uint4 b = *(const uint4*)&bs[(wn0 + ni*8 + g) * 16 + c*4];
            #pragma unroll
            for (int mi = 0; mi < 4; mi++) {
                mma16(acc[mi][ni], alo[mi].x, ahi[mi].x, alo[mi].y, ahi[mi].y, b.x, b.y);
                mma16(acc[mi][ni], alo[mi].z, ahi[mi].z, alo[mi].w, ahi[mi].w, b.z, b.w);
            }
        }
    }

    if (ACT == 4) {
        float rsum[4][2];
        #pragma unroll
        for (int mi = 0; mi < 4; mi++) { rsum[mi][0] = 0.f; rsum[mi][1] = 0.f; }
        #pragma unroll
        for (int ni = 0; ni < 4; ni++) {
            int cn = n0 + wn0 + ni*8 + c*2;
            float b0 = __ldg(&bias[cn]),  b1 = __ldg(&bias[cn+1]);
            float p0 = __ldg(&predW[cn]), p1 = __ldg(&predW[cn+1]);
            #pragma unroll
            for (int mi = 0; mi < 4; mi++) {
                rsum[mi][0] += ftanh(acc[mi][ni][0] + b0) * p0 + ftanh(acc[mi][ni][1] + b1) * p1;
                rsum[mi][1] += ftanh(acc[mi][ni][2] + b0) * p0 + ftanh(acc[mi][ni][3] + b1) * p1;
            }
        }
        __syncthreads();
        if (tid < 128) sred[tid] = 0.f;
        __syncthreads();
        #pragma unroll
        for (int mi = 0; mi < 4; mi++)
            #pragma unroll
            for (int h = 0; h < 2; h++) {
                float v = rsum[mi][h];
                v += __shfl_xor_sync(0xffffffffu, v, 1);
                v += __shfl_xor_sync(0xffffffffu, v, 2);
                if (c == 0) atomicAdd(&sred[wm0 + mi*16 + h*8 + g], v);
            }
        __syncthreads();
        if (tid < 128) atomicAdd(&predS[m0 + tid], sred[tid]);
    } else {
        __half* C = (__half*)Cv;
        #pragma unroll
        for (int ni = 0; ni < 4; ni++) {
            int cn  = n0 + wn0 + ni*8 + c*2;
            int cnp = permc(cn);
            float b0 = __ldg(&bias[cn]), b1 = __ldg(&bias[cn+1]);
            #pragma unroll
            for (int mi = 0; mi < 4; mi++) {
                int r0 = m0 + wm0 + mi*16 + g;
                float v0 = acc[mi][ni][0] + b0, v1 = acc[mi][ni][1] + b1;
                float v2 = acc[mi][ni][2] + b0, v3 = acc[mi][ni][3] + b1;
                if (cn < DV_) { v0 = fsig(v0); v1 = fsig(v1); v2 = fsig(v2); v3 = fsig(v3); }
                else          { v0 = ftanh(v0); v1 = ftanh(v1); v2 = ftanh(v2); v3 = ftanh(v3); }
                *(__half2*)&C[(size_t)r0    *ldc + cnp] = __floats2half2_rn(v0, v1);
                *(__half2*)&C[(size_t)(r0+8)*ldc + cnp] = __floats2half2_rn(v2, v3);
            }
        }
    }
}

// ==================== fused lin1 -> tanh -> lin2 (+ X3 build) ===============
__global__ void __launch_bounds__(256, 2) k_lin12(
    const __half* __restrict__ A,
    const __half* __restrict__ W1, const __half* __restrict__ W2,
    const float* __restrict__ b1, const float* __restrict__ b2,
    __half* __restrict__ TD, __half* __restrict__ X3,
    const int* __restrict__ q_data, const int* __restrict__ attempt_data,
    const int* __restrict__ hint_data, const int* __restrict__ hintTotal_data,
    const float* __restrict__ q_emb, const float* __restrict__ attempt_emb,
    const float* __restrict__ ht_emb)
{
    extern __shared__ uint32_t sm[];
    uint32_t* Xs = sm;             // 3*2048
    uint32_t* Bs = sm + 3*2048;    // 3*2048
    uint32_t* Us = sm + 6*2048;    // 128*USTR (padded, conflict-free)

    const int tid  = threadIdx.x;
    const int m0   = blockIdx.x * 128;
    const int lane = tid & 31, w = tid >> 5;
    const int g    = lane >> 2, c = lane & 3;
    const int wm0  = (w >> 2) * 64;
    const int wn0  = (w & 3) * 32;
    const int srow = tid >> 2;
    const int grp  = tid & 3;

    const uint32_t* Ag  = (const uint32_t*)A  + (size_t)(m0 + srow) * 64 + grp * 4;
    const uint32_t* W1g = (const uint32_t*)W1 + (size_t)srow * 64 + grp * 4;
    const uint32_t* W2g = (const uint32_t*)W2 + (size_t)srow * 64 + grp * 4;

    const uint32_t xsb = (uint32_t)__cvta_generic_to_shared(Xs) + (srow*16 + grp*4) * 4;
    const uint32_t bsb = (uint32_t)__cvta_generic_to_shared(Bs) + (srow*16 + grp*4) * 4;

    float acc[4][4][4];
    #pragma unroll
    for (int i = 0; i < 4; i++)
        #pragma unroll
        for (int j = 0; j < 4; j++)
            #pragma unroll
            for (int r = 0; r < 4; r++) acc[i][j][r] = 0.f;

    auto stage1 = [&](int ch, int s) {
        uint32_t xb = xsb + s * 2048 * 4;
        cpa16(xb,               Ag + ch * 16);
        cpa16(xb + 64*16*4,     Ag + (size_t)64*64 + ch * 16);
        uint32_t bb = bsb + s * 2048 * 4;
        cpa16(bb,               W1g + ch * 16);
        cpa16(bb + 64*16*4,     W1g + (size_t)64*64 + ch * 16);
        asm volatile("cp.async.commit_group;");
    };

    stage1(0, 0); stage1(1, 1);
    for (int ch = 0; ch < 4; ch++) {
        asm volatile("cp.async.wait_group 1;");
        __syncthreads();
        if (ch + 2 < 4) stage1(ch + 2, (ch + 2) % 3);
        else asm volatile("cp.async.commit_group;");
        const uint32_t* xs = Xs + (ch % 3) * 2048;
        const uint32_t* bs = Bs + (ch % 3) * 2048;
        uint4 alo[4], ahi[4];
        #pragma unroll
        for (int mi = 0; mi < 4; mi++) {
            alo[mi] = *(const uint4*)&xs[(wm0 + mi*16 + g)     * 16 + c*4];
            ahi[mi] = *(const uint4*)&xs[(wm0 + mi*16 + g + 8) * 16 + c*4];
        }
        #pragma unroll
        for (int ni = 0; ni < 4; ni++) {
            uint4 b = *(const uint4*)&bs[(wn0 + ni*8 + g) * 16 + c*4];
            #pragma unroll
            for (int mi = 0; mi < 4; mi++) {
                mma16(acc[mi][ni], alo[mi].x, ahi[mi].x, alo[mi].y, ahi[mi].y, b.x, b.y);
                mma16(acc[mi][ni], alo[mi].z, ahi[mi].z, alo[mi].w, ahi[mi].w, b.z, b.w);
            }
        }
    }
    asm volatile("cp.async.wait_group 0;");

    // U = tanh(acc + b1) -> padded smem, reset acc
    #pragma unroll
    for (int ni = 0; ni < 4; ni++) {
        int cn = wn0 + ni*8 + c*2;
        float bb0 = __ldg(&b1[cn]), bb1 = __ldg(&b1[cn+1]);
        int pw = permc(cn) >> 1;
        #pragma unroll
        for (int mi = 0; mi < 4; mi++) {
            int r0 = wm0 + mi*16 + g;
            __half2 h0 = __floats2half2_rn(ftanh(acc[mi][ni][0] + bb0), ftanh(acc[mi][ni][1] + bb1));
            __half2 h1 = __floats2half2_rn(ftanh(acc[mi][ni][2] + bb0), ftanh(acc[mi][ni][3] + bb1));
            Us[r0*USTR + pw]     = *(uint32_t*)&h0;
            Us[(r0+8)*USTR + pw] = *(uint32_t*)&h1;
            acc[mi][ni][0] = acc[mi][ni][1] = acc[mi][ni][2] = acc[mi][ni][3] = 0.f;
        }
    }
    __syncthreads();

    // GEMM2: A = Us (smem), B = W2 staged
    auto stage2 = [&](int ch, int s) {
        uint32_t bb = bsb + s * 2048 * 4;
        cpa16(bb,           W2g + ch * 16);
        cpa16(bb + 64*16*4, W2g + (size_t)64*64 + ch * 16);
        asm volatile("cp.async.commit_group;");
    };
    stage2(0, 0); stage2(1, 1);
    for (int ch = 0; ch < 4; ch++) {
        asm volatile("cp.async.wait_group 1;");
        __syncthreads();
        if (ch + 2 < 4) stage2(ch + 2, (ch + 2) % 3);
        else asm volatile("cp.async.commit_group;");
        const uint32_t* bs = Bs + (ch % 3) * 2048;
        uint4 alo[4], ahi[4];
        #pragma unroll
        for (int mi = 0; mi < 4; mi++) {
            alo[mi] = *(const uint4*)&Us[(wm0 + mi*16 + g)     * USTR + ch*16 + c*4];
            ahi[mi] = *(const uint4*)&Us[(wm0 + mi*16 + g + 8) * USTR + ch*16 + c*4];
        }
        #pragma unroll
        for (int ni = 0; ni < 4; ni++) {
            uint4 b = *(const uint4*)&bs[(wn0 + ni*8 + g) * 16 + c*4];
            #pragma unroll
            for (int mi = 0; mi < 4; mi++) {
                mma16(acc[mi][ni], alo[mi].x, ahi[mi].x, alo[mi].y, ahi[mi].y, b.x, b.y);
                mma16(acc[mi][ni], alo[mi].z, ahi[mi].z, alo[mi].w, ahi[mi].w, b.z, b.w);
            }
        }
    }

    // epilogue
    const bool isdiff = (m0 >= T_);
    #pragma unroll
    for (int mi = 0; mi < 4; mi++) {
        #pragma unroll
        for (int h = 0; h < 2; h++) {
            int r = wm0 + mi*16 + g + h*8;
            int t = m0 + r;
            if (!isdiff) {
                #pragma unroll
                for (int ni = 0; ni < 4; ni++) {
                    int cn = wn0 + ni*8 + c*2;
                    float v0 = fsig(acc[mi][ni][2*h]   + __ldg(&b2[cn]));
                    float v1 = fsig(acc[mi][ni][2*h+1] + __ldg(&b2[cn+1]));
                    *(__half2*)&TD[(size_t)t*DQ_ + cn] = __floats2half2_rn(v0, v1);
                }
            } else {
                int tt = t - T_;
                int qi = q_data[tt], ai = attempt_data[tt];
                int hi = hint_data[tt], hti = hintTotal_data[tt];
                #pragma unroll
                for (int ni = 0; ni < 4; ni++) {
                    int cn = wn0 + ni*8 + c*2;
                    float v0 = fsig(acc[mi][ni][2*h]   + __ldg(&b2[cn]));
                    float v1 = fsig(acc[mi][ni][2*h+1] + __ldg(&b2[cn+1]));
                    float qe0 = q_emb[(size_t)qi*DQ_ + cn],   qe1 = q_emb[(size_t)qi*DQ_ + cn+1];
                    float g0  = attempt_emb[(size_t)ai*DQ_ + cn]
                              + ht_emb[(size_t)hi*DQ_ + cn] + ht_emb[(size_t)hti*DQ_ + cn];
                    float g1  = attempt_emb[(size_t)ai*DQ_ + cn+1]
                              + ht_emb[(size_t)hi*DQ_ + cn+1] + ht_emb[(size_t)hti*DQ_ + cn+1];
                    *(__half2*)&X3[(size_t)tt*DQ_ + permc(cn)] =
                        __floats2half2_rn(fmaf(v0, g0, qe0), fmaf(v1, g1, qe1));
                }
            }
        }
    }
}

// ==================== fused q_proc -> input_embed + logits -> softmax =======
__global__ void __launch_bounds__(256, 2) k_qplog(
    const __half* __restrict__ A,
    const __half* __restrict__ W1,
    const __half* __restrict__ WM,
    const float* __restrict__ b1,
    const __half* __restrict__ TD,
    const int* __restrict__ time_data, const float* __restrict__ time_emb,
    __half* __restrict__ PredIn, float* __restrict__ logits)
{
    extern __shared__ uint32_t sm[];
    uint32_t* Xs  = sm;
    uint32_t* Bs  = sm + 3*2048;
    uint32_t* Us  = sm + 6*2048;                         // 128*USTR
    float*    red = (float*)(sm + 6*2048 + 128*USTR);    // 512 floats

    const int tid  = threadIdx.x;
    const int m0   = blockIdx.x * 128;
    const int lane = tid & 31, w = tid >> 5;
    const int g    = lane >> 2, c = lane & 3;
    const int wm0  = (w >> 2) * 64;
    const int wn0  = (w & 3) * 32;
    const int srow = tid >> 2;
    const int grp  = tid & 3;

    const uint32_t* Ag  = (const uint32_t*)A  + (size_t)(m0 + srow) * 64 + grp * 4;
    const uint32_t* W1g = (const uint32_t*)W1 + (size_t)srow * 64 + grp * 4;
    const uint32_t* WMg = (const uint32_t*)WM + (size_t)srow * 64 + grp * 4;

    const uint32_t xsb = (uint32_t)__cvta_generic_to_shared(Xs) + (srow*16 + grp*4) * 4;
    const uint32_t bsb = (uint32_t)__cvta_generic_to_shared(Bs) + (srow*16 + grp*4) * 4;

    float acc[4][4][4];
    #pragma unroll
    for (int i = 0; i < 4; i++)
        #pragma unroll
        for (int j = 0; j < 4; j++)
            #pragma unroll
            for (int r = 0; r < 4; r++) acc[i][j][r] = 0.f;

    auto stage1 = [&](int ch, int s) {
        uint32_t xb = xsb + s * 2048 * 4;
        cpa16(xb,           Ag + ch * 16);
        cpa16(xb + 64*16*4, Ag + (size_t)64*64 + ch * 16);
        uint32_t bb = bsb + s * 2048 * 4;
        cpa16(bb,           W1g + ch * 16);
        cpa16(bb + 64*16*4, W1g + (size_t)64*64 + ch * 16);
        asm volatile("cp.async.commit_group;");
    };
    stage1(0, 0); stage1(1, 1);
    for (int ch = 0; ch < 4; ch++) {
        asm volatile("cp.async.wait_group 1;");
        __syncthreads();
        if (ch + 2 < 4) stage1(ch + 2, (ch + 2) % 3);
        else asm volatile("cp.async.commit_group;");
        const uint32_t* xs = Xs + (ch % 3) * 2048;
        const uint32_t* bs = Bs + (ch % 3) * 2048;
        uint4 alo[4], ahi[4];
        #pragma unroll
        for (int mi = 0; mi < 4; mi++) {
            alo[mi] = *(const uint4*)&xs[(wm0 + mi*16 + g)     * 16 + c*4];
            ahi[mi] = *(const uint4*)&xs[(wm0 + mi*16 + g + 8) * 16 + c*4];
        }
        #pragma unroll
        for (int ni = 0; ni < 4; ni++) {
            uint4 b = *(const uint4*)&bs[(wn0 + ni*8 + g) * 16 + c*4];
            #pragma unroll
            for (int mi = 0; mi < 4; mi++) {
                mma16(acc[mi][ni], alo[mi].x, ahi[mi].x, alo[mi].y, ahi[mi].y, b.x, b.y);
                mma16(acc[mi][ni], alo[mi].z, ahi[mi].z, alo[mi].w, ahi[mi].w, b.z, b.w);
            }
        }
    }
    asm volatile("cp.async.wait_group 0;");

    // epilogue1: qp -> Us (padded); input_embed -> PredIn
    #pragma unroll
    for (int mi = 0; mi < 4; mi++) {
        #pragma unroll
        for (int h = 0; h < 2; h++) {
            int r = wm0 + mi*16 + g + h*8;
            int t = m0 + r;
            int ti = time_data[t];
            #pragma unroll
            for (int ni = 0; ni < 4; ni++) {
                int cn = wn0 + ni*8 + c*2;
                float q0 = acc[mi][ni][2*h]   + __ldg(&b1[cn]);
                float q1 = acc[mi][ni][2*h+1] + __ldg(&b1[cn+1]);
                __half2 hq = __floats2half2_rn(q0, q1);
                Us[r*USTR + (permc(cn) >> 1)] = *(uint32_t*)&hq;
                float2 qp2 = __half22float2(hq);
                __half2 tfh = *(const __half2*)&TD[(size_t)t*DQ_ + cn];
                float2 tf2 = __half22float2(tfh);
                float te0 = time_emb[(size_t)ti*DQ_ + cn], te1 = time_emb[(size_t)ti*DQ_ + cn+1];
                *(__half2*)&PredIn[(size_t)t*KRO_ + DV_ + permc(cn)] =
                    __floats2half2_rn(fmaf(tf2.x, te0, qp2.x), fmaf(tf2.y, te1, qp2.y));
                acc[mi][ni][2*h] = 0.f; acc[mi][ni][2*h+1] = 0.f;
            }
        }
    }
    __syncthreads();

    // GEMM2: logits = QP(Us) @ Mk128^T
    auto stage2 = [&](int ch, int s) {
        uint32_t bb = bsb + s * 2048 * 4;
        cpa16(bb,           WMg + ch * 16);
        cpa16(bb + 64*16*4, WMg + (size_t)64*64 + ch * 16);
        asm volatile("cp.async.commit_group;");
    };
    stage2(0, 0); stage2(1, 1);
    for (int ch = 0; ch < 4; ch++) {
        asm volatile("cp.async.wait_group 1;");
        __syncthreads();
        if (ch + 2 < 4) stage2(ch + 2, (ch + 2) % 3);
        else asm volatile("cp.async.commit_group;");
        const uint32_t* bs = Bs + (ch % 3) * 2048;
        uint4 alo[4], ahi[4];
        #pragma unroll
        for (int mi = 0; mi < 4; mi++) {
            alo[mi] = *(const uint4*)&Us[(wm0 + mi*16 + g)     * USTR + ch*16 + c*4];
            ahi[mi] = *(const uint4*)&Us[(wm0 + mi*16 + g + 8) * USTR + ch*16 + c*4];
        }
        #pragma unroll
        for (int ni = 0; ni < 4; ni++) {
            uint4 b = *(const uint4*)&bs[(wn0 + ni*8 + g) * 16 + c*4];
            #pragma unroll
            for (int mi = 0; mi < 4; mi++) {
                mma16(acc[mi][ni], alo[mi].x, ahi[mi].x, alo[mi].y, ahi[mi].y, b.x, b.y);
                mma16(acc[mi][ni], alo[mi].z, ahi[mi].z, alo[mi].w, ahi[mi].w, b.z, b.w);
            }
        }
    }

    // fused masked softmax over cols < M_
    float mx[4][2];
    #pragma unroll
    for (int mi = 0; mi < 4; mi++) { mx[mi][0] = -1e30f; mx[mi][1] = -1e30f; }
    #pragma unroll
    for (int ni = 0; ni < 4; ni++) {
        int cn = wn0 + ni*8 + c*2;
        bool ok0 = cn < M_, ok1 = (cn+1) < M_;
        #pragma unroll
        for (int mi = 0; mi < 4; mi++)
            #pragma unroll
            for (int h = 0; h < 2; h++) {
                if (ok0) mx[mi][h] = fmaxf(mx[mi][h], acc[mi][ni][2*h]);
                if (ok1) mx[mi][h] = fmaxf(mx[mi][h], acc[mi][ni][2*h+1]);
            }
    }
    #pragma unroll
    for (int mi = 0; mi < 4; mi++)
        #pragma unroll
        for (int h = 0; h < 2; h++) {
            mx[mi][h] = fmaxf(mx[mi][h], __shfl_xor_sync(0xffffffffu, mx[mi][h], 1));
            mx[mi][h] = fmaxf(mx[mi][h], __shfl_xor_sync(0xffffffffu, mx[mi][h], 2));
        }
    __syncthreads();
    if (c == 0) {
        #pragma unroll
        for (int mi = 0; mi < 4; mi++)
            #pragma unroll
            for (int h = 0; h < 2; h++)
                red[(w & 3) * 128 + wm0 + mi*16 + g + h*8] = mx[mi][h];
    }
    __syncthreads();
    float mxr[4][2];
    #pragma unroll
    for (int mi = 0; mi < 4; mi++)
        #pragma unroll
        for (int h = 0; h < 2; h++) {
            int r = wm0 + mi*16 + g + h*8;
            mxr[mi][h] = fmaxf(fmaxf(red[r], red[128 + r]), fmaxf(red[256 + r], red[384 + r]));
        }
    __syncthreads();
    float sum_[4][2];
    #pragma unroll
    for (int mi = 0; mi < 4; mi++) { sum_[mi][0] = 0.f; sum_[mi][1] = 0.f; }
    #pragma unroll
    for (int ni = 0; ni < 4; ni++) {
        int cn = wn0 + ni*8 + c*2;
        bool ok0 = cn < M_, ok1 = (cn+1) < M_;
        #pragma unroll
        for (int mi = 0; mi < 4; mi++)
            #pragma unroll
            for (int h = 0; h < 2; h++) {
                float e0 = ok0 ? __expf(acc[mi][ni][2*h]   - mxr[mi][h]) : 0.f;
                float e1 = ok1 ? __expf(acc[mi][ni][2*h+1] - mxr[mi][h]) : 0.f;
                acc[mi][ni][2*h] = e0; acc[mi][ni][2*h+1] = e1;
                sum_[mi][h] += e0 + e1;
            }
    }
    #pragma unroll
    for (int mi = 0; mi < 4; mi++)
        #pragma unroll
        for (int h = 0; h < 2; h++) {
            sum_[mi][h] += __shfl_xor_sync(0xffffffffu, sum_[mi][h], 1);
            sum_[mi][h] += __shfl_xor_sync(0xffffffffu, sum_[mi][h], 2);
        }
    if (c == 0) {
        #pragma unroll
        for (int mi = 0; mi < 4; mi++)
            #pragma unroll
            for (int h = 0; h < 2; h++)
                red[(w & 3) * 128 + wm0 + mi*16 + g + h*8] = sum_[mi][h];
    }
    __syncthreads();
    #pragma unroll
    for (int mi = 0; mi < 4; mi++) {
        #pragma unroll
        for (int h = 0; h < 2; h++) {
            int r = wm0 + mi*16 + g + h*8;
            float inv = 1.f / (red[r] + red[128 + r] + red[256 + r] + red[384 + r]);
            size_t t = m0 + r;
            #pragma unroll
            for (int ni = 0; ni < 4; ni++) {
                int cn = wn0 + ni*8 + c*2;
                if (cn < M_)   logits[t*LML_ + cn]   = acc[mi][ni][2*h]   * inv;
                if (cn+1 < M_) logits[t*LML_ + cn+1] = acc[mi][ni][2*h+1] * inv;
            }
        }
    }
}

// ==================== small kernels ====================
__global__ void k_prep(const float* __restrict__ eW, const float* __restrict__ eb,
                       const float* __restrict__ aW, const float* __restrict__ ab,
                       const float* __restrict__ d1W, const float* __restrict__ d2W,
                       const float* __restrict__ roW, const float* __restrict__ Mk)
{
    int i = blockIdx.x * blockDim.x + threadIdx.x;
    int stride = gridDim.x * blockDim.x;
    for (int j = i; j < NEA_*KEA_; j += stride) {
        int n = j / KEA_, k = j % KEA_;
        g_Wea[n*KEA_ + ph(k)] = __float2half((n < DV_) ? eW[n*KEA_ + k] : aW[(n - DV_)*KEA_ + k]);
    }
    for (int j = i; j < DQ_*DQ_; j += stride) {
        int n = j / DQ_, k = j % DQ_;
        g_Wd1[n*DQ_ + ph(k)] = __float2half(d1W[j]);
        g_Wd2[n*DQ_ + ph(k)] = __float2half(d2W[j]);
    }
    for (int j = i; j < F_*KRO_; j += stride) {
        int n = j / KRO_, k = j % KRO_;
        g_Wro[n*KRO_ + ph(k)] = __float2half(roW[j]);
    }
    for (int j = i; j < 128*DQ_; j += stride) {
        int n = j / DQ_, k = j % DQ_;
        g_Wmk[n*DQ_ + ph(k)] = __float2half(n < M_ ? Mk[n*DQ_ + k] : 0.f);
    }
    for (int j = i; j < NEA_; j += stride) g_bea[j] = (j < DV_) ? eb[j] : ab[j - DV_];
    for (int j = i; j < T_;  j += stride) g_predS[j] = 0.f;
    if (i < 2) g_accum[i] = 0.f;
}

__global__ void k_gather1(const int* __restrict__ q_data, const int* __restrict__ qa_data,
                          const int* __restrict__ time_data, const int* __restrict__ attempt_data,
                          const int* __restrict__ hint_data, const int* __restrict__ hintTotal_data,
                          const float* __restrict__ q_emb, const float* __restrict__ qa_emb,
                          const float* __restrict__ time_emb, const float* __restrict__ attempt_emb,
                          const float* __restrict__ ht_emb)
{
    int t = blockIdx.x, d = threadIdx.x;
    int pd = ph(d);
    int qi = q_data[t], ti = time_data[t], ai = attempt_data[t];
    int hi = hint_data[t], hti = hintTotal_data[t];
    float qe  = q_emb[(size_t)qi*DQ_ + d];
    float te  = time_emb[(size_t)ti*DQ_ + d];
    float ae  = attempt_emb[(size_t)ai*DQ_ + d];
    float he  = ht_emb[(size_t)hi*DQ_ + d];
    float hte = ht_emb[(size_t)hti*DQ_ + d];
    g_bufX[(size_t)t*DQ_ + pd]      = __float2half(te + qe);
    g_bufX[(size_t)(T_+t)*DQ_ + pd] = __float2half(he + hte + ae + qe);
    int qai = qa_data[t];
    g_bufQA[(size_t)t*DV_ + pd]          = __float2half(qa_emb[(size_t)qai*DV_ + d]);
    g_bufQA[(size_t)t*DV_ + ph(d + DQ_)] = __float2half(qa_emb[(size_t)qai*DV_ + DQ_ + d]);
}

// DV split 2-way -> 512 CTAs; PER-WARP ws copies, no block barriers
__global__ void __launch_bounds__(128) k_scan(const float* __restrict__ Mv0)
{
    int b = blockIdx.x;
    int tidw = threadIdx.x & 31;
    int wid  = threadIdx.x >> 5;
    int d = blockIdx.y * 128 + threadIdx.x;
    int pe = ph(d);
    int pa = ph(d + DV_);
    float mv[M_];
    #pragma unroll
    for (int m = 0; m < M_; m++) mv[m] = Mv0[m*DV_ + d];
    __shared__ float ws[4][2][64];
    size_t t0 = (size_t)b * S_;
    if (tidw < M_ - 32 || tidw < 32) {
        if (tidw < 32 && tidw < M_) ws[wid][0][tidw] = g_logits[t0*LML_ + tidw];
        if (tidw + 32 < M_)         ws[wid][0][tidw + 32] = g_logits[t0*LML_ + tidw + 32];
    }
    float e = __half2float(g_bufEA[t0*NEA_ + pe]);
    float a = __half2float(g_bufEA[t0*NEA_ + pa]);
    __syncwarp();
    for (int s = 0; s < S_; s++) {
        size_t t = t0 + s;
        float en = 0.f, an = 0.f;
        if (s + 1 < S_) {
            en = __half2float(g_bufEA[(t+1)*NEA_ + pe]);
            an = __half2float(g_bufEA[(t+1)*NEA_ + pa]);
            int nb = (s+1) & 1;
            if (tidw < M_)      ws[wid][nb][tidw]      = g_logits[(t+1)*LML_ + tidw];
            if (tidw + 32 < M_) ws[wid][nb][tidw + 32] = g_logits[(t+1)*LML_ + tidw + 32];
        }
        const float* wcur = ws[wid][s & 1];
        float rd0 = 0.f, rd1 = 0.f;
        #pragma unroll
        for (int m = 0; m < M_; m += 2) {
            float w0 = wcur[m], w1 = wcur[m+1];
            rd0 = fmaf(w0, mv[m],   rd0);
            rd1 = fmaf(w1, mv[m+1], rd1);
            mv[m]   = fmaf(mv[m],   fmaf(-w0, e, 1.f), w0 * a);
            mv[m+1] = fmaf(mv[m+1], fmaf(-w1, e, 1.f), w1 * a);
        }
        g_PredIn[t*KRO_ + pe] = __float2half(rd0 + rd1);
        __syncwarp();
        e = en; a = an;
    }
}

__global__ void k_loss(const int* __restrict__ target, const float* __restrict__ pred_b,
                       float* __restrict__ out)
{
    int i = blockIdx.x * blockDim.x + threadIdx.x;
    float le = 0.f, cnt = 0.f;
    if (i < T_) {
        float p = g_predS[i] + pred_b[0];
        int tg = target[i];
        bool mask = tg >= 1;
        float y = mask ? (float)(tg - 1) : 0.f;
        float sig = 1.f / (1.f + expf(-p));
        out[1 + i]      = mask ? sig : 0.f;
        out[1 + T_ + i] = mask ? y   : 0.f;
        if (mask) {
            le = fmaxf(p, 0.f) + log1pf(expf(-fabsf(p))) - p * y;
            cnt = 1.f;
        }
    }
    __shared__ float sle[256], scn[256];
    sle[threadIdx.x] = le; scn[threadIdx.x] = cnt;
    __syncthreads();
    for (int o = 128; o; o >>= 1) {
        if (threadIdx.x < o) { sle[threadIdx.x] += sle[threadIdx.x + o]; scn[threadIdx.x] += scn[threadIdx.x + o]; }
        __syncthreads();
    }
    if (threadIdx.x == 0) { atomicAdd(&g_accum[0], sle[0]); atomicAdd(&g_accum[1], scn[0]); }
}

__global__ void k_final(float* __restrict__ out)
{
    out[0] = g_accum[0] / fmaxf(g_accum[1], 1.f);
}

// ==================== host ====================
extern "C" void kernel_launch(void* const* d_in, const int* in_sizes, int n_in,
                              void* d_out, int out_size)
{
    const int*   q_data      = (const int*)  d_in[0];
    const int*   qa_data     = (const int*)  d_in[1];
    const int*   target      = (const int*)  d_in[2];
    const int*   time_data   = (const int*)  d_in[3];
    const int*   attempt_data= (const int*)  d_in[4];
    const int*   hint_data   = (const int*)  d_in[5];
    const int*   hintTotal   = (const int*)  d_in[6];
    const float* q_emb       = (const float*)d_in[7];
    const float* qa_emb      = (const float*)d_in[8];
    const float* time_emb    = (const float*)d_in[9];
    const float* attempt_emb = (const float*)d_in[10];
    const float* ht_emb      = (const float*)d_in[11];
    const float* Mk          = (const float*)d_in[12];
    const float* Mv0         = (const float*)d_in[13];
    const float* diff_W      = (const float*)d_in[14];
    const float* diff_b      = (const float*)d_in[15];
    const float* diff2_W     = (const float*)d_in[16];
    const float* diff2_b     = (const float*)d_in[17];
    const float* erase_W     = (const float*)d_in[18];
    const float* erase_b     = (const float*)d_in[19];
    const float* add_W       = (const float*)d_in[20];
    const float* add_b       = (const float*)d_in[21];
    const float* read_W      = (const float*)d_in[22];
    const float* read_b      = (const float*)d_in[23];
    const float* pred_W      = (const float*)d_in[24];
    const float* pred_b      = (const float*)d_in[25];
    float* out = (float*)d_out;

    __half *bufX, *bufX3, *bufTD, *bufQA, *bufEA, *predin;
    __half *Wea, *Wd1, *Wd2, *Wro, *Wmk;
    float *logits, *predS, *bea;
    cudaGetSymbolAddress((void**)&bufX,   g_bufX);
    cudaGetSymbolAddress((void**)&bufX3,  g_bufX3);
    cudaGetSymbolAddress((void**)&bufTD,  g_bufTD);
    cudaGetSymbolAddress((void**)&bufQA,  g_bufQA);
    cudaGetSymbolAddress((void**)&bufEA,  g_bufEA);
    cudaGetSymbolAddress((void**)&predin, g_PredIn);
    cudaGetSymbolAddress((void**)&logits, g_logits);
    cudaGetSymbolAddress((void**)&predS,  g_predS);
    cudaGetSymbolAddress((void**)&Wea,    g_Wea);
    cudaGetSymbolAddress((void**)&Wd1,    g_Wd1);
    cudaGetSymbolAddress((void**)&Wd2,    g_Wd2);
    cudaGetSymbolAddress((void**)&Wro,    g_Wro);
    cudaGetSymbolAddress((void**)&Wmk,    g_Wmk);
    cudaGetSymbolAddress((void**)&bea,    g_bea);

    const int SMG = (6*2048 + 128) * 4;                    // 49664
    const int SML = (6*2048 + 128*USTR) * 4;               // 90112
    const int SMQ = (6*2048 + 128*USTR + 512) * 4;         // 92160
    cudaFuncSetAttribute(k_mma<3>, cudaFuncAttributeMaxDynamicSharedMemorySize, SMG);
    cudaFuncSetAttribute(k_mma<4>, cudaFuncAttributeMaxDynamicSharedMemorySize, SMG);
    cudaFuncSetAttribute(k_lin12,  cudaFuncAttributeMaxDynamicSharedMemorySize, SML);
    cudaFuncSetAttribute(k_qplog,  cudaFuncAttributeMaxDynamicSharedMemorySize, SMQ);

    k_prep<<<1024, 256>>>(erase_W, erase_b, add_W, add_b, diff_W, diff2_W, read_W, Mk);
    k_gather1<<<T_, 128>>>(q_data, qa_data, time_data, attempt_data, hint_data, hintTotal,
                           q_emb, qa_emb, time_emb, attempt_emb, ht_emb);
    k_lin12<<<2*T_/128, 256, SML>>>(bufX, Wd1, Wd2, diff_b, diff2_b, bufTD, bufX3,
                                    q_data, attempt_data, hint_data, hintTotal,
                                    q_emb, attempt_emb, ht_emb);
    k_qplog<<<T_/128, 256, SMQ>>>(bufX3, Wd1, Wmk, diff_b, bufTD,
                                  time_data, time_emb, predin, logits);
    k_mma<3><<<dim3(4, T_/128), 256, SMG>>>(bufQA, KEA_, KEA_, Wea, bea, bufEA, NEA_, nullptr, nullptr);
    k_scan<<<dim3(B_, 2), 128>>>(Mv0);
    k_mma<4><<<dim3(4, T_/128), 256, SMG>>>(predin, KRO_, KRO_, Wro, read_b, nullptr, 0, pred_W, predS);
    k_loss<<<(T_ + 255)/256, 256>>>(target, pred_b, out);
    k_final<<<1, 1>>>(out);
}

// round 11
// speedup vs baseline: 3.8641x; 1.0022x over previous
#include <cuda_runtime.h>
#include <cuda_fp16.h>
#include <math.h>
#include <stdint.h>

#define B_   256
#define S_   500
#define T_   (B_*S_)        // 128000
#define DQ_  128
#define DV_  256
#define M_   50
#define F_   512
#define NEA_ 512
#define KEA_ 256
#define KRO_ 384            // DV + DQ
#define LML_ 64             // padded logits row stride
#define USTR 80             // padded Us row stride (words)

// ---------------- scratch (device globals; no allocations) ----------------
__device__ __half g_bufX [2*T_*DQ_];    // permuted
__device__ __half g_bufX3[T_*DQ_];      // permuted
__device__ __half g_bufTD[T_*DQ_];      // plain
__device__ __half g_bufQA[T_*DV_];      // permuted
__device__ __half g_bufEA[T_*NEA_];     // permuted
__device__ __half g_PredIn[T_*KRO_];    // permuted
__device__ float  g_logits[T_*LML_];
__device__ float  g_predP[4][T_];       // per-n-block partial pred sums
__device__ float  g_accum[2];
__device__ __half g_Wea[NEA_*KEA_];
__device__ __half g_Wd1[DQ_*DQ_];
__device__ __half g_Wd2[DQ_*DQ_];
__device__ __half g_Wro[F_*KRO_];
__device__ __half g_Wmk[128*DQ_];
__device__ float  g_bea[NEA_];

// ==================== helpers ====================
__device__ __forceinline__ int ph(int d) {
    int pair = d >> 1;
    int pi   = pair & 15;
    int pp   = (pair & ~15) | ((pi & 3) * 4 + (pi >> 2));
    return pp * 2 + (d & 1);
}
__device__ __forceinline__ int permc(int cn) {
    int pair = cn >> 1;
    int pi   = pair & 15;
    int pp   = (pair & ~15) | ((pi & 3) * 4 + (pi >> 2));
    return pp * 2;
}
__device__ __forceinline__ float fsig(float x) { return 1.f / (1.f + __expf(-x)); }
__device__ __forceinline__ float ftanh(float x) {
    float ax = fabsf(x);
    float t  = 1.f - 2.f / (1.f + __expf(2.f * ax));
    return copysignf(t, x);
}
__device__ __forceinline__ void mma16(float* d,
    uint32_t a0, uint32_t a1, uint32_t a2, uint32_t a3,
    uint32_t b0, uint32_t b1)
{
    asm volatile(
        "mma.sync.aligned.m16n8k16.row.col.f32.f16.f16.f32 "
        "{%0,%1,%2,%3},{%4,%5,%6,%7},{%8,%9},{%0,%1,%2,%3};"
        : "+f"(d[0]), "+f"(d[1]), "+f"(d[2]), "+f"(d[3])
        : "r"(a0), "r"(a1), "r"(a2), "r"(a3), "r"(b0), "r"(b1));
}
__device__ __forceinline__ void cpa16(uint32_t dst, const void* src) {
    asm volatile("cp.async.cg.shared.global [%0], [%1], 16;" :: "r"(dst), "l"(src));
}

// ==================== generic f16 tensor GEMM (EA / readout) ================
// Compile-time K -> fully unrolled mainloop, immediate stage offsets.
// ACT: 3=EA-split(perm store)  4=readout + fused pred dot (partial buffers)
template<int ACT, int K>
__global__ void __launch_bounds__(256, 2) k_mma(
    const __half* __restrict__ A,
    const __half* __restrict__ W,
    const float* __restrict__ bias,
    void* __restrict__ Cv, int ldc,
    const float* __restrict__ predW, float* __restrict__ predP)
{
    constexpr int NCH  = K >> 5;
    constexpr int LDP  = K >> 1;     // uint32 words per row

    extern __shared__ uint32_t sm[];
    uint32_t* As   = sm;
    uint32_t* Bs   = sm + 3 * 2048;
    float*    sred = (float*)(sm + 6 * 2048);

    const int tid  = threadIdx.x;
    const int m0   = blockIdx.y * 128;
    const int n0   = blockIdx.x * 128;
    const int lane = tid & 31, w = tid >> 5;
    const int g    = lane >> 2, c = lane & 3;
    const int wm0  = (w >> 2) * 64;
    const int wn0  = (w & 3) * 32;
    const int srow = tid >> 2;
    const int grp  = tid & 3;

    const uint32_t* Ag = (const uint32_t*)A + (size_t)(m0 + srow) * LDP + grp * 4;
    const uint32_t* Wg = (const uint32_t*)W + (size_t)(n0 + srow) * LDP + grp * 4;

    const uint32_t asb = (uint32_t)__cvta_generic_to_shared(As) + (srow * 16 + grp * 4) * 4;
    const uint32_t bsb = (uint32_t)__cvta_generic_to_shared(Bs) + (srow * 16 + grp * 4) * 4;

    float acc[4][4][4];
    #pragma unroll
    for (int i = 0; i < 4; i++)
        #pragma unroll
        for (int j = 0; j < 4; j++)
            #pragma unroll
            for (int r = 0; r < 4; r++) acc[i][j][r] = 0.f;

    auto stage = [&](int ch, int s) {
        uint32_t ab = asb + s * 2048 * 4;
        cpa16(ab,                Ag + ch * 16);
        cpa16(ab + 64 * 16 * 4,  Ag + (size_t)64 * LDP + ch * 16);
        uint32_t bb = bsb + s * 2048 * 4;
        cpa16(bb,                Wg + ch * 16);
        cpa16(bb + 64 * 16 * 4,  Wg + (size_t)64 * LDP + ch * 16);
        asm volatile("cp.async.commit_group;");
    };

    stage(0, 0);
    stage(1, 1);

    #pragma unroll
    for (int ch = 0; ch < NCH; ch++) {
        asm volatile("cp.async.wait_group 1;");
        __syncthreads();
        if (ch + 2 < NCH) stage(ch + 2, (ch + 2) % 3);
        else asm volatile("cp.async.commit_group;");

        const uint32_t* as = As + (ch % 3) * 2048;
        const uint32_t* bs = Bs + (ch % 3) * 2048;
        uint4 alo[4], ahi[4];
        #pragma unroll
        for (int mi = 0; mi < 4; mi++) {
            alo[mi] = *(const uint4*)&as[(wm0 + mi*16 + g)     * 16 + c*4];
            ahi[mi] = *(const uint4*)&as[(wm0 + mi*16 + g + 8) * 16 + c*4];
        }
        #pragma unroll
        for (int ni = 0; ni < 4; ni++) {
            uint4 b = *(const uint4*)&bs[(wn0 + ni*8 + g) * 16 + c*4];
            #pragma unroll
            for (int mi = 0; mi < 4; mi++) {
                mma16(acc[mi][ni], alo[mi].x, ahi[mi].x, alo[mi].y, ahi[mi].y, b.x, b.y);
                mma16(acc[mi][ni], alo[mi].z, ahi[mi].z, alo[mi].w, ahi[mi].w, b.z, b.w);
            }
        }
    }

    if (ACT == 4) {
        float rsum[4][2];
        #pragma unroll
        for (int mi = 0; mi < 4; mi++) { rsum[mi][0] = 0.f; rsum[mi][1] = 0.f; }
        #pragma unroll
        for (int ni = 0; ni < 4; ni++) {
            int cn = n0 + wn0 + ni*8 + c*2;
            float b0 = __ldg(&bias[cn]),  b1 = __ldg(&bias[cn+1]);
            float p0 = __ldg(&predW[cn]), p1 = __ldg(&predW[cn+1]);
            #pragma unroll
            for (int mi = 0; mi < 4; mi++) {
                rsum[mi][0] += ftanh(acc[mi][ni][0] + b0) * p0 + ftanh(acc[mi][ni][1] + b1) * p1;
                rsum[mi][1] += ftanh(acc[mi][ni][2] + b0) * p0 + ftanh(acc[mi][ni][3] + b1) * p1;
            }
        }
        __syncthreads();
        if (tid < 128) sred[tid] = 0.f;
        __syncthreads();
        #pragma unroll
        for (int mi = 0; mi < 4; mi++)
            #pragma unroll
            for (int h = 0; h < 2; h++) {
                float v = rsum[mi][h];
                v += __shfl_xor_sync(0xffffffffu, v, 1);
                v += __shfl_xor_sync(0xffffffffu, v, 2);
                if (c == 0) atomicAdd(&sred[wm0 + mi*16 + h*8 + g], v);
            }
        __syncthreads();
        if (tid < 128) predP[(size_t)blockIdx.x * T_ + m0 + tid] = sred[tid];
    } else {
        __half* C = (__half*)Cv;
        #pragma unroll
        for (int ni = 0; ni < 4; ni++) {
            int cn  = n0 + wn0 + ni*8 + c*2;
            int cnp = permc(cn);
            float b0 = __ldg(&bias[cn]), b1 = __ldg(&bias[cn+1]);
            #pragma unroll
            for (int mi = 0; mi < 4; mi++) {
                int r0 = m0 + wm0 + mi*16 + g;
                float v0 = acc[mi][ni][0] + b0, v1 = acc[mi][ni][1] + b1;
                float v2 = acc[mi][ni][2] + b0, v3 = acc[mi][ni][3] + b1;
                if (cn < DV_) { v0 = fsig(v0); v1 = fsig(v1); v2 = fsig(v2); v3 = fsig(v3); }
                else          { v0 = ftanh(v0); v1 = ftanh(v1); v2 = ftanh(v2); v3 = ftanh(v3); }
                *(__half2*)&C[(size_t)r0    *ldc + cnp] = __floats2half2_rn(v0, v1);
                *(__half2*)&C[(size_t)(r0+8)*ldc + cnp] = __floats2half2_rn(v2, v3);
            }
        }
    }
}

// ==================== fused lin1 -> tanh -> lin2 (+ X3 build) ===============
__global__ void __launch_bounds__(256, 2) k_lin12(
    const __half* __restrict__ A,
    const __half* __restrict__ W1, const __half* __restrict__ W2,
    const float* __restrict__ b1, const float* __restrict__ b2,
    __half* __restrict__ TD, __half* __restrict__ X3,
    const int* __restrict__ q_data, const int* __restrict__ attempt_data,
    const int* __restrict__ hint_data, const int* __restrict__ hintTotal_data,
    const float* __restrict__ q_emb, const float* __restrict__ attempt_emb,
    const float* __restrict__ ht_emb)
{
    extern __shared__ uint32_t sm[];
    uint32_t* Xs = sm;
    uint32_t* Bs = sm + 3*2048;
    uint32_t* Us = sm + 6*2048;

    const int tid  = threadIdx.x;
    const int m0   = blockIdx.x * 128;
    const int lane = tid & 31, w = tid >> 5;
    const int g    = lane >> 2, c = lane & 3;
    const int wm0  = (w >> 2) * 64;
    const int wn0  = (w & 3) * 32;
    const int srow = tid >> 2;
    const int grp  = tid & 3;

    const uint32_t* Ag  = (const uint32_t*)A  + (size_t)(m0 + srow) * 64 + grp * 4;
    const uint32_t* W1g = (const uint32_t*)W1 + (size_t)srow * 64 + grp * 4;
    const uint32_t* W2g = (const uint32_t*)W2 + (size_t)srow * 64 + grp * 4;

    const uint32_t xsb = (uint32_t)__cvta_generic_to_shared(Xs) + (srow*16 + grp*4) * 4;
    const uint32_t bsb = (uint32_t)__cvta_generic_to_shared(Bs) + (srow*16 + grp*4) * 4;

    float acc[4][4][4];
    #pragma unroll
    for (int i = 0; i < 4; i++)
        #pragma unroll
        for (int j = 0; j < 4; j++)
            #pragma unroll
            for (int r = 0; r < 4; r++) acc[i][j][r] = 0.f;

    auto stage1 = [&](int ch, int s) {
        uint32_t xb = xsb + s * 2048 * 4;
        cpa16(xb,               Ag + ch * 16);
        cpa16(xb + 64*16*4,     Ag + (size_t)64*64 + ch * 16);
        uint32_t bb = bsb + s * 2048 * 4;
        cpa16(bb,               W1g + ch * 16);
        cpa16(bb + 64*16*4,     W1g + (size_t)64*64 + ch * 16);
        asm volatile("cp.async.commit_group;");
    };

    stage1(0, 0); stage1(1, 1);
    #pragma unroll
    for (int ch = 0; ch < 4; ch++) {
        asm volatile("cp.async.wait_group 1;");
        __syncthreads();
        if (ch + 2 < 4) stage1(ch + 2, (ch + 2) % 3);
        else asm volatile("cp.async.commit_group;");
        const uint32_t* xs = Xs + (ch % 3) * 2048;
        const uint32_t* bs = Bs + (ch % 3) * 2048;
        uint4 alo[4], ahi[4];
        #pragma unroll
        for (int mi = 0; mi < 4; mi++) {
            alo[mi] = *(const uint4*)&xs[(wm0 + mi*16 + g)     * 16 + c*4];
            ahi[mi] = *(const uint4*)&xs[(wm0 + mi*16 + g + 8) * 16 + c*4];
        }
        #pragma unroll
        for (int ni = 0; ni < 4; ni++) {
            uint4 b = *(const uint4*)&bs[(wn0 + ni*8 + g) * 16 + c*4];
            #pragma unroll
            for (int mi = 0; mi < 4; mi++) {
                mma16(acc[mi][ni], alo[mi].x, ahi[mi].x, alo[mi].y, ahi[mi].y, b.x, b.y);
                mma16(acc[mi][ni], alo[mi].z, ahi[mi].z, alo[mi].w, ahi[mi].w, b.z, b.w);
            }
        }
    }
    asm volatile("cp.async.wait_group 0;");

    #pragma unroll
    for (int ni = 0; ni < 4; ni++) {
        int cn = wn0 + ni*8 + c*2;
        float bb0 = __ldg(&b1[cn]), bb1 = __ldg(&b1[cn+1]);
        int pw = permc(cn) >> 1;
        #pragma unroll
        for (int mi = 0; mi < 4; mi++) {
            int r0 = wm0 + mi*16 + g;
            __half2 h0 = __floats2half2_rn(ftanh(acc[mi][ni][0] + bb0), ftanh(acc[mi][ni][1] + bb1));
            __half2 h1 = __floats2half2_rn(ftanh(acc[mi][ni][2] + bb0), ftanh(acc[mi][ni][3] + bb1));
            Us[r0*USTR + pw]     = *(uint32_t*)&h0;
            Us[(r0+8)*USTR + pw] = *(uint32_t*)&h1;
            acc[mi][ni][0] = acc[mi][ni][1] = acc[mi][ni][2] = acc[mi][ni][3] = 0.f;
        }
    }
    __syncthreads();

    auto stage2 = [&](int ch, int s) {
        uint32_t bb = bsb + s * 2048 * 4;
        cpa16(bb,           W2g + ch * 16);
        cpa16(bb + 64*16*4, W2g + (size_t)64*64 + ch * 16);
        asm volatile("cp.async.commit_group;");
    };
    stage2(0, 0); stage2(1, 1);
    #pragma unroll
    for (int ch = 0; ch < 4; ch++) {
        asm volatile("cp.async.wait_group 1;");
        __syncthreads();
        if (ch + 2 < 4) stage2(ch + 2, (ch + 2) % 3);
        else asm volatile("cp.async.commit_group;");
        const uint32_t* bs = Bs + (ch % 3) * 2048;
        uint4 alo[4], ahi[4];
        #pragma unroll
        for (int mi = 0; mi < 4; mi++) {
            alo[mi] = *(const uint4*)&Us[(wm0 + mi*16 + g)     * USTR + ch*16 + c*4];
            ahi[mi] = *(const uint4*)&Us[(wm0 + mi*16 + g + 8) * USTR + ch*16 + c*4];
        }
        #pragma unroll
        for (int ni = 0; ni < 4; ni++) {
            uint4 b = *(const uint4*)&bs[(wn0 + ni*8 + g) * 16 + c*4];
            #pragma unroll
            for (int mi = 0; mi < 4; mi++) {
                mma16(acc[mi][ni], alo[mi].x, ahi[mi].x, alo[mi].y, ahi[mi].y, b.x, b.y);
                mma16(acc[mi][ni], alo[mi].z, ahi[mi].z, alo[mi].w, ahi[mi].w, b.z, b.w);
            }
        }
    }

    const bool isdiff = (m0 >= T_);
    #pragma unroll
    for (int mi = 0; mi < 4; mi++) {
        #pragma unroll
        for (int h = 0; h < 2; h++) {
            int r = wm0 + mi*16 + g + h*8;
            int t = m0 + r;
            if (!isdiff) {
                #pragma unroll
                for (int ni = 0; ni < 4; ni++) {
                    int cn = wn0 + ni*8 + c*2;
                    float v0 = fsig(acc[mi][ni][2*h]   + __ldg(&b2[cn]));
                    float v1 = fsig(acc[mi][ni][2*h+1] + __ldg(&b2[cn+1]));
                    *(__half2*)&TD[(size_t)t*DQ_ + cn] = __floats2half2_rn(v0, v1);
                }
            } else {
                int tt = t - T_;
                int qi = q_data[tt], ai = attempt_data[tt];
                int hi = hint_data[tt], hti = hintTotal_data[tt];
                #pragma unroll
                for (int ni = 0; ni < 4; ni++) {
                    int cn = wn0 + ni*8 + c*2;
                    float v0 = fsig(acc[mi][ni][2*h]   + __ldg(&b2[cn]));
                    float v1 = fsig(acc[mi][ni][2*h+1] + __ldg(&b2[cn+1]));
                    float qe0 = q_emb[(size_t)qi*DQ_ + cn],   qe1 = q_emb[(size_t)qi*DQ_ + cn+1];
                    float g0  = attempt_emb[(size_t)ai*DQ_ + cn]
                              + ht_emb[(size_t)hi*DQ_ + cn] + ht_emb[(size_t)hti*DQ_ + cn];
                    float g1  = attempt_emb[(size_t)ai*DQ_ + cn+1]
                              + ht_emb[(size_t)hi*DQ_ + cn+1] + ht_emb[(size_t)hti*DQ_ + cn+1];
                    *(__half2*)&X3[(size_t)tt*DQ_ + permc(cn)] =
                        __floats2half2_rn(fmaf(v0, g0, qe0), fmaf(v1, g1, qe1));
                }
            }
        }
    }
}

// ==================== fused q_proc -> input_embed + logits -> softmax =======
__global__ void __launch_bounds__(256, 2) k_qplog(
    const __half* __restrict__ A,
    const __half* __restrict__ W1,
    const __half* __restrict__ WM,
    const float* __restrict__ b1,
    const __half* __restrict__ TD,
    const int* __restrict__ time_data, const float* __restrict__ time_emb,
    __half* __restrict__ PredIn, float* __restrict__ logits)
{
    extern __shared__ uint32_t sm[];
    uint32_t* Xs  = sm;
    uint32_t* Bs  = sm + 3*2048;
    uint32_t* Us  = sm + 6*2048;
    float*    red = (float*)(sm + 6*2048 + 128*USTR);

    const int tid  = threadIdx.x;
    const int m0   = blockIdx.x * 128;
    const int lane = tid & 31, w = tid >> 5;
    const int g    = lane >> 2, c = lane & 3;
    const int wm0  = (w >> 2) * 64;
    const int wn0  = (w & 3) * 32;
    const int srow = tid >> 2;
    const int grp  = tid & 3;

    const uint32_t* Ag  = (const uint32_t*)A  + (size_t)(m0 + srow) * 64 + grp * 4;
    const uint32_t* W1g = (const uint32_t*)W1 + (size_t)srow * 64 + grp * 4;
    const uint32_t* WMg = (const uint32_t*)WM + (size_t)srow * 64 + grp * 4;

    const uint32_t xsb = (uint32_t)__cvta_generic_to_shared(Xs) + (srow*16 + grp*4) * 4;
    const uint32_t bsb = (uint32_t)__cvta_generic_to_shared(Bs) + (srow*16 + grp*4) * 4;

    float acc[4][4][4];
    #pragma unroll
    for (int i = 0; i < 4; i++)
        #pragma unroll
        for (int j = 0; j < 4; j++)
            #pragma unroll
            for (int r = 0; r < 4; r++) acc[i][j][r] = 0.f;

    auto stage1 = [&](int ch, int s) {
        uint32_t xb = xsb + s * 2048 * 4;
        cpa16(xb,           Ag + ch * 16);
        cpa16(xb + 64*16*4, Ag + (size_t)64*64 + ch * 16);
        uint32_t bb = bsb + s * 2048 * 4;
        cpa16(bb,           W1g + ch * 16);
        cpa16(bb + 64*16*4, W1g + (size_t)64*64 + ch * 16);
        asm volatile("cp.async.commit_group;");
    };
    stage1(0, 0); stage1(1, 1);
    #pragma unroll
    for (int ch = 0; ch < 4; ch++) {
        asm volatile("cp.async.wait_group 1;");
        __syncthreads();
        if (ch + 2 < 4) stage1(ch + 2, (ch + 2) % 3);
        else asm volatile("cp.async.commit_group;");
        const uint32_t* xs = Xs + (ch % 3) * 2048;
        const uint32_t* bs = Bs + (ch % 3) * 2048;
        uint4 alo[4], ahi[4];
        #pragma unroll
        for (int mi = 0; mi < 4; mi++) {
            alo[mi] = *(const uint4*)&xs[(wm0 + mi*16 + g)     * 16 + c*4];
            ahi[mi] = *(const uint4*)&xs[(wm0 + mi*16 + g + 8) * 16 + c*4];
        }
        #pragma unroll
        for (int ni = 0; ni < 4; ni++) {
            uint4 b = *(const uint4*)&bs[(wn0 + ni*8 + g) * 16 + c*4];
            #pragma unroll
            for (int mi = 0; mi < 4; mi++) {
                mma16(acc[mi][ni], alo[mi].x, ahi[mi].x, alo[mi].y, ahi[mi].y, b.x, b.y);
                mma16(acc[mi][ni], alo[mi].z, ahi[mi].z, alo[mi].w, ahi[mi].w, b.z, b.w);
            }
        }
    }
    asm volatile("cp.async.wait_group 0;");

    #pragma unroll
    for (int mi = 0; mi < 4; mi++) {
        #pragma unroll
        for (int h = 0; h < 2; h++) {
            int r = wm0 + mi*16 + g + h*8;
            int t = m0 + r;
            int ti = time_data[t];
            #pragma unroll
            for (int ni = 0; ni < 4; ni++) {
                int cn = wn0 + ni*8 + c*2;
                float q0 = acc[mi][ni][2*h]   + __ldg(&b1[cn]);
                float q1 = acc[mi][ni][2*h+1] + __ldg(&b1[cn+1]);
                __half2 hq = __floats2half2_rn(q0, q1);
                Us[r*USTR + (permc(cn) >> 1)] = *(uint32_t*)&hq;
                float2 qp2 = __half22float2(hq);
                __half2 tfh = *(const __half2*)&TD[(size_t)t*DQ_ + cn];
                float2 tf2 = __half22float2(tfh);
                float te0 = time_emb[(size_t)ti*DQ_ + cn], te1 = time_emb[(size_t)ti*DQ_ + cn+1];
                *(__half2*)&PredIn[(size_t)t*KRO_ + DV_ + permc(cn)] =
                    __floats2half2_rn(fmaf(tf2.x, te0, qp2.x), fmaf(tf2.y, te1, qp2.y));
                acc[mi][ni][2*h] = 0.f; acc[mi][ni][2*h+1] = 0.f;
            }
        }
    }
    __syncthreads();

    auto stage2 = [&](int ch, int s) {
        uint32_t bb = bsb + s * 2048 * 4;
        cpa16(bb,           WMg + ch * 16);
        cpa16(bb + 64*16*4, WMg + (size_t)64*64 + ch * 16);
        asm volatile("cp.async.commit_group;");
    };
    stage2(0, 0); stage2(1, 1);
    #pragma unroll
    for (int ch = 0; ch < 4; ch++) {
        asm volatile("cp.async.wait_group 1;");
        __syncthreads();
        if (ch + 2 < 4) stage2(ch + 2, (ch + 2) % 3);
        else asm volatile("cp.async.commit_group;");
        const uint32_t* bs = Bs + (ch % 3) * 2048;
        uint4 alo[4], ahi[4];
        #pragma unroll
        for (int mi = 0; mi < 4; mi++) {
            alo[mi] = *(const uint4*)&Us[(wm0 + mi*16 + g)     * USTR + ch*16 + c*4];
            ahi[mi] = *(const uint4*)&Us[(wm0 + mi*16 + g + 8) * USTR + ch*16 + c*4];
        }
        #pragma unroll
        for (int ni = 0; ni < 4; ni++) {
            uint4 b = *(const uint4*)&bs[(wn0 + ni*8 + g) * 16 + c*4];
            #pragma unroll
            for (int mi = 0; mi < 4; mi++) {
                mma16(acc[mi][ni], alo[mi].x, ahi[mi].x, alo[mi].y, ahi[mi].y, b.x, b.y);
                mma16(acc[mi][ni], alo[mi].z, ahi[mi].z, alo[mi].w, ahi[mi].w, b.z, b.w);
            }
        }
    }

    // fused masked softmax over cols < M_
    float mx[4][2];
    #pragma unroll
    for (int mi = 0; mi < 4; mi++) { mx[mi][0] = -1e30f; mx[mi][1] = -1e30f; }
    #pragma unroll
    for (int ni = 0; ni < 4; ni++) {
        int cn = wn0 + ni*8 + c*2;
        bool ok0 = cn < M_, ok1 = (cn+1) < M_;
        #pragma unroll
        for (int mi = 0; mi < 4; mi++)
            #pragma unroll
            for (int h = 0; h < 2; h++) {
                if (ok0) mx[mi][h] = fmaxf(mx[mi][h], acc[mi][ni][2*h]);
                if (ok1) mx[mi][h] = fmaxf(mx[mi][h], acc[mi][ni][2*h+1]);
            }
    }
    #pragma unroll
    for (int mi = 0; mi < 4; mi++)
        #pragma unroll
        for (int h = 0; h < 2; h++) {
            mx[mi][h] = fmaxf(mx[mi][h], __shfl_xor_sync(0xffffffffu, mx[mi][h], 1));
            mx[mi][h] = fmaxf(mx[mi][h], __shfl_xor_sync(0xffffffffu, mx[mi][h], 2));
        }
    __syncthreads();
    if (c == 0) {
        #pragma unroll
        for (int mi = 0; mi < 4; mi++)
            #pragma unroll
            for (int h = 0; h < 2; h++)
                red[(w & 3) * 128 + wm0 + mi*16 + g + h*8] = mx[mi][h];
    }
    __syncthreads();
    float mxr[4][2];
    #pragma unroll
    for (int mi = 0; mi < 4; mi++)
        #pragma unroll
        for (int h = 0; h < 2; h++) {
            int r = wm0 + mi*16 + g + h*8;
            mxr[mi][h] = fmaxf(fmaxf(red[r], red[128 + r]), fmaxf(red[256 + r], red[384 + r]));
        }
    __syncthreads();
    float sum_[4][2];
    #pragma unroll
    for (int mi = 0; mi < 4; mi++) { sum_[mi][0] = 0.f; sum_[mi][1] = 0.f; }
    #pragma unroll
    for (int ni = 0; ni < 4; ni++) {
        int cn = wn0 + ni*8 + c*2;
        bool ok0 = cn < M_, ok1 = (cn+1) < M_;
        #pragma unroll
        for (int mi = 0; mi < 4; mi++)
            #pragma unroll
            for (int h = 0; h < 2; h++) {
                float e0 = ok0 ? __expf(acc[mi][ni][2*h]   - mxr[mi][h]) : 0.f;
                float e1 = ok1 ? __expf(acc[mi][ni][2*h+1] - mxr[mi][h]) : 0.f;
                acc[mi][ni][2*h] = e0; acc[mi][ni][2*h+1] = e1;
                sum_[mi][h] += e0 + e1;
            }
    }
    #pragma unroll
    for (int mi = 0; mi < 4; mi++)
        #pragma unroll
        for (int h = 0; h < 2; h++) {
            sum_[mi][h] += __shfl_xor_sync(0xffffffffu, sum_[mi][h], 1);
            sum_[mi][h] += __shfl_xor_sync(0xffffffffu, sum_[mi][h], 2);
        }
    if (c == 0) {
        #pragma unroll
        for (int mi = 0; mi < 4; mi++)
            #pragma unroll
            for (int h = 0; h < 2; h++)
                red[(w & 3) * 128 + wm0 + mi*16 + g + h*8] = sum_[mi][h];
    }
    __syncthreads();
    #pragma unroll
    for (int mi = 0; mi < 4; mi++) {
        #pragma unroll
        for (int h = 0; h < 2; h++) {
            int r = wm0 + mi*16 + g + h*8;
            float inv = 1.f / (red[r] + red[128 + r] + red[256 + r] + red[384 + r]);
            size_t t = m0 + r;
            #pragma unroll
            for (int ni = 0; ni < 4; ni++) {
                int cn = wn0 + ni*8 + c*2;
                if (cn < M_)   logits[t*LML_ + cn]   = acc[mi][ni][2*h]   * inv;
                if (cn+1 < M_) logits[t*LML_ + cn+1] = acc[mi][ni][2*h+1] * inv;
            }
        }
    }
}

// ==================== small kernels ====================
__global__ void k_prep(const float* __restrict__ eW, const float* __restrict__ eb,
                       const float* __restrict__ aW, const float* __restrict__ ab,
                       const float* __restrict__ d1W, const float* __restrict__ d2W,
                       const float* __restrict__ roW, const float* __restrict__ Mk)
{
    int i = blockIdx.x * blockDim.x + threadIdx.x;
    int stride = gridDim.x * blockDim.x;
    for (int j = i; j < NEA_*KEA_; j += stride) {
        int n = j / KEA_, k = j % KEA_;
        g_Wea[n*KEA_ + ph(k)] = __float2half((n < DV_) ? eW[n*KEA_ + k] : aW[(n - DV_)*KEA_ + k]);
    }
    for (int j = i; j < DQ_*DQ_; j += stride) {
        int n = j / DQ_, k = j % DQ_;
        g_Wd1[n*DQ_ + ph(k)] = __float2half(d1W[j]);
        g_Wd2[n*DQ_ + ph(k)] = __float2half(d2W[j]);
    }
    for (int j = i; j < F_*KRO_; j += stride) {
        int n = j / KRO_, k = j % KRO_;
        g_Wro[n*KRO_ + ph(k)] = __float2half(roW[j]);
    }
    for (int j = i; j < 128*DQ_; j += stride) {
        int n = j / DQ_, k = j % DQ_;
        g_Wmk[n*DQ_ + ph(k)] = __float2half(n < M_ ? Mk[n*DQ_ + k] : 0.f);
    }
    for (int j = i; j < NEA_; j += stride) g_bea[j] = (j < DV_) ? eb[j] : ab[j - DV_];
    if (i < 2) g_accum[i] = 0.f;
}

__global__ void k_gather1(const int* __restrict__ q_data, const int* __restrict__ qa_data,
                          const int* __restrict__ time_data, const int* __restrict__ attempt_data,
                          const int* __restrict__ hint_data, const int* __restrict__ hintTotal_data,
                          const float* __restrict__ q_emb, const float* __restrict__ qa_emb,
                          const float* __restrict__ time_emb, const float* __restrict__ attempt_emb,
                          const float* __restrict__ ht_emb)
{
    int t = blockIdx.x, d = threadIdx.x;
    int pd = ph(d);
    int qi = q_data[t], ti = time_data[t], ai = attempt_data[t];
    int hi = hint_data[t], hti = hintTotal_data[t];
    float qe  = q_emb[(size_t)qi*DQ_ + d];
    float te  = time_emb[(size_t)ti*DQ_ + d];
    float ae  = attempt_emb[(size_t)ai*DQ_ + d];
    float he  = ht_emb[(size_t)hi*DQ_ + d];
    float hte = ht_emb[(size_t)hti*DQ_ + d];
    g_bufX[(size_t)t*DQ_ + pd]      = __float2half(te + qe);
    g_bufX[(size_t)(T_+t)*DQ_ + pd] = __float2half(he + hte + ae + qe);
    int qai = qa_data[t];
    g_bufQA[(size_t)t*DV_ + pd]          = __float2half(qa_emb[(size_t)qai*DV_ + d]);
    g_bufQA[(size_t)t*DV_ + ph(d + DQ_)] = __float2half(qa_emb[(size_t)qai*DV_ + DQ_ + d]);
}

// DV split 2-way -> 512 CTAs; per-warp ws, no block barriers
__global__ void __launch_bounds__(128) k_scan(const float* __restrict__ Mv0)
{
    int b = blockIdx.x;
    int tidw = threadIdx.x & 31;
    int wid  = threadIdx.x >> 5;
    int d = blockIdx.y * 128 + threadIdx.x;
    int pe = ph(d);
    int pa = ph(d + DV_);
    float mv[M_];
    #pragma unroll
    for (int m = 0; m < M_; m++) mv[m] = Mv0[m*DV_ + d];
    __shared__ float ws[4][2][64];
    size_t t0 = (size_t)b * S_;
    if (tidw < M_)      ws[wid][0][tidw]      = g_logits[t0*LML_ + tidw];
    if (tidw + 32 < M_) ws[wid][0][tidw + 32] = g_logits[t0*LML_ + tidw + 32];
    float e = __half2float(g_bufEA[t0*NEA_ + pe]);
    float a = __half2float(g_bufEA[t0*NEA_ + pa]);
    __syncwarp();
    for (int s = 0; s < S_; s++) {
        size_t t = t0 + s;
        float en = 0.f, an = 0.f;
        if (s + 1 < S_) {
            en = __half2float(g_bufEA[(t+1)*NEA_ + pe]);
            an = __half2float(g_bufEA[(t+1)*NEA_ + pa]);
            int nb = (s+1) & 1;
            if (tidw < M_)      ws[wid][nb][tidw]      = g_logits[(t+1)*LML_ + tidw];
            if (tidw + 32 < M_) ws[wid][nb][tidw + 32] = g_logits[(t+1)*LML_ + tidw + 32];
        }
        const float* wcur = ws[wid][s & 1];
        float rd0 = 0.f, rd1 = 0.f;
        #pragma unroll
        for (int m = 0; m < M_; m += 2) {
            float w0 = wcur[m], w1 = wcur[m+1];
            rd0 = fmaf(w0, mv[m],   rd0);
            rd1 = fmaf(w1, mv[m+1], rd1);
            mv[m]   = fmaf(mv[m],   fmaf(-w0, e, 1.f), w0 * a);
            mv[m+1] = fmaf(mv[m+1], fmaf(-w1, e, 1.f), w1 * a);
        }
        g_PredIn[t*KRO_ + pe] = __float2half(rd0 + rd1);
        __syncwarp();
        e = en; a = an;
    }
}

__global__ void k_loss(const int* __restrict__ target, const float* __restrict__ pred_b,
                       float* __restrict__ out)
{
    int i = blockIdx.x * blockDim.x + threadIdx.x;
    float le = 0.f, cnt = 0.f;
    if (i < T_) {
        float p = g_predP[0][i] + g_predP[1][i] + g_predP[2][i] + g_predP[3][i] + pred_b[0];
        int tg = target[i];
        bool mask = tg >= 1;
        float y = mask ? (float)(tg - 1) : 0.f;
        float sig = 1.f / (1.f + expf(-p));
        out[1 + i]      = mask ? sig : 0.f;
        out[1 + T_ + i] = mask ? y   : 0.f;
        if (mask) {
            le = fmaxf(p, 0.f) + log1pf(expf(-fabsf(p))) - p * y;
            cnt = 1.f;
        }
    }
    __shared__ float sle[256], scn[256];
    sle[threadIdx.x] = le; scn[threadIdx.x] = cnt;
    __syncthreads();
    for (int o = 128; o; o >>= 1) {
        if (threadIdx.x < o) { sle[threadIdx.x] += sle[threadIdx.x + o]; scn[threadIdx.x] += scn[threadIdx.x + o]; }
        __syncthreads();
    }
    if (threadIdx.x == 0) { atomicAdd(&g_accum[0], sle[0]); atomicAdd(&g_accum[1], scn[0]); }
}

__global__ void k_final(float* __restrict__ out)
{
    out[0] = g_accum[0] / fmaxf(g_accum[1], 1.f);
}

// ==================== host ====================
extern "C" void kernel_launch(void* const* d_in, const int* in_sizes, int n_in,
                              void* d_out, int out_size)
{
    const int*   q_data      = (const int*)  d_in[0];
    const int*   qa_data     = (const int*)  d_in[1];
    const int*   target      = (const int*)  d_in[2];
    const int*   time_data   = (const int*)  d_in[3];
    const int*   attempt_data= (const int*)  d_in[4];
    const int*   hint_data   = (const int*)  d_in[5];
    const int*   hintTotal   = (const int*)  d_in[6];
    const float* q_emb       = (const float*)d_in[7];
    const float* qa_emb      = (const float*)d_in[8];
    const float* time_emb    = (const float*)d_in[9];
    const float* attempt_emb = (const float*)d_in[10];
    const float* ht_emb      = (const float*)d_in[11];
    const float* Mk          = (const float*)d_in[12];
    const float* Mv0         = (const float*)d_in[13];
    const float* diff_W      = (const float*)d_in[14];
    const float* diff_b      = (const float*)d_in[15];
    const float* diff2_W     = (const float*)d_in[16];
    const float* diff2_b     = (const float*)d_in[17];
    const float* erase_W     = (const float*)d_in[18];
    const float* erase_b     = (const float*)d_in[19];
    const float* add_W       = (const float*)d_in[20];
    const float* add_b       = (const float*)d_in[21];
    const float* read_W      = (const float*)d_in[22];
    const float* read_b      = (const float*)d_in[23];
    const float* pred_W      = (const float*)d_in[24];
    const float* pred_b      = (const float*)d_in[25];
    float* out = (float*)d_out;

    __half *bufX, *bufX3, *bufTD, *bufQA, *bufEA, *predin;
    __half *Wea, *Wd1, *Wd2, *Wro, *Wmk;
    float *logits, *predP, *bea;
    cudaGetSymbolAddress((void**)&bufX,   g_bufX);
    cudaGetSymbolAddress((void**)&bufX3,  g_bufX3);
    cudaGetSymbolAddress((void**)&bufTD,  g_bufTD);
    cudaGetSymbolAddress((void**)&bufQA,  g_bufQA);
    cudaGetSymbolAddress((void**)&bufEA,  g_bufEA);
    cudaGetSymbolAddress((void**)&predin, g_PredIn);
    cudaGetSymbolAddress((void**)&logits, g_logits);
    cudaGetSymbolAddress((void**)&predP,  g_predP);
    cudaGetSymbolAddress((void**)&Wea,    g_Wea);
    cudaGetSymbolAddress((void**)&Wd1,    g_Wd1);
    cudaGetSymbolAddress((void**)&Wd2,    g_Wd2);
    cudaGetSymbolAddress((void**)&Wro,    g_Wro);
    cudaGetSymbolAddress((void**)&Wmk,    g_Wmk);
    cudaGetSymbolAddress((void**)&bea,    g_bea);

    const int SMG = (6*2048 + 128) * 4;
    const int SML = (6*2048 + 128*USTR) * 4;
    const int SMQ = (6*2048 + 128*USTR + 512) * 4;
    cudaFuncSetAttribute(k_mma<3,KEA_>, cudaFuncAttributeMaxDynamicSharedMemorySize, SMG);
    cudaFuncSetAttribute(k_mma<4,KRO_>, cudaFuncAttributeMaxDynamicSharedMemorySize, SMG);
    cudaFuncSetAttribute(k_lin12, cudaFuncAttributeMaxDynamicSharedMemorySize, SML);
    cudaFuncSetAttribute(k_qplog, cudaFuncAttributeMaxDynamicSharedMemorySize, SMQ);

    k_prep<<<1024, 256>>>(erase_W, erase_b, add_W, add_b, diff_W, diff2_W, read_W, Mk);
    k_gather1<<<T_, 128>>>(q_data, qa_data, time_data, attempt_data, hint_data, hintTotal,
                           q_emb, qa_emb, time_emb, attempt_emb, ht_emb);
    k_lin12<<<2*T_/128, 256, SML>>>(bufX, Wd1, Wd2, diff_b, diff2_b, bufTD, bufX3,
                                    q_data, attempt_data, hint_data, hintTotal,
                                    q_emb, attempt_emb, ht_emb);
    k_qplog<<<T_/128, 256, SMQ>>>(bufX3, Wd1, Wmk, diff_b, bufTD,
                                  time_data, time_emb, predin, logits);
    k_mma<3,KEA_><<<dim3(4, T_/128), 256, SMG>>>(bufQA, Wea, bea, bufEA, NEA_, nullptr, nullptr);
    k_scan<<<dim3(B_, 2), 128>>>(Mv0);
    k_mma<4,KRO_><<<dim3(4, T_/128), 256, SMG>>>(predin, Wro, read_b, nullptr, 0, pred_W, predP);
    k_loss<<<(T_ + 255)/256, 256>>>(target, pred_b, out);
    k_final<<<1, 1>>>(out);
}

// round 12
// speedup vs baseline: 3.9163x; 1.0135x over previous
#include <cuda_runtime.h>
#include <cuda_fp16.h>
#include <math.h>
#include <stdint.h>

#define B_   256
#define S_   500
#define T_   (B_*S_)        // 128000
#define DQ_  128
#define DV_  256
#define M_   50
#define F_   512
#define NEA_ 512
#define KEA_ 256
#define KRO_ 384
#define LML_ 64
#define USTR 80

// ---------------- scratch (device globals) ----------------
__device__ __half g_bufX [2*T_*DQ_];
__device__ __half g_bufX3[T_*DQ_];
__device__ __half g_bufTD[T_*DQ_];
__device__ __half g_bufQA[T_*DV_];
__device__ __half g_bufEA[T_*NEA_];
__device__ __half g_PredIn[T_*KRO_];
__device__ float  g_logits[T_*LML_];
__device__ float  g_predP[4][T_];
__device__ float  g_accum[2];
__device__ __half g_Wea[NEA_*KEA_];
__device__ __half g_Wd1[DQ_*DQ_];
__device__ __half g_Wd2[DQ_*DQ_];
__device__ __half g_Wro[F_*KRO_];
__device__ __half g_Wmk[128*DQ_];
__device__ float  g_bea[NEA_];

// ==================== helpers ====================
__device__ __forceinline__ int ph(int d) {
    int pair = d >> 1;
    int pi   = pair & 15;
    int pp   = (pair & ~15) | ((pi & 3) * 4 + (pi >> 2));
    return pp * 2 + (d & 1);
}
__device__ __forceinline__ int permc(int cn) {
    int pair = cn >> 1;
    int pi   = pair & 15;
    int pp   = (pair & ~15) | ((pi & 3) * 4 + (pi >> 2));
    return pp * 2;
}
__device__ __forceinline__ float fsig(float x) { return 1.f / (1.f + __expf(-x)); }
__device__ __forceinline__ float ftanh(float x) {
    float ax = fabsf(x);
    float t  = 1.f - 2.f / (1.f + __expf(2.f * ax));
    return copysignf(t, x);
}
__device__ __forceinline__ void mma16(float* d,
    uint32_t a0, uint32_t a1, uint32_t a2, uint32_t a3,
    uint32_t b0, uint32_t b1)
{
    asm volatile(
        "mma.sync.aligned.m16n8k16.row.col.f32.f16.f16.f32 "
        "{%0,%1,%2,%3},{%4,%5,%6,%7},{%8,%9},{%0,%1,%2,%3};"
        : "+f"(d[0]), "+f"(d[1]), "+f"(d[2]), "+f"(d[3])
        : "r"(a0), "r"(a1), "r"(a2), "r"(a3), "r"(b0), "r"(b1));
}
__device__ __forceinline__ void cpa16(uint32_t dst, const void* src) {
    asm volatile("cp.async.cg.shared.global [%0], [%1], 16;" :: "r"(dst), "l"(src));
}

// ==================== device GEMM body: EA (K=256, perm store) ==============
__device__ __forceinline__ void dev_ea(uint32_t* sm, int m0, int n0,
    const __half* __restrict__ A, const __half* __restrict__ W,
    const float* __restrict__ bias, __half* __restrict__ C)
{
    constexpr int NCH = 8, LDP = 128;
    uint32_t* As = sm;
    uint32_t* Bs = sm + 3 * 2048;

    const int tid  = threadIdx.x;
    const int lane = tid & 31, w = tid >> 5;
    const int g    = lane >> 2, c = lane & 3;
    const int wm0  = (w >> 2) * 64;
    const int wn0  = (w & 3) * 32;
    const int srow = tid >> 2;
    const int grp  = tid & 3;

    const uint32_t* Ag = (const uint32_t*)A + (size_t)(m0 + srow) * LDP + grp * 4;
    const uint32_t* Wg = (const uint32_t*)W + (size_t)(n0 + srow) * LDP + grp * 4;
    const uint32_t asb = (uint32_t)__cvta_generic_to_shared(As) + (srow * 16 + grp * 4) * 4;
    const uint32_t bsb = (uint32_t)__cvta_generic_to_shared(Bs) + (srow * 16 + grp * 4) * 4;

    float acc[4][4][4];
    #pragma unroll
    for (int i = 0; i < 4; i++)
        #pragma unroll
        for (int j = 0; j < 4; j++)
            #pragma unroll
            for (int r = 0; r < 4; r++) acc[i][j][r] = 0.f;

    auto stage = [&](int ch, int s) {
        uint32_t ab = asb + s * 2048 * 4;
        cpa16(ab,               Ag + ch * 16);
        cpa16(ab + 64 * 16 * 4, Ag + (size_t)64 * LDP + ch * 16);
        uint32_t bb = bsb + s * 2048 * 4;
        cpa16(bb,               Wg + ch * 16);
        cpa16(bb + 64 * 16 * 4, Wg + (size_t)64 * LDP + ch * 16);
        asm volatile("cp.async.commit_group;");
    };

    stage(0, 0); stage(1, 1);
    #pragma unroll
    for (int ch = 0; ch < NCH; ch++) {
        asm volatile("cp.async.wait_group 1;");
        __syncthreads();
        if (ch + 2 < NCH) stage(ch + 2, (ch + 2) % 3);
        else asm volatile("cp.async.commit_group;");
        const uint32_t* as = As + (ch % 3) * 2048;
        const uint32_t* bs = Bs + (ch % 3) * 2048;
        uint4 alo[4], ahi[4];
        #pragma unroll
        for (int mi = 0; mi < 4; mi++) {
            alo[mi] = *(const uint4*)&as[(wm0 + mi*16 + g)     * 16 + c*4];
            ahi[mi] = *(const uint4*)&as[(wm0 + mi*16 + g + 8) * 16 + c*4];
        }
        #pragma unroll
        for (int ni = 0; ni < 4; ni++) {
            uint4 b = *(const uint4*)&bs[(wn0 + ni*8 + g) * 16 + c*4];
            #pragma unroll
            for (int mi = 0; mi < 4; mi++) {
                mma16(acc[mi][ni], alo[mi].x, ahi[mi].x, alo[mi].y, ahi[mi].y, b.x, b.y);
                mma16(acc[mi][ni], alo[mi].z, ahi[mi].z, alo[mi].w, ahi[mi].w, b.z, b.w);
            }
        }
    }

    #pragma unroll
    for (int ni = 0; ni < 4; ni++) {
        int cn  = n0 + wn0 + ni*8 + c*2;
        int cnp = permc(cn);
        float b0 = __ldg(&bias[cn]), b1 = __ldg(&bias[cn+1]);
        #pragma unroll
        for (int mi = 0; mi < 4; mi++) {
            int r0 = m0 + wm0 + mi*16 + g;
            float v0 = acc[mi][ni][0] + b0, v1 = acc[mi][ni][1] + b1;
            float v2 = acc[mi][ni][2] + b0, v3 = acc[mi][ni][3] + b1;
            if (cn < DV_) { v0 = fsig(v0); v1 = fsig(v1); v2 = fsig(v2); v3 = fsig(v3); }
            else          { v0 = ftanh(v0); v1 = ftanh(v1); v2 = ftanh(v2); v3 = ftanh(v3); }
            *(__half2*)&C[(size_t)r0    *NEA_ + cnp] = __floats2half2_rn(v0, v1);
            *(__half2*)&C[(size_t)(r0+8)*NEA_ + cnp] = __floats2half2_rn(v2, v3);
        }
    }
}

// ==================== device body: lin12 ====================
__device__ __forceinline__ void dev_lin12(uint32_t* sm, int m0,
    const __half* __restrict__ A,
    const __half* __restrict__ W1, const __half* __restrict__ W2,
    const float* __restrict__ b1, const float* __restrict__ b2,
    __half* __restrict__ TD, __half* __restrict__ X3,
    const int* __restrict__ q_data, const int* __restrict__ attempt_data,
    const int* __restrict__ hint_data, const int* __restrict__ hintTotal_data,
    const float* __restrict__ q_emb, const float* __restrict__ attempt_emb,
    const float* __restrict__ ht_emb)
{
    uint32_t* Xs = sm;
    uint32_t* Bs = sm + 3*2048;
    uint32_t* Us = sm + 6*2048;

    const int tid  = threadIdx.x;
    const int lane = tid & 31, w = tid >> 5;
    const int g    = lane >> 2, c = lane & 3;
    const int wm0  = (w >> 2) * 64;
    const int wn0  = (w & 3) * 32;
    const int srow = tid >> 2;
    const int grp  = tid & 3;

    const uint32_t* Ag  = (const uint32_t*)A  + (size_t)(m0 + srow) * 64 + grp * 4;
    const uint32_t* W1g = (const uint32_t*)W1 + (size_t)srow * 64 + grp * 4;
    const uint32_t* W2g = (const uint32_t*)W2 + (size_t)srow * 64 + grp * 4;

    const uint32_t xsb = (uint32_t)__cvta_generic_to_shared(Xs) + (srow*16 + grp*4) * 4;
    const uint32_t bsb = (uint32_t)__cvta_generic_to_shared(Bs) + (srow*16 + grp*4) * 4;

    float acc[4][4][4];
    #pragma unroll
    for (int i = 0; i < 4; i++)
        #pragma unroll
        for (int j = 0; j < 4; j++)
            #pragma unroll
            for (int r = 0; r < 4; r++) acc[i][j][r] = 0.f;

    auto stage1 = [&](int ch, int s) {
        uint32_t xb = xsb + s * 2048 * 4;
        cpa16(xb,           Ag + ch * 16);
        cpa16(xb + 64*16*4, Ag + (size_t)64*64 + ch * 16);
        uint32_t bb = bsb + s * 2048 * 4;
        cpa16(bb,           W1g + ch * 16);
        cpa16(bb + 64*16*4, W1g + (size_t)64*64 + ch * 16);
        asm volatile("cp.async.commit_group;");
    };

    stage1(0, 0); stage1(1, 1);
    #pragma unroll
    for (int ch = 0; ch < 4; ch++) {
        asm volatile("cp.async.wait_group 1;");
        __syncthreads();
        if (ch + 2 < 4) stage1(ch + 2, (ch + 2) % 3);
        else asm volatile("cp.async.commit_group;");
        const uint32_t* xs = Xs + (ch % 3) * 2048;
        const uint32_t* bs = Bs + (ch % 3) * 2048;
        uint4 alo[4], ahi[4];
        #pragma unroll
        for (int mi = 0; mi < 4; mi++) {
            alo[mi] = *(const uint4*)&xs[(wm0 + mi*16 + g)     * 16 + c*4];
            ahi[mi] = *(const uint4*)&xs[(wm0 + mi*16 + g + 8) * 16 + c*4];
        }
        #pragma unroll
        for (int ni = 0; ni < 4; ni++) {
            uint4 b = *(const uint4*)&bs[(wn0 + ni*8 + g) * 16 + c*4];
            #pragma unroll
            for (int mi = 0; mi < 4; mi++) {
                mma16(acc[mi][ni], alo[mi].x, ahi[mi].x, alo[mi].y, ahi[mi].y, b.x, b.y);
                mma16(acc[mi][ni], alo[mi].z, ahi[mi].z, alo[mi].w, ahi[mi].w, b.z, b.w);
            }
        }
    }
    asm volatile("cp.async.wait_group 0;");

    #pragma unroll
    for (int ni = 0; ni < 4; ni++) {
        int cn = wn0 + ni*8 + c*2;
        float bb0 = __ldg(&b1[cn]), bb1 = __ldg(&b1[cn+1]);
        int pw = permc(cn) >> 1;
        #pragma unroll
        for (int mi = 0; mi < 4; mi++) {
            int r0 = wm0 + mi*16 + g;
            __half2 h0 = __floats2half2_rn(ftanh(acc[mi][ni][0] + bb0), ftanh(acc[mi][ni][1] + bb1));
            __half2 h1 = __floats2half2_rn(ftanh(acc[mi][ni][2] + bb0), ftanh(acc[mi][ni][3] + bb1));
            Us[r0*USTR + pw]     = *(uint32_t*)&h0;
            Us[(r0+8)*USTR + pw] = *(uint32_t*)&h1;
            acc[mi][ni][0] = acc[mi][ni][1] = acc[mi][ni][2] = acc[mi][ni][3] = 0.f;
        }
    }
    __syncthreads();

    auto stage2 = [&](int ch, int s) {
        uint32_t bb = bsb + s * 2048 * 4;
        cpa16(bb,           W2g + ch * 16);
        cpa16(bb + 64*16*4, W2g + (size_t)64*64 + ch * 16);
        asm volatile("cp.async.commit_group;");
    };
    stage2(0, 0); stage2(1, 1);
    #pragma unroll
    for (int ch = 0; ch < 4; ch++) {
        asm volatile("cp.async.wait_group 1;");
        __syncthreads();
        if (ch + 2 < 4) stage2(ch + 2, (ch + 2) % 3);
        else asm volatile("cp.async.commit_group;");
        const uint32_t* bs = Bs + (ch % 3) * 2048;
        uint4 alo[4], ahi[4];
        #pragma unroll
        for (int mi = 0; mi < 4; mi++) {
            alo[mi] = *(const uint4*)&Us[(wm0 + mi*16 + g)     * USTR + ch*16 + c*4];
            ahi[mi] = *(const uint4*)&Us[(wm0 + mi*16 + g + 8) * USTR + ch*16 + c*4];
        }
        #pragma unroll
        for (int ni = 0; ni < 4; ni++) {
            uint4 b = *(const uint4*)&bs[(wn0 + ni*8 + g) * 16 + c*4];
            #pragma unroll
            for (int mi = 0; mi < 4; mi++) {
                mma16(acc[mi][ni], alo[mi].x, ahi[mi].x, alo[mi].y, ahi[mi].y, b.x, b.y);
                mma16(acc[mi][ni], alo[mi].z, ahi[mi].z, alo[mi].w, ahi[mi].w, b.z, b.w);
            }
        }
    }

    const bool isdiff = (m0 >= T_);
    #pragma unroll
    for (int mi = 0; mi < 4; mi++) {
        #pragma unroll
        for (int h = 0; h < 2; h++) {
            int r = wm0 + mi*16 + g + h*8;
            int t = m0 + r;
            if (!isdiff) {
                #pragma unroll
                for (int ni = 0; ni < 4; ni++) {
                    int cn = wn0 + ni*8 + c*2;
                    float v0 = fsig(acc[mi][ni][2*h]   + __ldg(&b2[cn]));
                    float v1 = fsig(acc[mi][ni][2*h+1] + __ldg(&b2[cn+1]));
                    *(__half2*)&TD[(size_t)t*DQ_ + cn] = __floats2half2_rn(v0, v1);
                }
            } else {
                int tt = t - T_;
                int qi = q_data[tt], ai = attempt_data[tt];
                int hi = hint_data[tt], hti = hintTotal_data[tt];
                #pragma unroll
                for (int ni = 0; ni < 4; ni++) {
                    int cn = wn0 + ni*8 + c*2;
                    float v0 = fsig(acc[mi][ni][2*h]   + __ldg(&b2[cn]));
                    float v1 = fsig(acc[mi][ni][2*h+1] + __ldg(&b2[cn+1]));
                    float qe0 = q_emb[(size_t)qi*DQ_ + cn],   qe1 = q_emb[(size_t)qi*DQ_ + cn+1];
                    float g0  = attempt_emb[(size_t)ai*DQ_ + cn]
                              + ht_emb[(size_t)hi*DQ_ + cn] + ht_emb[(size_t)hti*DQ_ + cn];
                    float g1  = attempt_emb[(size_t)ai*DQ_ + cn+1]
                              + ht_emb[(size_t)hi*DQ_ + cn+1] + ht_emb[(size_t)hti*DQ_ + cn+1];
                    *(__half2*)&X3[(size_t)tt*DQ_ + permc(cn)] =
                        __floats2half2_rn(fmaf(v0, g0, qe0), fmaf(v1, g1, qe1));
                }
            }
        }
    }
}

// ==================== device body: qplog ====================
__device__ __forceinline__ void dev_qplog(uint32_t* sm, int m0,
    const __half* __restrict__ A,
    const __half* __restrict__ W1, const __half* __restrict__ WM,
    const float* __restrict__ b1, const __half* __restrict__ TD,
    const int* __restrict__ time_data, const float* __restrict__ time_emb,
    __half* __restrict__ PredIn, float* __restrict__ logits)
{
    uint32_t* Xs  = sm;
    uint32_t* Bs  = sm + 3*2048;
    uint32_t* Us  = sm + 6*2048;
    float*    red = (float*)(sm + 6*2048 + 128*USTR);

    const int tid  = threadIdx.x;
    const int lane = tid & 31, w = tid >> 5;
    const int g    = lane >> 2, c = lane & 3;
    const int wm0  = (w >> 2) * 64;
    const int wn0  = (w & 3) * 32;
    const int srow = tid >> 2;
    const int grp  = tid & 3;

    const uint32_t* Ag  = (const uint32_t*)A  + (size_t)(m0 + srow) * 64 + grp * 4;
    const uint32_t* W1g = (const uint32_t*)W1 + (size_t)srow * 64 + grp * 4;
    const uint32_t* WMg = (const uint32_t*)WM + (size_t)srow * 64 + grp * 4;

    const uint32_t xsb = (uint32_t)__cvta_generic_to_shared(Xs) + (srow*16 + grp*4) * 4;
    const uint32_t bsb = (uint32_t)__cvta_generic_to_shared(Bs) + (srow*16 + grp*4) * 4;

    float acc[4][4][4];
    #pragma unroll
    for (int i = 0; i < 4; i++)
        #pragma unroll
        for (int j = 0; j < 4; j++)
            #pragma unroll
            for (int r = 0; r < 4; r++) acc[i][j][r] = 0.f;

    auto stage1 = [&](int ch, int s) {
        uint32_t xb = xsb + s * 2048 * 4;
        cpa16(xb,           Ag + ch * 16);
        cpa16(xb + 64*16*4, Ag + (size_t)64*64 + ch * 16);
        uint32_t bb = bsb + s * 2048 * 4;
        cpa16(bb,           W1g + ch * 16);
        cpa16(bb + 64*16*4, W1g + (size_t)64*64 + ch * 16);
        asm volatile("cp.async.commit_group;");
    };
    stage1(0, 0); stage1(1, 1);
    #pragma unroll
    for (int ch = 0; ch < 4; ch++) {
        asm volatile("cp.async.wait_group 1;");
        __syncthreads();
        if (ch + 2 < 4) stage1(ch + 2, (ch + 2) % 3);
        else asm volatile("cp.async.commit_group;");
        const uint32_t* xs = Xs + (ch % 3) * 2048;
        const uint32_t* bs = Bs + (ch % 3) * 2048;
        uint4 alo[4], ahi[4];
        #pragma unroll
        for (int mi = 0; mi < 4; mi++) {
            alo[mi] = *(const uint4*)&xs[(wm0 + mi*16 + g)     * 16 + c*4];
            ahi[mi] = *(const uint4*)&xs[(wm0 + mi*16 + g + 8) * 16 + c*4];
        }
        #pragma unroll
        for (int ni = 0; ni < 4; ni++) {
            uint4 b = *(const uint4*)&bs[(wn0 + ni*8 + g) * 16 + c*4];
            #pragma unroll
            for (int mi = 0; mi < 4; mi++) {
                mma16(acc[mi][ni], alo[mi].x, ahi[mi].x, alo[mi].y, ahi[mi].y, b.x, b.y);
                mma16(acc[mi][ni], alo[mi].z, ahi[mi].z, alo[mi].w, ahi[mi].w, b.z, b.w);
            }
        }
    }
    asm volatile("cp.async.wait_group 0;");

    #pragma unroll
    for (int mi = 0; mi < 4; mi++) {
        #pragma unroll
        for (int h = 0; h < 2; h++) {
            int r = wm0 + mi*16 + g + h*8;
            int t = m0 + r;
            int ti = time_data[t];
            #pragma unroll
            for (int ni = 0; ni < 4; ni++) {
                int cn = wn0 + ni*8 + c*2;
                float q0 = acc[mi][ni][2*h]   + __ldg(&b1[cn]);
                float q1 = acc[mi][ni][2*h+1] + __ldg(&b1[cn+1]);
                __half2 hq = __floats2half2_rn(q0, q1);
                Us[r*USTR + (permc(cn) >> 1)] = *(uint32_t*)&hq;
                float2 qp2 = __half22float2(hq);
                __half2 tfh = *(const __half2*)&TD[(size_t)t*DQ_ + cn];
                float2 tf2 = __half22float2(tfh);
                float te0 = time_emb[(size_t)ti*DQ_ + cn], te1 = time_emb[(size_t)ti*DQ_ + cn+1];
                *(__half2*)&PredIn[(size_t)t*KRO_ + DV_ + permc(cn)] =
                    __floats2half2_rn(fmaf(tf2.x, te0, qp2.x), fmaf(tf2.y, te1, qp2.y));
                acc[mi][ni][2*h] = 0.f; acc[mi][ni][2*h+1] = 0.f;
            }
        }
    }
    __syncthreads();

    auto stage2 = [&](int ch, int s) {
        uint32_t bb = bsb + s * 2048 * 4;
        cpa16(bb,           WMg + ch * 16);
        cpa16(bb + 64*16*4, WMg + (size_t)64*64 + ch * 16);
        asm volatile("cp.async.commit_group;");
    };
    stage2(0, 0); stage2(1, 1);
    #pragma unroll
    for (int ch = 0; ch < 4; ch++) {
        asm volatile("cp.async.wait_group 1;");
        __syncthreads();
        if (ch + 2 < 4) stage2(ch + 2, (ch + 2) % 3);
        else asm volatile("cp.async.commit_group;");
        const uint32_t* bs = Bs + (ch % 3) * 2048;
        uint4 alo[4], ahi[4];
        #pragma unroll
        for (int mi = 0; mi < 4; mi++) {
            alo[mi] = *(const uint4*)&Us[(wm0 + mi*16 + g)     * USTR + ch*16 + c*4];
            ahi[mi] = *(const uint4*)&Us[(wm0 + mi*16 + g + 8) * USTR + ch*16 + c*4];
        }
        #pragma unroll
        for (int ni = 0; ni < 4; ni++) {
            uint4 b = *(const uint4*)&bs[(wn0 + ni*8 + g) * 16 + c*4];
            #pragma unroll
            for (int mi = 0; mi < 4; mi++) {
                mma16(acc[mi][ni], alo[mi].x, ahi[mi].x, alo[mi].y, ahi[mi].y, b.x, b.y);
                mma16(acc[mi][ni], alo[mi].z, ahi[mi].z, alo[mi].w, ahi[mi].w, b.z, b.w);
            }
        }
    }

    float mx[4][2];
    #pragma unroll
    for (int mi = 0; mi < 4; mi++) { mx[mi][0] = -1e30f; mx[mi][1] = -1e30f; }
    #pragma unroll
    for (int ni = 0; ni < 4; ni++) {
        int cn = wn0 + ni*8 + c*2;
        bool ok0 = cn < M_, ok1 = (cn+1) < M_;
        #pragma unroll
        for (int mi = 0; mi < 4; mi++)
            #pragma unroll
            for (int h = 0; h < 2; h++) {
                if (ok0) mx[mi][h] = fmaxf(mx[mi][h], acc[mi][ni][2*h]);
                if (ok1) mx[mi][h] = fmaxf(mx[mi][h], acc[mi][ni][2*h+1]);
            }
    }
    #pragma unroll
    for (int mi = 0; mi < 4; mi++)
        #pragma unroll
        for (int h = 0; h < 2; h++) {
            mx[mi][h] = fmaxf(mx[mi][h], __shfl_xor_sync(0xffffffffu, mx[mi][h], 1));
            mx[mi][h] = fmaxf(mx[mi][h], __shfl_xor_sync(0xffffffffu, mx[mi][h], 2));
        }
    __syncthreads();
    if (c == 0) {
        #pragma unroll
        for (int mi = 0; mi < 4; mi++)
            #pragma unroll
            for (int h = 0; h < 2; h++)
                red[(w & 3) * 128 + wm0 + mi*16 + g + h*8] = mx[mi][h];
    }
    __syncthreads();
    float mxr[4][2];
    #pragma unroll
    for (int mi = 0; mi < 4; mi++)
        #pragma unroll
        for (int h = 0; h < 2; h++) {
            int r = wm0 + mi*16 + g + h*8;
            mxr[mi][h] = fmaxf(fmaxf(red[r], red[128 + r]), fmaxf(red[256 + r], red[384 + r]));
        }
    __syncthreads();
    float sum_[4][2];
    #pragma unroll
    for (int mi = 0; mi < 4; mi++) { sum_[mi][0] = 0.f; sum_[mi][1] = 0.f; }
    #pragma unroll
    for (int ni = 0; ni < 4; ni++) {
        int cn = wn0 + ni*8 + c*2;
        bool ok0 = cn < M_, ok1 = (cn+1) < M_;
        #pragma unroll
        for (int mi = 0; mi < 4; mi++)
            #pragma unroll
            for (int h = 0; h < 2; h++) {
                float e0 = ok0 ? __expf(acc[mi][ni][2*h]   - mxr[mi][h]) : 0.f;
                float e1 = ok1 ? __expf(acc[mi][ni][2*h+1] - mxr[mi][h]) : 0.f;
                acc[mi][ni][2*h] = e0; acc[mi][ni][2*h+1] = e1;
                sum_[mi][h] += e0 + e1;
            }
    }
    #pragma unroll
    for (int mi = 0; mi < 4; mi++)
        #pragma unroll
        for (int h = 0; h < 2; h++) {
            sum_[mi][h] += __shfl_xor_sync(0xffffffffu, sum_[mi][h], 1);
            sum_[mi][h] += __shfl_xor_sync(0xffffffffu, sum_[mi][h], 2);
        }
    if (c == 0) {
        #pragma unroll
        for (int mi = 0; mi < 4; mi++)
            #pragma unroll
            for (int h = 0; h < 2; h++)
                red[(w & 3) * 128 + wm0 + mi*16 + g + h*8] = sum_[mi][h];
    }
    __syncthreads();
    #pragma unroll
    for (int mi = 0; mi < 4; mi++) {
        #pragma unroll
        for (int h = 0; h < 2; h++) {
            int r = wm0 + mi*16 + g + h*8;
            float inv = 1.f / (red[r] + red[128 + r] + red[256 + r] + red[384 + r]);
            size_t t = m0 + r;
            #pragma unroll
            for (int ni = 0; ni < 4; ni++) {
                int cn = wn0 + ni*8 + c*2;
                if (cn < M_)   logits[t*LML_ + cn]   = acc[mi][ni][2*h]   * inv;
                if (cn+1 < M_) logits[t*LML_ + cn+1] = acc[mi][ni][2*h+1] * inv;
            }
        }
    }
}

// ==================== fused launches (grid-level co-residency) ==============
// fused1: blocks [0,2000) = lin12 over 2T rows; [2000,4000) = EA n-blocks 0,1
__global__ void __launch_bounds__(256, 2) k_fused1(
    const __half* A_lin, const __half* W1, const __half* W2,
    const float* b1, const float* b2,
    __half* TD, __half* X3,
    const int* q_data, const int* attempt_data,
    const int* hint_data, const int* hintTotal_data,
    const float* q_emb, const float* attempt_emb, const float* ht_emb,
    const __half* A_ea, const __half* Wea, const float* bea, __half* EA)
{
    extern __shared__ uint32_t sm[];
    int bx = blockIdx.x;
    if (bx < 2000) {
        dev_lin12(sm, bx * 128, A_lin, W1, W2, b1, b2, TD, X3,
                  q_data, attempt_data, hint_data, hintTotal_data,
                  q_emb, attempt_emb, ht_emb);
    } else {
        int idx = bx - 2000;
        dev_ea(sm, (idx % 1000) * 128, (idx / 1000) * 128, A_ea, Wea, bea, EA);
    }
}

// fused2: blocks [0,1000) = qplog; [1000,3000) = EA n-blocks 2,3
__global__ void __launch_bounds__(256, 2) k_fused2(
    const __half* A_qp, const __half* W1, const __half* WM,
    const float* b1, const __half* TD,
    const int* time_data, const float* time_emb,
    __half* PredIn, float* logits,
    const __half* A_ea, const __half* Wea, const float* bea, __half* EA)
{
    extern __shared__ uint32_t sm[];
    int bx = blockIdx.x;
    if (bx < 1000) {
        dev_qplog(sm, bx * 128, A_qp, W1, WM, b1, TD, time_data, time_emb, PredIn, logits);
    } else {
        int idx = bx - 1000;
        dev_ea(sm, (idx % 1000) * 128, (2 + idx / 1000) * 128, A_ea, Wea, bea, EA);
    }
}

// ==================== readout GEMM (unchanged from R11) ====================
__global__ void __launch_bounds__(256, 2) k_ro(
    const __half* __restrict__ A,
    const __half* __restrict__ W,
    const float* __restrict__ bias,
    const float* __restrict__ predW, float* __restrict__ predP)
{
    constexpr int NCH = 12, LDP = 192;
    extern __shared__ uint32_t sm[];
    uint32_t* As   = sm;
    uint32_t* Bs   = sm + 3 * 2048;
    float*    sred = (float*)(sm + 6 * 2048);

    const int tid  = threadIdx.x;
    const int m0   = blockIdx.y * 128;
    const int n0   = blockIdx.x * 128;
    const int lane = tid & 31, w = tid >> 5;
    const int g    = lane >> 2, c = lane & 3;
    const int wm0  = (w >> 2) * 64;
    const int wn0  = (w & 3) * 32;
    const int srow = tid >> 2;
    const int grp  = tid & 3;

    const uint32_t* Ag = (const uint32_t*)A + (size_t)(m0 + srow) * LDP + grp * 4;
    const uint32_t* Wg = (const uint32_t*)W + (size_t)(n0 + srow) * LDP + grp * 4;
    const uint32_t asb = (uint32_t)__cvta_generic_to_shared(As) + (srow * 16 + grp * 4) * 4;
    const uint32_t bsb = (uint32_t)__cvta_generic_to_shared(Bs) + (srow * 16 + grp * 4) * 4;

    float acc[4][4][4];
    #pragma unroll
    for (int i = 0; i < 4; i++)
        #pragma unroll
        for (int j = 0; j < 4; j++)
            #pragma unroll
            for (int r = 0; r < 4; r++) acc[i][j][r] = 0.f;

    auto stage = [&](int ch, int s) {
        uint32_t ab = asb + s * 2048 * 4;
        cpa16(ab,               Ag + ch * 16);
        cpa16(ab + 64 * 16 * 4, Ag + (size_t)64 * LDP + ch * 16);
        uint32_t bb = bsb + s * 2048 * 4;
        cpa16(bb,               Wg + ch * 16);
        cpa16(bb + 64 * 16 * 4, Wg + (size_t)64 * LDP + ch * 16);
        asm volatile("cp.async.commit_group;");
    };

    stage(0, 0); stage(1, 1);
    #pragma unroll
    for (int ch = 0; ch < NCH; ch++) {
        asm volatile("cp.async.wait_group 1;");
        __syncthreads();
        if (ch + 2 < NCH) stage(ch + 2, (ch + 2) % 3);
        else asm volatile("cp.async.commit_group;");
        const uint32_t* as = As + (ch % 3) * 2048;
        const uint32_t* bs = Bs + (ch % 3) * 2048;
        uint4 alo[4], ahi[4];
        #pragma unroll
        for (int mi = 0; mi < 4; mi++) {
            alo[mi] = *(const uint4*)&as[(wm0 + mi*16 + g)     * 16 + c*4];
            ahi[mi] = *(const uint4*)&as[(wm0 + mi*16 + g + 8) * 16 + c*4];
        }
        #pragma unroll
        for (int ni = 0; ni < 4; ni++) {
            uint4 b = *(const uint4*)&bs[(wn0 + ni*8 + g) * 16 + c*4];
            #pragma unroll
            for (int mi = 0; mi < 4; mi++) {
                mma16(acc[mi][ni], alo[mi].x, ahi[mi].x, alo[mi].y, ahi[mi].y, b.x, b.y);
                mma16(acc[mi][ni], alo[mi].z, ahi[mi].z, alo[mi].w, ahi[mi].w, b.z, b.w);
            }
        }
    }

    float rsum[4][2];
    #pragma unroll
    for (int mi = 0; mi < 4; mi++) { rsum[mi][0] = 0.f; rsum[mi][1] = 0.f; }
    #pragma unroll
    for (int ni = 0; ni < 4; ni++) {
        int cn = n0 + wn0 + ni*8 + c*2;
        float b0 = __ldg(&bias[cn]),  b1 = __ldg(&bias[cn+1]);
        float p0 = __ldg(&predW[cn]), p1 = __ldg(&predW[cn+1]);
        #pragma unroll
        for (int mi = 0; mi < 4; mi++) {
            rsum[mi][0] += ftanh(acc[mi][ni][0] + b0) * p0 + ftanh(acc[mi][ni][1] + b1) * p1;
            rsum[mi][1] += ftanh(acc[mi][ni][2] + b0) * p0 + ftanh(acc[mi][ni][3] + b1) * p1;
        }
    }
    __syncthreads();
    if (tid < 128) sred[tid] = 0.f;
    __syncthreads();
    #pragma unroll
    for (int mi = 0; mi < 4; mi++)
        #pragma unroll
        for (int h = 0; h < 2; h++) {
            float v = rsum[mi][h];
            v += __shfl_xor_sync(0xffffffffu, v, 1);
            v += __shfl_xor_sync(0xffffffffu, v, 2);
            if (c == 0) atomicAdd(&sred[wm0 + mi*16 + h*8 + g], v);
        }
    __syncthreads();
    if (tid < 128) predP[(size_t)blockIdx.x * T_ + m0 + tid] = sred[tid];
}

// ==================== small kernels ====================
__global__ void k_prep(const float* __restrict__ eW, const float* __restrict__ eb,
                       const float* __restrict__ aW, const float* __restrict__ ab,
                       const float* __restrict__ d1W, const float* __restrict__ d2W,
                       const float* __restrict__ roW, const float* __restrict__ Mk)
{
    int i = blockIdx.x * blockDim.x + threadIdx.x;
    int stride = gridDim.x * blockDim.x;
    for (int j = i; j < NEA_*KEA_; j += stride) {
        int n = j / KEA_, k = j % KEA_;
        g_Wea[n*KEA_ + ph(k)] = __float2half((n < DV_) ? eW[n*KEA_ + k] : aW[(n - DV_)*KEA_ + k]);
    }
    for (int j = i; j < DQ_*DQ_; j += stride) {
        int n = j / DQ_, k = j % DQ_;
        g_Wd1[n*DQ_ + ph(k)] = __float2half(d1W[j]);
        g_Wd2[n*DQ_ + ph(k)] = __float2half(d2W[j]);
    }
    for (int j = i; j < F_*KRO_; j += stride) {
        int n = j / KRO_, k = j % KRO_;
        g_Wro[n*KRO_ + ph(k)] = __float2half(roW[j]);
    }
    for (int j = i; j < 128*DQ_; j += stride) {
        int n = j / DQ_, k = j % DQ_;
        g_Wmk[n*DQ_ + ph(k)] = __float2half(n < M_ ? Mk[n*DQ_ + k] : 0.f);
    }
    for (int j = i; j < NEA_; j += stride) g_bea[j] = (j < DV_) ? eb[j] : ab[j - DV_];
    if (i < 2) g_accum[i] = 0.f;
}

__global__ void k_gather1(const int* __restrict__ q_data, const int* __restrict__ qa_data,
                          const int* __restrict__ time_data, const int* __restrict__ attempt_data,
                          const int* __restrict__ hint_data, const int* __restrict__ hintTotal_data,
                          const float* __restrict__ q_emb, const float* __restrict__ qa_emb,
                          const float* __restrict__ time_emb, const float* __restrict__ attempt_emb,
                          const float* __restrict__ ht_emb)
{
    int t = blockIdx.x, d = threadIdx.x;
    int pd = ph(d);
    int qi = q_data[t], ti = time_data[t], ai = attempt_data[t];
    int hi = hint_data[t], hti = hintTotal_data[t];
    float qe  = q_emb[(size_t)qi*DQ_ + d];
    float te  = time_emb[(size_t)ti*DQ_ + d];
    float ae  = attempt_emb[(size_t)ai*DQ_ + d];
    float he  = ht_emb[(size_t)hi*DQ_ + d];
    float hte = ht_emb[(size_t)hti*DQ_ + d];
    g_bufX[(size_t)t*DQ_ + pd]      = __float2half(te + qe);
    g_bufX[(size_t)(T_+t)*DQ_ + pd] = __float2half(he + hte + ae + qe);
    int qai = qa_data[t];
    g_bufQA[(size_t)t*DV_ + pd]          = __float2half(qa_emb[(size_t)qai*DV_ + d]);
    g_bufQA[(size_t)t*DV_ + ph(d + DQ_)] = __float2half(qa_emb[(size_t)qai*DV_ + DQ_ + d]);
}

// DV split 2-way; per-warp ws; 3-fma update
__global__ void __launch_bounds__(128) k_scan(const float* __restrict__ Mv0)
{
    int b = blockIdx.x;
    int tidw = threadIdx.x & 31;
    int wid  = threadIdx.x >> 5;
    int d = blockIdx.y * 128 + threadIdx.x;
    int pe = ph(d);
    int pa = ph(d + DV_);
    float mv[M_];
    #pragma unroll
    for (int m = 0; m < M_; m++) mv[m] = Mv0[m*DV_ + d];
    __shared__ float ws[4][2][64];
    size_t t0 = (size_t)b * S_;
    if (tidw < M_)      ws[wid][0][tidw]      = g_logits[t0*LML_ + tidw];
    if (tidw + 32 < M_) ws[wid][0][tidw + 32] = g_logits[t0*LML_ + tidw + 32];
    float e = __half2float(g_bufEA[t0*NEA_ + pe]);
    float a = __half2float(g_bufEA[t0*NEA_ + pa]);
    __syncwarp();
    for (int s = 0; s < S_; s++) {
        size_t t = t0 + s;
        float en = 0.f, an = 0.f;
        if (s + 1 < S_) {
            en = __half2float(g_bufEA[(t+1)*NEA_ + pe]);
            an = __half2float(g_bufEA[(t+1)*NEA_ + pa]);
            int nb = (s+1) & 1;
            if (tidw < M_)      ws[wid][nb][tidw]      = g_logits[(t+1)*LML_ + tidw];
            if (tidw + 32 < M_) ws[wid][nb][tidw + 32] = g_logits[(t+1)*LML_ + tidw + 32];
        }
        const float* wcur = ws[wid][s & 1];
        float rd0 = 0.f, rd1 = 0.f;
        #pragma unroll
        for (int m = 0; m < M_; m += 2) {
            float w0 = wcur[m], w1 = wcur[m+1];
            rd0 = fmaf(w0, mv[m],   rd0);
            rd1 = fmaf(w1, mv[m+1], rd1);
            mv[m]   = fmaf(w0, fmaf(-e, mv[m],   a), mv[m]);
            mv[m+1] = fmaf(w1, fmaf(-e, mv[m+1], a), mv[m+1]);
        }
        g_PredIn[t*KRO_ + pe] = __float2half(rd0 + rd1);
        __syncwarp();
        e = en; a = an;
    }
}

__global__ void k_loss(const int* __restrict__ target, const float* __restrict__ pred_b,
                       float* __restrict__ out)
{
    int i = blockIdx.x * blockDim.x + threadIdx.x;
    float le = 0.f, cnt = 0.f;
    if (i < T_) {
        float p = g_predP[0][i] + g_predP[1][i] + g_predP[2][i] + g_predP[3][i] + pred_b[0];
        int tg = target[i];
        bool mask = tg >= 1;
        float y = mask ? (float)(tg - 1) : 0.f;
        float sig = 1.f / (1.f + expf(-p));
        out[1 + i]      = mask ? sig : 0.f;
        out[1 + T_ + i] = mask ? y   : 0.f;
        if (mask) {
            le = fmaxf(p, 0.f) + log1pf(expf(-fabsf(p))) - p * y;
            cnt = 1.f;
        }
    }
    __shared__ float sle[256], scn[256];
    sle[threadIdx.x] = le; scn[threadIdx.x] = cnt;
    __syncthreads();
    for (int o = 128; o; o >>= 1) {
        if (threadIdx.x < o) { sle[threadIdx.x] += sle[threadIdx.x + o]; scn[threadIdx.x] += scn[threadIdx.x + o]; }
        __syncthreads();
    }
    if (threadIdx.x == 0) { atomicAdd(&g_accum[0], sle[0]); atomicAdd(&g_accum[1], scn[0]); }
}

__global__ void k_final(float* __restrict__ out)
{
    out[0] = g_accum[0] / fmaxf(g_accum[1], 1.f);
}

// ==================== host ====================
extern "C" void kernel_launch(void* const* d_in, const int* in_sizes, int n_in,
                              void* d_out, int out_size)
{
    const int*   q_data      = (const int*)  d_in[0];
    const int*   qa_data     = (const int*)  d_in[1];
    const int*   target      = (const int*)  d_in[2];
    const int*   time_data   = (const int*)  d_in[3];
    const int*   attempt_data= (const int*)  d_in[4];
    const int*   hint_data   = (const int*)  d_in[5];
    const int*   hintTotal   = (const int*)  d_in[6];
    const float* q_emb       = (const float*)d_in[7];
    const float* qa_emb      = (const float*)d_in[8];
    const float* time_emb    = (const float*)d_in[9];
    const float* attempt_emb = (const float*)d_in[10];
    const float* ht_emb      = (const float*)d_in[11];
    const float* Mk          = (const float*)d_in[12];
    const float* Mv0         = (const float*)d_in[13];
    const float* diff_W      = (const float*)d_in[14];
    const float* diff_b      = (const float*)d_in[15];
    const float* diff2_W     = (const float*)d_in[16];
    const float* diff2_b     = (const float*)d_in[17];
    const float* erase_W     = (const float*)d_in[18];
    const float* erase_b     = (const float*)d_in[19];
    const float* add_W       = (const float*)d_in[20];
    const float* add_b       = (const float*)d_in[21];
    const float* read_W      = (const float*)d_in[22];
    const float* read_b      = (const float*)d_in[23];
    const float* pred_W      = (const float*)d_in[24];
    const float* pred_b      = (const float*)d_in[25];
    float* out = (float*)d_out;

    __half *bufX, *bufX3, *bufTD, *bufQA, *bufEA, *predin;
    __half *Wea, *Wd1, *Wd2, *Wro, *Wmk;
    float *logits, *predP, *bea;
    cudaGetSymbolAddress((void**)&bufX,   g_bufX);
    cudaGetSymbolAddress((void**)&bufX3,  g_bufX3);
    cudaGetSymbolAddress((void**)&bufTD,  g_bufTD);
    cudaGetSymbolAddress((void**)&bufQA,  g_bufQA);
    cudaGetSymbolAddress((void**)&bufEA,  g_bufEA);
    cudaGetSymbolAddress((void**)&predin, g_PredIn);
    cudaGetSymbolAddress((void**)&logits, g_logits);
    cudaGetSymbolAddress((void**)&predP,  g_predP);
    cudaGetSymbolAddress((void**)&Wea,    g_Wea);
    cudaGetSymbolAddress((void**)&Wd1,    g_Wd1);
    cudaGetSymbolAddress((void**)&Wd2,    g_Wd2);
    cudaGetSymbolAddress((void**)&Wro,    g_Wro);
    cudaGetSymbolAddress((void**)&Wmk,    g_Wmk);
    cudaGetSymbolAddress((void**)&bea,    g_bea);

    const int SMG = (6*2048 + 128) * 4;                 // 49664
    const int SML = (6*2048 + 128*USTR) * 4;            // 90112
    const int SMQ = (6*2048 + 128*USTR + 512) * 4;      // 92160
    cudaFuncSetAttribute(k_fused1, cudaFuncAttributeMaxDynamicSharedMemorySize, SML);
    cudaFuncSetAttribute(k_fused2, cudaFuncAttributeMaxDynamicSharedMemorySize, SMQ);
    cudaFuncSetAttribute(k_ro,     cudaFuncAttributeMaxDynamicSharedMemorySize, SMG);

    k_prep<<<1024, 256>>>(erase_W, erase_b, add_W, add_b, diff_W, diff2_W, read_W, Mk);
    k_gather1<<<T_, 128>>>(q_data, qa_data, time_data, attempt_data, hint_data, hintTotal,
                           q_emb, qa_emb, time_emb, attempt_emb, ht_emb);
    // fused: lin12 (2000 blocks) + EA n-blocks 0,1 (2000 blocks)
    k_fused1<<<4000, 256, SML>>>(bufX, Wd1, Wd2, diff_b, diff2_b, bufTD, bufX3,
                                 q_data, attempt_data, hint_data, hintTotal,
                                 q_emb, attempt_emb, ht_emb,
                                 bufQA, Wea, bea, bufEA);
    // fused: qplog (1000 blocks) + EA n-blocks 2,3 (2000 blocks)
    k_fused2<<<3000, 256, SMQ>>>(bufX3, Wd1, Wmk, diff_b, bufTD,
                                 time_data, time_emb, predin, logits,
                                 bufQA, Wea, bea, bufEA);
    k_scan<<<dim3(B_, 2), 128>>>(Mv0);
    k_ro<<<dim3(4, 1000), 256, SMG>>>(predin, Wro, read_b, pred_W, predP);
    k_loss<<<(T_ + 255)/256, 256>>>(target, pred_b, out);
    k_final<<<1, 1>>>(out);
}

// round 13
// speedup vs baseline: 4.2813x; 1.0932x over previous
#include <cuda_runtime.h>
#include <cuda_fp16.h>
#include <math.h>
#include <stdint.h>

#define B_   256
#define S_   500
#define T_   (B_*S_)        // 128000
#define DQ_  128
#define DV_  256
#define M_   50
#define F_   512
#define NEA_ 512
#define KEA_ 256
#define KRO_ 384
#define LML_ 64
#define USTR 80

// ---------------- scratch (device globals) ----------------
__device__ __half g_bufX [2*T_*DQ_];
__device__ __half g_bufX3[T_*DQ_];
__device__ __half g_bufTD[T_*DQ_];
__device__ __half g_bufQA[T_*DV_];
__device__ __half g_bufEA[T_*NEA_];
__device__ __half g_PredIn[T_*KRO_];
__device__ float  g_logits[T_*LML_];
__device__ float  g_predP[4][T_];
__device__ float  g_accum[2];
__device__ __half g_Wea[NEA_*KEA_];
__device__ __half g_Wd1[DQ_*DQ_];
__device__ __half g_Wd2[DQ_*DQ_];
__device__ __half g_Wro[F_*KRO_];
__device__ __half g_Wmk[128*DQ_];
__device__ float  g_bea[NEA_];

// ==================== helpers ====================
__device__ __forceinline__ int ph(int d) {
    int pair = d >> 1;
    int pi   = pair & 15;
    int pp   = (pair & ~15) | ((pi & 3) * 4 + (pi >> 2));
    return pp * 2 + (d & 1);
}
__device__ __forceinline__ int permc(int cn) {
    int pair = cn >> 1;
    int pi   = pair & 15;
    int pp   = (pair & ~15) | ((pi & 3) * 4 + (pi >> 2));
    return pp * 2;
}
__device__ __forceinline__ float fsig(float x) { return 1.f / (1.f + __expf(-x)); }
__device__ __forceinline__ float ftanh(float x) {
    float ax = fabsf(x);
    float t  = 1.f - 2.f / (1.f + __expf(2.f * ax));
    return copysignf(t, x);
}
__device__ __forceinline__ void mma16(float* d,
    uint32_t a0, uint32_t a1, uint32_t a2, uint32_t a3,
    uint32_t b0, uint32_t b1)
{
    asm volatile(
        "mma.sync.aligned.m16n8k16.row.col.f32.f16.f16.f32 "
        "{%0,%1,%2,%3},{%4,%5,%6,%7},{%8,%9},{%0,%1,%2,%3};"
        : "+f"(d[0]), "+f"(d[1]), "+f"(d[2]), "+f"(d[3])
        : "r"(a0), "r"(a1), "r"(a2), "r"(a3), "r"(b0), "r"(b1));
}
__device__ __forceinline__ void cpa16(uint32_t dst, const void* src) {
    asm volatile("cp.async.cg.shared.global [%0], [%1], 16;" :: "r"(dst), "l"(src));
}
// packed f32x2 (sm_100-family base PTX)
__device__ __forceinline__ unsigned long long pk2(float lo, float hi) {
    unsigned long long r;
    asm("mov.b64 %0, {%1, %2};" : "=l"(r) : "f"(lo), "f"(hi));
    return r;
}
__device__ __forceinline__ float2 upk2(unsigned long long v) {
    float2 r;
    asm("mov.b64 {%0, %1}, %2;" : "=f"(r.x), "=f"(r.y) : "l"(v));
    return r;
}
__device__ __forceinline__ unsigned long long fma2(
    unsigned long long a, unsigned long long b, unsigned long long c)
{
    unsigned long long d;
    asm("fma.rn.f32x2 %0, %1, %2, %3;" : "=l"(d) : "l"(a), "l"(b), "l"(c));
    return d;
}

// ==================== device GEMM body: EA (K=256, perm store) ==============
__device__ __forceinline__ void dev_ea(uint32_t* sm, int m0, int n0,
    const __half* __restrict__ A, const __half* __restrict__ W,
    const float* __restrict__ bias, __half* __restrict__ C)
{
    constexpr int NCH = 8, LDP = 128;
    uint32_t* As = sm;
    uint32_t* Bs = sm + 3 * 2048;

    const int tid  = threadIdx.x;
    const int lane = tid & 31, w = tid >> 5;
    const int g    = lane >> 2, c = lane & 3;
    const int wm0  = (w >> 2) * 64;
    const int wn0  = (w & 3) * 32;
    const int srow = tid >> 2;
    const int grp  = tid & 3;

    const uint32_t* Ag = (const uint32_t*)A + (size_t)(m0 + srow) * LDP + grp * 4;
    const uint32_t* Wg = (const uint32_t*)W + (size_t)(n0 + srow) * LDP + grp * 4;
    const uint32_t asb = (uint32_t)__cvta_generic_to_shared(As) + (srow * 16 + grp * 4) * 4;
    const uint32_t bsb = (uint32_t)__cvta_generic_to_shared(Bs) + (srow * 16 + grp * 4) * 4;

    float acc[4][4][4];
    #pragma unroll
    for (int i = 0; i < 4; i++)
        #pragma unroll
        for (int j = 0; j < 4; j++)
            #pragma unroll
            for (int r = 0; r < 4; r++) acc[i][j][r] = 0.f;

    auto stage = [&](int ch, int s) {
        uint32_t ab = asb + s * 2048 * 4;
        cpa16(ab,               Ag + ch * 16);
        cpa16(ab + 64 * 16 * 4, Ag + (size_t)64 * LDP + ch * 16);
        uint32_t bb = bsb + s * 2048 * 4;
        cpa16(bb,               Wg + ch * 16);
        cpa16(bb + 64 * 16 * 4, Wg + (size_t)64 * LDP + ch * 16);
        asm volatile("cp.async.commit_group;");
    };

    stage(0, 0); stage(1, 1);
    #pragma unroll
    for (int ch = 0; ch < NCH; ch++) {
        asm volatile("cp.async.wait_group 1;");
        __syncthreads();
        if (ch + 2 < NCH) stage(ch + 2, (ch + 2) % 3);
        else asm volatile("cp.async.commit_group;");
        const uint32_t* as = As + (ch % 3) * 2048;
        const uint32_t* bs = Bs + (ch % 3) * 2048;
        uint4 alo[4], ahi[4];
        #pragma unroll
        for (int mi = 0; mi < 4; mi++) {
            alo[mi] = *(const uint4*)&as[(wm0 + mi*16 + g)     * 16 + c*4];
            ahi[mi] = *(const uint4*)&as[(wm0 + mi*16 + g + 8) * 16 + c*4];
        }
        #pragma unroll
        for (int ni = 0; ni < 4; ni++) {
            uint4 b = *(const uint4*)&bs[(wn0 + ni*8 + g) * 16 + c*4];
            #pragma unroll
            for (int mi = 0; mi < 4; mi++) {
                mma16(acc[mi][ni], alo[mi].x, ahi[mi].x, alo[mi].y, ahi[mi].y, b.x, b.y);
                mma16(acc[mi][ni], alo[mi].z, ahi[mi].z, alo[mi].w, ahi[mi].w, b.z, b.w);
            }
        }
    }

    #pragma unroll
    for (int ni = 0; ni < 4; ni++) {
        int cn  = n0 + wn0 + ni*8 + c*2;
        int cnp = permc(cn);
        float b0 = __ldg(&bias[cn]), b1 = __ldg(&bias[cn+1]);
        #pragma unroll
        for (int mi = 0; mi < 4; mi++) {
            int r0 = m0 + wm0 + mi*16 + g;
            float v0 = acc[mi][ni][0] + b0, v1 = acc[mi][ni][1] + b1;
            float v2 = acc[mi][ni][2] + b0, v3 = acc[mi][ni][3] + b1;
            if (cn < DV_) { v0 = fsig(v0); v1 = fsig(v1); v2 = fsig(v2); v3 = fsig(v3); }
            else          { v0 = ftanh(v0); v1 = ftanh(v1); v2 = ftanh(v2); v3 = ftanh(v3); }
            *(__half2*)&C[(size_t)r0    *NEA_ + cnp] = __floats2half2_rn(v0, v1);
            *(__half2*)&C[(size_t)(r0+8)*NEA_ + cnp] = __floats2half2_rn(v2, v3);
        }
    }
}

// ==================== device body: lin12 ====================
__device__ __forceinline__ void dev_lin12(uint32_t* sm, int m0,
    const __half* __restrict__ A,
    const __half* __restrict__ W1, const __half* __restrict__ W2,
    const float* __restrict__ b1, const float* __restrict__ b2,
    __half* __restrict__ TD, __half* __restrict__ X3,
    const int* __restrict__ q_data, const int* __restrict__ attempt_data,
    const int* __restrict__ hint_data, const int* __restrict__ hintTotal_data,
    const float* __restrict__ q_emb, const float* __restrict__ attempt_emb,
    const float* __restrict__ ht_emb)
{
    uint32_t* Xs = sm;
    uint32_t* Bs = sm + 3*2048;
    uint32_t* Us = sm + 6*2048;

    const int tid  = threadIdx.x;
    const int lane = tid & 31, w = tid >> 5;
    const int g    = lane >> 2, c = lane & 3;
    const int wm0  = (w >> 2) * 64;
    const int wn0  = (w & 3) * 32;
    const int srow = tid >> 2;
    const int grp  = tid & 3;

    const uint32_t* Ag  = (const uint32_t*)A  + (size_t)(m0 + srow) * 64 + grp * 4;
    const uint32_t* W1g = (const uint32_t*)W1 + (size_t)srow * 64 + grp * 4;
    const uint32_t* W2g = (const uint32_t*)W2 + (size_t)srow * 64 + grp * 4;

    const uint32_t xsb = (uint32_t)__cvta_generic_to_shared(Xs) + (srow*16 + grp*4) * 4;
    const uint32_t bsb = (uint32_t)__cvta_generic_to_shared(Bs) + (srow*16 + grp*4) * 4;

    float acc[4][4][4];
    #pragma unroll
    for (int i = 0; i < 4; i++)
        #pragma unroll
        for (int j = 0; j < 4; j++)
            #pragma unroll
            for (int r = 0; r < 4; r++) acc[i][j][r] = 0.f;

    auto stage1 = [&](int ch, int s) {
        uint32_t xb = xsb + s * 2048 * 4;
        cpa16(xb,           Ag + ch * 16);
        cpa16(xb + 64*16*4, Ag + (size_t)64*64 + ch * 16);
        uint32_t bb = bsb + s * 2048 * 4;
        cpa16(bb,           W1g + ch * 16);
        cpa16(bb + 64*16*4, W1g + (size_t)64*64 + ch * 16);
        asm volatile("cp.async.commit_group;");
    };

    stage1(0, 0); stage1(1, 1);
    #pragma unroll
    for (int ch = 0; ch < 4; ch++) {
        asm volatile("cp.async.wait_group 1;");
        __syncthreads();
        if (ch + 2 < 4) stage1(ch + 2, (ch + 2) % 3);
        else asm volatile("cp.async.commit_group;");
        const uint32_t* xs = Xs + (ch % 3) * 2048;
        const uint32_t* bs = Bs + (ch % 3) * 2048;
        uint4 alo[4], ahi[4];
        #pragma unroll
        for (int mi = 0; mi < 4; mi++) {
            alo[mi] = *(const uint4*)&xs[(wm0 + mi*16 + g)     * 16 + c*4];
            ahi[mi] = *(const uint4*)&xs[(wm0 + mi*16 + g + 8) * 16 + c*4];
        }
        #pragma unroll
        for (int ni = 0; ni < 4; ni++) {
            uint4 b = *(const uint4*)&bs[(wn0 + ni*8 + g) * 16 + c*4];
            #pragma unroll
            for (int mi = 0; mi < 4; mi++) {
                mma16(acc[mi][ni], alo[mi].x, ahi[mi].x, alo[mi].y, ahi[mi].y, b.x, b.y);
                mma16(acc[mi][ni], alo[mi].z, ahi[mi].z, alo[mi].w, ahi[mi].w, b.z, b.w);
            }
        }
    }
    asm volatile("cp.async.wait_group 0;");

    #pragma unroll
    for (int ni = 0; ni < 4; ni++) {
        int cn = wn0 + ni*8 + c*2;
        float bb0 = __ldg(&b1[cn]), bb1 = __ldg(&b1[cn+1]);
        int pw = permc(cn) >> 1;
        #pragma unroll
        for (int mi = 0; mi < 4; mi++) {
            int r0 = wm0 + mi*16 + g;
            __half2 h0 = __floats2half2_rn(ftanh(acc[mi][ni][0] + bb0), ftanh(acc[mi][ni][1] + bb1));
            __half2 h1 = __floats2half2_rn(ftanh(acc[mi][ni][2] + bb0), ftanh(acc[mi][ni][3] + bb1));
            Us[r0*USTR + pw]     = *(uint32_t*)&h0;
            Us[(r0+8)*USTR + pw] = *(uint32_t*)&h1;
            acc[mi][ni][0] = acc[mi][ni][1] = acc[mi][ni][2] = acc[mi][ni][3] = 0.f;
        }
    }
    __syncthreads();

    auto stage2 = [&](int ch, int s) {
        uint32_t bb = bsb + s * 2048 * 4;
        cpa16(bb,           W2g + ch * 16);
        cpa16(bb + 64*16*4, W2g + (size_t)64*64 + ch * 16);
        asm volatile("cp.async.commit_group;");
    };
    stage2(0, 0); stage2(1, 1);
    #pragma unroll
    for (int ch = 0; ch < 4; ch++) {
        asm volatile("cp.async.wait_group 1;");
        __syncthreads();
        if (ch + 2 < 4) stage2(ch + 2, (ch + 2) % 3);
        else asm volatile("cp.async.commit_group;");
        const uint32_t* bs = Bs + (ch % 3) * 2048;
        uint4 alo[4], ahi[4];
        #pragma unroll
        for (int mi = 0; mi < 4; mi++) {
            alo[mi] = *(const uint4*)&Us[(wm0 + mi*16 + g)     * USTR + ch*16 + c*4];
            ahi[mi] = *(const uint4*)&Us[(wm0 + mi*16 + g + 8) * USTR + ch*16 + c*4];
        }
        #pragma unroll
        for (int ni = 0; ni < 4; ni++) {
            uint4 b = *(const uint4*)&bs[(wn0 + ni*8 + g) * 16 + c*4];
            #pragma unroll
            for (int mi = 0; mi < 4; mi++) {
                mma16(acc[mi][ni], alo[mi].x, ahi[mi].x, alo[mi].y, ahi[mi].y, b.x, b.y);
                mma16(acc[mi][ni], alo[mi].z, ahi[mi].z, alo[mi].w, ahi[mi].w, b.z, b.w);
            }
        }
    }

    const bool isdiff = (m0 >= T_);
    #pragma unroll
    for (int mi = 0; mi < 4; mi++) {
        #pragma unroll
        for (int h = 0; h < 2; h++) {
            int r = wm0 + mi*16 + g + h*8;
            int t = m0 + r;
            if (!isdiff) {
                #pragma unroll
                for (int ni = 0; ni < 4; ni++) {
                    int cn = wn0 + ni*8 + c*2;
                    float v0 = fsig(acc[mi][ni][2*h]   + __ldg(&b2[cn]));
                    float v1 = fsig(acc[mi][ni][2*h+1] + __ldg(&b2[cn+1]));
                    *(__half2*)&TD[(size_t)t*DQ_ + cn] = __floats2half2_rn(v0, v1);
                }
            } else {
                int tt = t - T_;
                int qi = q_data[tt], ai = attempt_data[tt];
                int hi = hint_data[tt], hti = hintTotal_data[tt];
                #pragma unroll
                for (int ni = 0; ni < 4; ni++) {
                    int cn = wn0 + ni*8 + c*2;
                    float v0 = fsig(acc[mi][ni][2*h]   + __ldg(&b2[cn]));
                    float v1 = fsig(acc[mi][ni][2*h+1] + __ldg(&b2[cn+1]));
                    float qe0 = q_emb[(size_t)qi*DQ_ + cn],   qe1 = q_emb[(size_t)qi*DQ_ + cn+1];
                    float g0  = attempt_emb[(size_t)ai*DQ_ + cn]
                              + ht_emb[(size_t)hi*DQ_ + cn] + ht_emb[(size_t)hti*DQ_ + cn];
                    float g1  = attempt_emb[(size_t)ai*DQ_ + cn+1]
                              + ht_emb[(size_t)hi*DQ_ + cn+1] + ht_emb[(size_t)hti*DQ_ + cn+1];
                    *(__half2*)&X3[(size_t)tt*DQ_ + permc(cn)] =
                        __floats2half2_rn(fmaf(v0, g0, qe0), fmaf(v1, g1, qe1));
                }
            }
        }
    }
}

// ==================== device body: qplog ====================
__device__ __forceinline__ void dev_qplog(uint32_t* sm, int m0,
    const __half* __restrict__ A,
    const __half* __restrict__ W1, const __half* __restrict__ WM,
    const float* __restrict__ b1, const __half* __restrict__ TD,
    const int* __restrict__ time_data, const float* __restrict__ time_emb,
    __half* __restrict__ PredIn, float* __restrict__ logits)
{
    uint32_t* Xs  = sm;
    uint32_t* Bs  = sm + 3*2048;
    uint32_t* Us  = sm + 6*2048;
    float*    red = (float*)(sm + 6*2048 + 128*USTR);

    const int tid  = threadIdx.x;
    const int lane = tid & 31, w = tid >> 5;
    const int g    = lane >> 2, c = lane & 3;
    const int wm0  = (w >> 2) * 64;
    const int wn0  = (w & 3) * 32;
    const int srow = tid >> 2;
    const int grp  = tid & 3;

    const uint32_t* Ag  = (const uint32_t*)A  + (size_t)(m0 + srow) * 64 + grp * 4;
    const uint32_t* W1g = (const uint32_t*)W1 + (size_t)srow * 64 + grp * 4;
    const uint32_t* WMg = (const uint32_t*)WM + (size_t)srow * 64 + grp * 4;

    const uint32_t xsb = (uint32_t)__cvta_generic_to_shared(Xs) + (srow*16 + grp*4) * 4;
    const uint32_t bsb = (uint32_t)__cvta_generic_to_shared(Bs) + (srow*16 + grp*4) * 4;

    float acc[4][4][4];
    #pragma unroll
    for (int i = 0; i < 4; i++)
        #pragma unroll
        for (int j = 0; j < 4; j++)
            #pragma unroll
            for (int r = 0; r < 4; r++) acc[i][j][r] = 0.f;

    auto stage1 = [&](int ch, int s) {
        uint32_t xb = xsb + s * 2048 * 4;
        cpa16(xb,           Ag + ch * 16);
        cpa16(xb + 64*16*4, Ag + (size_t)64*64 + ch * 16);
        uint32_t bb = bsb + s * 2048 * 4;
        cpa16(bb,           W1g + ch * 16);
        cpa16(bb + 64*16*4, W1g + (size_t)64*64 + ch * 16);
        asm volatile("cp.async.commit_group;");
    };
    stage1(0, 0); stage1(1, 1);
    #pragma unroll
    for (int ch = 0; ch < 4; ch++) {
        asm volatile("cp.async.wait_group 1;");
        __syncthreads();
        if (ch + 2 < 4) stage1(ch + 2, (ch + 2) % 3);
        else asm volatile("cp.async.commit_group;");
        const uint32_t* xs = Xs + (ch % 3) * 2048;
        const uint32_t* bs = Bs + (ch % 3) * 2048;
        uint4 alo[4], ahi[4];
        #pragma unroll
        for (int mi = 0; mi < 4; mi++) {
            alo[mi] = *(const uint4*)&xs[(wm0 + mi*16 + g)     * 16 + c*4];
            ahi[mi] = *(const uint4*)&xs[(wm0 + mi*16 + g + 8) * 16 + c*4];
        }
        #pragma unroll
        for (int ni = 0; ni < 4; ni++) {
            uint4 b = *(const uint4*)&bs[(wn0 + ni*8 + g) * 16 + c*4];
            #pragma unroll
            for (int mi = 0; mi < 4; mi++) {
                mma16(acc[mi][ni], alo[mi].x, ahi[mi].x, alo[mi].y, ahi[mi].y, b.x, b.y);
                mma16(acc[mi][ni], alo[mi].z, ahi[mi].z, alo[mi].w, ahi[mi].w, b.z, b.w);
            }
        }
    }
    asm volatile("cp.async.wait_group 0;");

    #pragma unroll
    for (int mi = 0; mi < 4; mi++) {
        #pragma unroll
        for (int h = 0; h < 2; h++) {
            int r = wm0 + mi*16 + g + h*8;
            int t = m0 + r;
            int ti = time_data[t];
            #pragma unroll
            for (int ni = 0; ni < 4; ni++) {
                int cn = wn0 + ni*8 + c*2;
                float q0 = acc[mi][ni][2*h]   + __ldg(&b1[cn]);
                float q1 = acc[mi][ni][2*h+1] + __ldg(&b1[cn+1]);
                __half2 hq = __floats2half2_rn(q0, q1);
                Us[r*USTR + (permc(cn) >> 1)] = *(uint32_t*)&hq;
                float2 qp2 = __half22float2(hq);
                __half2 tfh = *(const __half2*)&TD[(size_t)t*DQ_ + cn];
                float2 tf2 = __half22float2(tfh);
                float te0 = time_emb[(size_t)ti*DQ_ + cn], te1 = time_emb[(size_t)ti*DQ_ + cn+1];
                *(__half2*)&PredIn[(size_t)t*KRO_ + DV_ + permc(cn)] =
                    __floats2half2_rn(fmaf(tf2.x, te0, qp2.x), fmaf(tf2.y, te1, qp2.y));
                acc[mi][ni][2*h] = 0.f; acc[mi][ni][2*h+1] = 0.f;
            }
        }
    }
    __syncthreads();

    auto stage2 = [&](int ch, int s) {
        uint32_t bb = bsb + s * 2048 * 4;
        cpa16(bb,           WMg + ch * 16);
        cpa16(bb + 64*16*4, WMg + (size_t)64*64 + ch * 16);
        asm volatile("cp.async.commit_group;");
    };
    stage2(0, 0); stage2(1, 1);
    #pragma unroll
    for (int ch = 0; ch < 4; ch++) {
        asm volatile("cp.async.wait_group 1;");
        __syncthreads();
        if (ch + 2 < 4) stage2(ch + 2, (ch + 2) % 3);
        else asm volatile("cp.async.commit_group;");
        const uint32_t* bs = Bs + (ch % 3) * 2048;
        uint4 alo[4], ahi[4];
        #pragma unroll
        for (int mi = 0; mi < 4; mi++) {
            alo[mi] = *(const uint4*)&Us[(wm0 + mi*16 + g)     * USTR + ch*16 + c*4];
            ahi[mi] = *(const uint4*)&Us[(wm0 + mi*16 + g + 8) * USTR + ch*16 + c*4];
        }
        #pragma unroll
        for (int ni = 0; ni < 4; ni++) {
            uint4 b = *(const uint4*)&bs[(wn0 + ni*8 + g) * 16 + c*4];
            #pragma unroll
            for (int mi = 0; mi < 4; mi++) {
                mma16(acc[mi][ni], alo[mi].x, ahi[mi].x, alo[mi].y, ahi[mi].y, b.x, b.y);
                mma16(acc[mi][ni], alo[mi].z, ahi[mi].z, alo[mi].w, ahi[mi].w, b.z, b.w);
            }
        }
    }

    float mx[4][2];
    #pragma unroll
    for (int mi = 0; mi < 4; mi++) { mx[mi][0] = -1e30f; mx[mi][1] = -1e30f; }
    #pragma unroll
    for (int ni = 0; ni < 4; ni++) {
        int cn = wn0 + ni*8 + c*2;
        bool ok0 = cn < M_, ok1 = (cn+1) < M_;
        #pragma unroll
        for (int mi = 0; mi < 4; mi++)
            #pragma unroll
            for (int h = 0; h < 2; h++) {
                if (ok0) mx[mi][h] = fmaxf(mx[mi][h], acc[mi][ni][2*h]);
                if (ok1) mx[mi][h] = fmaxf(mx[mi][h], acc[mi][ni][2*h+1]);
            }
    }
    #pragma unroll
    for (int mi = 0; mi < 4; mi++)
        #pragma unroll
        for (int h = 0; h < 2; h++) {
            mx[mi][h] = fmaxf(mx[mi][h], __shfl_xor_sync(0xffffffffu, mx[mi][h], 1));
            mx[mi][h] = fmaxf(mx[mi][h], __shfl_xor_sync(0xffffffffu, mx[mi][h], 2));
        }
    __syncthreads();
    if (c == 0) {
        #pragma unroll
        for (int mi = 0; mi < 4; mi++)
            #pragma unroll
            for (int h = 0; h < 2; h++)
                red[(w & 3) * 128 + wm0 + mi*16 + g + h*8] = mx[mi][h];
    }
    __syncthreads();
    float mxr[4][2];
    #pragma unroll
    for (int mi = 0; mi < 4; mi++)
        #pragma unroll
        for (int h = 0; h < 2; h++) {
            int r = wm0 + mi*16 + g + h*8;
            mxr[mi][h] = fmaxf(fmaxf(red[r], red[128 + r]), fmaxf(red[256 + r], red[384 + r]));
        }
    __syncthreads();
    float sum_[4][2];
    #pragma unroll
    for (int mi = 0; mi < 4; mi++) { sum_[mi][0] = 0.f; sum_[mi][1] = 0.f; }
    #pragma unroll
    for (int ni = 0; ni < 4; ni++) {
        int cn = wn0 + ni*8 + c*2;
        bool ok0 = cn < M_, ok1 = (cn+1) < M_;
        #pragma unroll
        for (int mi = 0; mi < 4; mi++)
            #pragma unroll
            for (int h = 0; h < 2; h++) {
                float e0 = ok0 ? __expf(acc[mi][ni][2*h]   - mxr[mi][h]) : 0.f;
                float e1 = ok1 ? __expf(acc[mi][ni][2*h+1] - mxr[mi][h]) : 0.f;
                acc[mi][ni][2*h] = e0; acc[mi][ni][2*h+1] = e1;
                sum_[mi][h] += e0 + e1;
            }
    }
    #pragma unroll
    for (int mi = 0; mi < 4; mi++)
        #pragma unroll
        for (int h = 0; h < 2; h++) {
            sum_[mi][h] += __shfl_xor_sync(0xffffffffu, sum_[mi][h], 1);
            sum_[mi][h] += __shfl_xor_sync(0xffffffffu, sum_[mi][h], 2);
        }
    if (c == 0) {
        #pragma unroll
        for (int mi = 0; mi < 4; mi++)
            #pragma unroll
            for (int h = 0; h < 2; h++)
                red[(w & 3) * 128 + wm0 + mi*16 + g + h*8] = sum_[mi][h];
    }
    __syncthreads();
    #pragma unroll
    for (int mi = 0; mi < 4; mi++) {
        #pragma unroll
        for (int h = 0; h < 2; h++) {
            int r = wm0 + mi*16 + g + h*8;
            float inv = 1.f / (red[r] + red[128 + r] + red[256 + r] + red[384 + r]);
            size_t t = m0 + r;
            #pragma unroll
            for (int ni = 0; ni < 4; ni++) {
                int cn = wn0 + ni*8 + c*2;
                if (cn < M_)   logits[t*LML_ + cn]   = acc[mi][ni][2*h]   * inv;
                if (cn+1 < M_) logits[t*LML_ + cn+1] = acc[mi][ni][2*h+1] * inv;
            }
        }
    }
}

// ==================== fused launches ====================
__global__ void __launch_bounds__(256, 2) k_fused1(
    const __half* A_lin, const __half* W1, const __half* W2,
    const float* b1, const float* b2,
    __half* TD, __half* X3,
    const int* q_data, const int* attempt_data,
    const int* hint_data, const int* hintTotal_data,
    const float* q_emb, const float* attempt_emb, const float* ht_emb,
    const __half* A_ea, const __half* Wea, const float* bea, __half* EA)
{
    extern __shared__ uint32_t sm[];
    int bx = blockIdx.x;
    if (bx < 2000) {
        dev_lin12(sm, bx * 128, A_lin, W1, W2, b1, b2, TD, X3,
                  q_data, attempt_data, hint_data, hintTotal_data,
                  q_emb, attempt_emb, ht_emb);
    } else {
        int idx = bx - 2000;
        dev_ea(sm, (idx % 1000) * 128, (idx / 1000) * 128, A_ea, Wea, bea, EA);
    }
}

__global__ void __launch_bounds__(256, 2) k_fused2(
    const __half* A_qp, const __half* W1, const __half* WM,
    const float* b1, const __half* TD,
    const int* time_data, const float* time_emb,
    __half* PredIn, float* logits,
    const __half* A_ea, const __half* Wea, const float* bea, __half* EA)
{
    extern __shared__ uint32_t sm[];
    int bx = blockIdx.x;
    if (bx < 1000) {
        dev_qplog(sm, bx * 128, A_qp, W1, WM, b1, TD, time_data, time_emb, PredIn, logits);
    } else {
        int idx = bx - 1000;
        dev_ea(sm, (idx % 1000) * 128, (2 + idx / 1000) * 128, A_ea, Wea, bea, EA);
    }
}

// ==================== readout GEMM ====================
__global__ void __launch_bounds__(256, 2) k_ro(
    const __half* __restrict__ A,
    const __half* __restrict__ W,
    const float* __restrict__ bias,
    const float* __restrict__ predW, float* __restrict__ predP)
{
    constexpr int NCH = 12, LDP = 192;
    extern __shared__ uint32_t sm[];
    uint32_t* As   = sm;
    uint32_t* Bs   = sm + 3 * 2048;
    float*    sred = (float*)(sm + 6 * 2048);

    const int tid  = threadIdx.x;
    const int m0   = blockIdx.y * 128;
    const int n0   = blockIdx.x * 128;
    const int lane = tid & 31, w = tid >> 5;
    const int g    = lane >> 2, c = lane & 3;
    const int wm0  = (w >> 2) * 64;
    const int wn0  = (w & 3) * 32;
    const int srow = tid >> 2;
    const int grp  = tid & 3;

    const uint32_t* Ag = (const uint32_t*)A + (size_t)(m0 + srow) * LDP + grp * 4;
    const uint32_t* Wg = (const uint32_t*)W + (size_t)(n0 + srow) * LDP + grp * 4;
    const uint32_t asb = (uint32_t)__cvta_generic_to_shared(As) + (srow * 16 + grp * 4) * 4;
    const uint32_t bsb = (uint32_t)__cvta_generic_to_shared(Bs) + (srow * 16 + grp * 4) * 4;

    float acc[4][4][4];
    #pragma unroll
    for (int i = 0; i < 4; i++)
        #pragma unroll
        for (int j = 0; j < 4; j++)
            #pragma unroll
            for (int r = 0; r < 4; r++) acc[i][j][r] = 0.f;

    auto stage = [&](int ch, int s) {
        uint32_t ab = asb + s * 2048 * 4;
        cpa16(ab,               Ag + ch * 16);
        cpa16(ab + 64 * 16 * 4, Ag + (size_t)64 * LDP + ch * 16);
        uint32_t bb = bsb + s * 2048 * 4;
        cpa16(bb,               Wg + ch * 16);
        cpa16(bb + 64 * 16 * 4, Wg + (size_t)64 * LDP + ch * 16);
        asm volatile("cp.async.commit_group;");
    };

    stage(0, 0); stage(1, 1);
    #pragma unroll
    for (int ch = 0; ch < NCH; ch++) {
        asm volatile("cp.async.wait_group 1;");
        __syncthreads();
        if (ch + 2 < NCH) stage(ch + 2, (ch + 2) % 3);
        else asm volatile("cp.async.commit_group;");
        const uint32_t* as = As + (ch % 3) * 2048;
        const uint32_t* bs = Bs + (ch % 3) * 2048;
        uint4 alo[4], ahi[4];
        #pragma unroll
        for (int mi = 0; mi < 4; mi++) {
            alo[mi] = *(const uint4*)&as[(wm0 + mi*16 + g)     * 16 + c*4];
            ahi[mi] = *(const uint4*)&as[(wm0 + mi*16 + g + 8) * 16 + c*4];
        }
        #pragma unroll
        for (int ni = 0; ni < 4; ni++) {
            uint4 b = *(const uint4*)&bs[(wn0 + ni*8 + g) * 16 + c*4];
            #pragma unroll
            for (int mi = 0; mi < 4; mi++) {
                mma16(acc[mi][ni], alo[mi].x, ahi[mi].x, alo[mi].y, ahi[mi].y, b.x, b.y);
                mma16(acc[mi][ni], alo[mi].z, ahi[mi].z, alo[mi].w, ahi[mi].w, b.z, b.w);
            }
        }
    }

    float rsum[4][2];
    #pragma unroll
    for (int mi = 0; mi < 4; mi++) { rsum[mi][0] = 0.f; rsum[mi][1] = 0.f; }
    #pragma unroll
    for (int ni = 0; ni < 4; ni++) {
        int cn = n0 + wn0 + ni*8 + c*2;
        float b0 = __ldg(&bias[cn]),  float_b1 = __ldg(&bias[cn+1]);
        float p0 = __ldg(&predW[cn]), p1 = __ldg(&predW[cn+1]);
        #pragma unroll
        for (int mi = 0; mi < 4; mi++) {
            rsum[mi][0] += ftanh(acc[mi][ni][0] + b0) * p0 + ftanh(acc[mi][ni][1] + float_b1) * p1;
            rsum[mi][1] += ftanh(acc[mi][ni][2] + b0) * p0 + ftanh(acc[mi][ni][3] + float_b1) * p1;
        }
    }
    __syncthreads();
    if (tid < 128) sred[tid] = 0.f;
    __syncthreads();
    #pragma unroll
    for (int mi = 0; mi < 4; mi++)
        #pragma unroll
        for (int h = 0; h < 2; h++) {
            float v = rsum[mi][h];
            v += __shfl_xor_sync(0xffffffffu, v, 1);
            v += __shfl_xor_sync(0xffffffffu, v, 2);
            if (c == 0) atomicAdd(&sred[wm0 + mi*16 + h*8 + g], v);
        }
    __syncthreads();
    if (tid < 128) predP[(size_t)blockIdx.x * T_ + m0 + tid] = sred[tid];
}

// ==================== small kernels ====================
__global__ void k_prep(const float* __restrict__ eW, const float* __restrict__ eb,
                       const float* __restrict__ aW, const float* __restrict__ ab,
                       const float* __restrict__ d1W, const float* __restrict__ d2W,
                       const float* __restrict__ roW, const float* __restrict__ Mk)
{
    int i = blockIdx.x * blockDim.x + threadIdx.x;
    int stride = gridDim.x * blockDim.x;
    for (int j = i; j < NEA_*KEA_; j += stride) {
        int n = j / KEA_, k = j % KEA_;
        g_Wea[n*KEA_ + ph(k)] = __float2half((n < DV_) ? eW[n*KEA_ + k] : aW[(n - DV_)*KEA_ + k]);
    }
    for (int j = i; j < DQ_*DQ_; j += stride) {
        int n = j / DQ_, k = j % DQ_;
        g_Wd1[n*DQ_ + ph(k)] = __float2half(d1W[j]);
        g_Wd2[n*DQ_ + ph(k)] = __float2half(d2W[j]);
    }
    for (int j = i; j < F_*KRO_; j += stride) {
        int n = j / KRO_, k = j % KRO_;
        g_Wro[n*KRO_ + ph(k)] = __float2half(roW[j]);
    }
    for (int j = i; j < 128*DQ_; j += stride) {
        int n = j / DQ_, k = j % DQ_;
        g_Wmk[n*DQ_ + ph(k)] = __float2half(n < M_ ? Mk[n*DQ_ + k] : 0.f);
    }
    for (int j = i; j < NEA_; j += stride) g_bea[j] = (j < DV_) ? eb[j] : ab[j - DV_];
    if (i < 2) g_accum[i] = 0.f;
}

__global__ void k_gather1(const int* __restrict__ q_data, const int* __restrict__ qa_data,
                          const int* __restrict__ time_data, const int* __restrict__ attempt_data,
                          const int* __restrict__ hint_data, const int* __restrict__ hintTotal_data,
                          const float* __restrict__ q_emb, const float* __restrict__ qa_emb,
                          const float* __restrict__ time_emb, const float* __restrict__ attempt_emb,
                          const float* __restrict__ ht_emb)
{
    int t = blockIdx.x, d = threadIdx.x;
    int pd = ph(d);
    int qi = q_data[t], ti = time_data[t], ai = attempt_data[t];
    int hi = hint_data[t], hti = hintTotal_data[t];
    float qe  = q_emb[(size_t)qi*DQ_ + d];
    float te  = time_emb[(size_t)ti*DQ_ + d];
    float ae  = attempt_emb[(size_t)ai*DQ_ + d];
    float he  = ht_emb[(size_t)hi*DQ_ + d];
    float hte = ht_emb[(size_t)hti*DQ_ + d];
    g_bufX[(size_t)t*DQ_ + pd]      = __float2half(te + qe);
    g_bufX[(size_t)(T_+t)*DQ_ + pd] = __float2half(he + hte + ae + qe);
    int qai = qa_data[t];
    g_bufQA[(size_t)t*DV_ + pd]          = __float2half(qa_emb[(size_t)qai*DV_ + d]);
    g_bufQA[(size_t)t*DV_ + ph(d + DQ_)] = __float2half(qa_emb[(size_t)qai*DV_ + DQ_ + d]);
}

// DV split 2-way; per-warp ws; packed f32x2 FMA (m-pairs)
__global__ void __launch_bounds__(128) k_scan(const float* __restrict__ Mv0)
{
    int b = blockIdx.x;
    int tidw = threadIdx.x & 31;
    int wid  = threadIdx.x >> 5;
    int d = blockIdx.y * 128 + threadIdx.x;
    int pe = ph(d);
    int pa = ph(d + DV_);
    unsigned long long mv2[M_/2];
    #pragma unroll
    for (int j = 0; j < M_/2; j++)
        mv2[j] = pk2(Mv0[(2*j)*DV_ + d], Mv0[(2*j+1)*DV_ + d]);
    __shared__ float ws[4][2][64];
    size_t t0 = (size_t)b * S_;
    if (tidw < M_)      ws[wid][0][tidw]      = g_logits[t0*LML_ + tidw];
    if (tidw + 32 < M_) ws[wid][0][tidw + 32] = g_logits[t0*LML_ + tidw + 32];
    float e = __half2float(g_bufEA[t0*NEA_ + pe]);
    float a = __half2float(g_bufEA[t0*NEA_ + pa]);
    __syncwarp();
    for (int s = 0; s < S_; s++) {
        size_t t = t0 + s;
        float en = 0.f, an = 0.f;
        if (s + 1 < S_) {
            en = __half2float(g_bufEA[(t+1)*NEA_ + pe]);
            an = __half2float(g_bufEA[(t+1)*NEA_ + pa]);
            int nb = (s+1) & 1;
            if (tidw < M_)      ws[wid][nb][tidw]      = g_logits[(t+1)*LML_ + tidw];
            if (tidw + 32 < M_) ws[wid][nb][tidw + 32] = g_logits[(t+1)*LML_ + tidw + 32];
        }
        const float* wcur = ws[wid][s & 1];
        unsigned long long ne2 = pk2(-e, -e);
        unsigned long long a2  = pk2(a, a);
        unsigned long long rd2 = 0ull;   // (0.f, 0.f)
        #pragma unroll
        for (int j = 0; j < M_/2; j++) {
            float2 wp = *(const float2*)&wcur[2*j];
            unsigned long long w2 = pk2(wp.x, wp.y);
            rd2 = fma2(w2, mv2[j], rd2);
            mv2[j] = fma2(w2, fma2(ne2, mv2[j], a2), mv2[j]);
        }
        float2 rd = upk2(rd2);
        g_PredIn[t*KRO_ + pe] = __float2half(rd.x + rd.y);
        __syncwarp();
        e = en; a = an;
    }
}

__global__ void k_loss(const int* __restrict__ target, const float* __restrict__ pred_b,
                       float* __restrict__ out)
{
    int i = blockIdx.x * blockDim.x + threadIdx.x;
    float le = 0.f, cnt = 0.f;
    if (i < T_) {
        float p = g_predP[0][i] + g_predP[1][i] + g_predP[2][i] + g_predP[3][i] + pred_b[0];
        int tg = target[i];
        bool mask = tg >= 1;
        float y = mask ? (float)(tg - 1) : 0.f;
        float sig = 1.f / (1.f + expf(-p));
        out[1 + i]      = mask ? sig : 0.f;
        out[1 + T_ + i] = mask ? y   : 0.f;
        if (mask) {
            le = fmaxf(p, 0.f) + log1pf(expf(-fabsf(p))) - p * y;
            cnt = 1.f;
        }
    }
    __shared__ float sle[256], scn[256];
    sle[threadIdx.x] = le; scn[threadIdx.x] = cnt;
    __syncthreads();
    for (int o = 128; o; o >>= 1) {
        if (threadIdx.x < o) { sle[threadIdx.x] += sle[threadIdx.x + o]; scn[threadIdx.x] += scn[threadIdx.x + o]; }
        __syncthreads();
    }
    if (threadIdx.x == 0) { atomicAdd(&g_accum[0], sle[0]); atomicAdd(&g_accum[1], scn[0]); }
}

__global__ void k_final(float* __restrict__ out)
{
    out[0] = g_accum[0] / fmaxf(g_accum[1], 1.f);
}

// ==================== host ====================
extern "C" void kernel_launch(void* const* d_in, const int* in_sizes, int n_in,
                              void* d_out, int out_size)
{
    const int*   q_data      = (const int*)  d_in[0];
    const int*   qa_data     = (const int*)  d_in[1];
    const int*   target      = (const int*)  d_in[2];
    const int*   time_data   = (const int*)  d_in[3];
    const int*   attempt_data= (const int*)  d_in[4];
    const int*   hint_data   = (const int*)  d_in[5];
    const int*   hintTotal   = (const int*)  d_in[6];
    const float* q_emb       = (const float*)d_in[7];
    const float* qa_emb      = (const float*)d_in[8];
    const float* time_emb    = (const float*)d_in[9];
    const float* attempt_emb = (const float*)d_in[10];
    const float* ht_emb      = (const float*)d_in[11];
    const float* Mk          = (const float*)d_in[12];
    const float* Mv0         = (const float*)d_in[13];
    const float* diff_W      = (const float*)d_in[14];
    const float* diff_b      = (const float*)d_in[15];
    const float* diff2_W     = (const float*)d_in[16];
    const float* diff2_b     = (const float*)d_in[17];
    const float* erase_W     = (const float*)d_in[18];
    const float* erase_b     = (const float*)d_in[19];
    const float* add_W       = (const float*)d_in[20];
    const float* add_b       = (const float*)d_in[21];
    const float* read_W      = (const float*)d_in[22];
    const float* read_b      = (const float*)d_in[23];
    const float* pred_W      = (const float*)d_in[24];
    const float* pred_b      = (const float*)d_in[25];
    float* out = (float*)d_out;

    __half *bufX, *bufX3, *bufTD, *bufQA, *bufEA, *predin;
    __half *Wea, *Wd1, *Wd2, *Wro, *Wmk;
    float *logits, *predP, *bea;
    cudaGetSymbolAddress((void**)&bufX,   g_bufX);
    cudaGetSymbolAddress((void**)&bufX3,  g_bufX3);
    cudaGetSymbolAddress((void**)&bufTD,  g_bufTD);
    cudaGetSymbolAddress((void**)&bufQA,  g_bufQA);
    cudaGetSymbolAddress((void**)&bufEA,  g_bufEA);
    cudaGetSymbolAddress((void**)&predin, g_PredIn);
    cudaGetSymbolAddress((void**)&logits, g_logits);
    cudaGetSymbolAddress((void**)&predP,  g_predP);
    cudaGetSymbolAddress((void**)&Wea,    g_Wea);
    cudaGetSymbolAddress((void**)&Wd1,    g_Wd1);
    cudaGetSymbolAddress((void**)&Wd2,    g_Wd2);
    cudaGetSymbolAddress((void**)&Wro,    g_Wro);
    cudaGetSymbolAddress((void**)&Wmk,    g_Wmk);
    cudaGetSymbolAddress((void**)&bea,    g_bea);

    const int SMG = (6*2048 + 128) * 4;
    const int SML = (6*2048 + 128*USTR) * 4;
    const int SMQ = (6*2048 + 128*USTR + 512) * 4;
    cudaFuncSetAttribute(k_fused1, cudaFuncAttributeMaxDynamicSharedMemorySize, SML);
    cudaFuncSetAttribute(k_fused2, cudaFuncAttributeMaxDynamicSharedMemorySize, SMQ);
    cudaFuncSetAttribute(k_ro,     cudaFuncAttributeMaxDynamicSharedMemorySize, SMG);

    k_prep<<<1024, 256>>>(erase_W, erase_b, add_W, add_b, diff_W, diff2_W, read_W, Mk);
    k_gather1<<<T_, 128>>>(q_data, qa_data, time_data, attempt_data, hint_data, hintTotal,
                           q_emb, qa_emb, time_emb, attempt_emb, ht_emb);
    k_fused1<<<4000, 256, SML>>>(bufX, Wd1, Wd2, diff_b, diff2_b, bufTD, bufX3,
                                 q_data, attempt_data, hint_data, hintTotal,
                                 q_emb, attempt_emb, ht_emb,
                                 bufQA, Wea, bea, bufEA);
    k_fused2<<<3000, 256, SMQ>>>(bufX3, Wd1, Wmk, diff_b, bufTD,
                                 time_data, time_emb, predin, logits,
                                 bufQA, Wea, bea, bufEA);
    k_scan<<<dim3(B_, 2), 128>>>(Mv0);
    k_ro<<<dim3(4, 1000), 256, SMG>>>(predin, Wro, read_b, pred_W, predP);
    k_loss<<<(T_ + 255)/256, 256>>>(target, pred_b, out);
    k_final<<<1, 1>>>(out);
}